// round 1
// baseline (speedup 1.0000x reference)
#include <cuda_runtime.h>
#include <cstdint>

#define D_MODEL 1024
#define NHEAD   16
#define DHEAD   64
#define SEQ     2048
#define BATCH   2
#define M_TOTAL (BATCH * SEQ)   /* 4096 */
#define RANK    32

// ---------------- device scratch (no allocations allowed) ----------------
__device__ float g_Wm[4ull * D_MODEL * D_MODEL];                    // merged weights q,k,v,o
__device__ float g_q [(size_t)BATCH * NHEAD * SEQ * DHEAD];         // [b,h,n,d]
__device__ float g_k [(size_t)BATCH * NHEAD * SEQ * DHEAD];
__device__ float g_v [(size_t)BATCH * NHEAD * SEQ * DHEAD];
__device__ float g_ao[(size_t)M_TOTAL * D_MODEL];                   // attention output [m, 1024]

// ---------------- LoRA merge: Wm[n,k] = W[n,k] + sum_r dB[n,r]*dW[r,k] ----
__global__ void merge_lora(const float* __restrict__ W,
                           const float* __restrict__ dW,
                           const float* __restrict__ dB,
                           int layer)
{
    int idx = blockIdx.x * 256 + threadIdx.x;      // 0 .. 1M-1
    int n = idx >> 10;
    int k = idx & 1023;
    float s = W[idx];
#pragma unroll
    for (int r = 0; r < RANK; r++)
        s += dB[n * RANK + r] * dW[r * D_MODEL + k];
    g_Wm[(size_t)layer * D_MODEL * D_MODEL + idx] = s;
}

// ---------------- 128x128x8 SGEMM core: C = A @ W^T ----------------------
// A: [*,1024] row-major tile base Ab (128 rows). W: [*,1024] row-major tile base Wb (128 rows).
__device__ __forceinline__ void sgemm_128x128(const float* __restrict__ Ab,
                                              const float* __restrict__ Wb,
                                              float (&acc)[8][8])
{
    __shared__ __align__(16) float As[8][128];
    __shared__ __align__(16) float Bs[8][128];

    const int tid  = threadIdx.x;
    const int trow = (tid >> 4) << 3;   // 0..120
    const int tcol = (tid & 15) << 3;   // 0..120
    const int lr   = tid >> 1;          // 0..127 (tile row to load)
    const int lk   = (tid & 1) << 2;    // 0 or 4

    for (int k0 = 0; k0 < D_MODEL; k0 += 8) {
        float4 a4 = *(const float4*)(Ab + (size_t)lr * D_MODEL + k0 + lk);
        float4 b4 = *(const float4*)(Wb + (size_t)lr * D_MODEL + k0 + lk);
        As[lk + 0][lr] = a4.x; As[lk + 1][lr] = a4.y;
        As[lk + 2][lr] = a4.z; As[lk + 3][lr] = a4.w;
        Bs[lk + 0][lr] = b4.x; Bs[lk + 1][lr] = b4.y;
        Bs[lk + 2][lr] = b4.z; Bs[lk + 3][lr] = b4.w;
        __syncthreads();
#pragma unroll
        for (int k = 0; k < 8; k++) {
            float af[8], bf[8];
            *(float4*)&af[0] = *(const float4*)&As[k][trow];
            *(float4*)&af[4] = *(const float4*)&As[k][trow + 4];
            *(float4*)&bf[0] = *(const float4*)&Bs[k][tcol];
            *(float4*)&bf[4] = *(const float4*)&Bs[k][tcol + 4];
#pragma unroll
            for (int i = 0; i < 8; i++)
#pragma unroll
                for (int j = 0; j < 8; j++)
                    acc[i][j] += af[i] * bf[j];
        }
        __syncthreads();
    }
}

// ---------------- QKV projection: y = x @ Wm^T + b, scatter to [b,h,n,d] --
__global__ void __launch_bounds__(256, 2)
gemm_qkv(const float* __restrict__ x,
         const float* __restrict__ bq,
         const float* __restrict__ bk,
         const float* __restrict__ bv)
{
    const int z = blockIdx.z;                                   // 0=q,1=k,2=v
    const float* W    = g_Wm + (size_t)z * D_MODEL * D_MODEL;
    const float* bias = (z == 0) ? bq : (z == 1) ? bk : bv;
    float* outp       = (z == 0) ? g_q : (z == 1) ? g_k : g_v;

    float acc[8][8] = {};
    const float* Ab = x + (size_t)blockIdx.y * 128 * D_MODEL;
    const float* Wb = W + (size_t)blockIdx.x * 128 * D_MODEL;
    sgemm_128x128(Ab, Wb, acc);

    const int tid  = threadIdx.x;
    const int trow = (tid >> 4) << 3;
    const int tcol = (tid & 15) << 3;
    const int gm0  = blockIdx.y * 128 + trow;
    const int gn0  = blockIdx.x * 128 + tcol;
    const int h    = gn0 >> 6;          // tcol multiple of 8 -> 8 cols stay in one head
    const int d0   = gn0 & 63;

    float bb[8];
#pragma unroll
    for (int j = 0; j < 8; j++) bb[j] = bias[gn0 + j];

#pragma unroll
    for (int i = 0; i < 8; i++) {
        int m  = gm0 + i;
        int b  = m >> 11;               // / 2048
        int ns = m & 2047;
        float* orow = outp + (((size_t)(b * NHEAD + h) * SEQ + ns) * DHEAD) + d0;
        float4 o0, o1;
        o0.x = acc[i][0] + bb[0]; o0.y = acc[i][1] + bb[1];
        o0.z = acc[i][2] + bb[2]; o0.w = acc[i][3] + bb[3];
        o1.x = acc[i][4] + bb[4]; o1.y = acc[i][5] + bb[5];
        o1.z = acc[i][6] + bb[6]; o1.w = acc[i][7] + bb[7];
        *(float4*)(orow)     = o0;
        *(float4*)(orow + 4) = o1;
    }
}

// ---------------- O projection: out = g_ao @ Wm_o^T + b -------------------
__global__ void __launch_bounds__(256, 2)
gemm_o(const float* __restrict__ bias, float* __restrict__ C)
{
    float acc[8][8] = {};
    const float* Ab = g_ao + (size_t)blockIdx.y * 128 * D_MODEL;
    const float* Wb = g_Wm + 3ull * D_MODEL * D_MODEL + (size_t)blockIdx.x * 128 * D_MODEL;
    sgemm_128x128(Ab, Wb, acc);

    const int tid  = threadIdx.x;
    const int trow = (tid >> 4) << 3;
    const int tcol = (tid & 15) << 3;
    const int gm0  = blockIdx.y * 128 + trow;
    const int gn0  = blockIdx.x * 128 + tcol;

    float bb[8];
#pragma unroll
    for (int j = 0; j < 8; j++) bb[j] = bias[gn0 + j];

#pragma unroll
    for (int i = 0; i < 8; i++) {
        float* crow = C + (size_t)(gm0 + i) * D_MODEL + gn0;
        float4 o0, o1;
        o0.x = acc[i][0] + bb[0]; o0.y = acc[i][1] + bb[1];
        o0.z = acc[i][2] + bb[2]; o0.w = acc[i][3] + bb[3];
        o1.x = acc[i][4] + bb[4]; o1.y = acc[i][5] + bb[5];
        o1.z = acc[i][6] + bb[6]; o1.w = acc[i][7] + bb[7];
        *(float4*)(crow)     = o0;
        *(float4*)(crow + 4) = o1;
    }
}

// ---------------- Flash attention: 64-query tile per block ----------------
// grid: (32 q-tiles, 32 bh).  block: 256 threads (16x16, 4x4 micro-tile).
#define FPAD 68   // row stride in floats: 272B, float4-aligned, conflict-light

__global__ void __launch_bounds__(256)
flash_attn(float* __restrict__ gout)
{
    const int qt = blockIdx.x;          // 0..31
    const int bh = blockIdx.y;          // 0..31  (b*16+h)

    extern __shared__ float sm[];
    float* Qs   = sm;                   // 64*FPAD
    float* Ks   = Qs + 64 * FPAD;
    float* Vs   = Ks + 64 * FPAD;
    float* Ss   = Vs + 64 * FPAD;
    float* mrow = Ss + 64 * FPAD;       // 64
    float* lrow = mrow + 64;            // 64
    float* arow = lrow + 64;            // 64
    float* pm   = arow + 64;            // 64*4
    float* pl   = pm + 256;             // 64*4

    const int tid = threadIdx.x;
    const int tx  = tid & 15, ty = tid >> 4;
    const int row = ty << 2, col = tx << 2;
    const float scale = 0.125f;         // 1/sqrt(64)

    const float* qbase = g_q + ((size_t)bh * SEQ + (size_t)qt * 64) * DHEAD;
    const float* kbase = g_k + (size_t)bh * SEQ * DHEAD;
    const float* vbase = g_v + (size_t)bh * SEQ * DHEAD;

    // load Q tile (64x64 floats = 1024 float4)
#pragma unroll
    for (int i = 0; i < 4; i++) {
        int e  = tid + i * 256;
        int rr = e >> 4;
        int cc = (e & 15) << 2;
        *(float4*)&Qs[rr * FPAD + cc] = *(const float4*)(qbase + rr * DHEAD + cc);
    }
    if (tid < 64) { mrow[tid] = -1e30f; lrow[tid] = 0.f; }

    float acc[4][4] = {};
    __syncthreads();

    for (int kt = 0; kt < SEQ / 64; kt++) {
        // load K and V tiles
#pragma unroll
        for (int i = 0; i < 4; i++) {
            int e  = tid + i * 256;
            int rr = e >> 4;
            int cc = (e & 15) << 2;
            *(float4*)&Ks[rr * FPAD + cc] = *(const float4*)(kbase + (size_t)kt * 4096 + rr * DHEAD + cc);
            *(float4*)&Vs[rr * FPAD + cc] = *(const float4*)(vbase + (size_t)kt * 4096 + rr * DHEAD + cc);
        }
        __syncthreads();

        // S = Q K^T * scale  (each thread: 4x4 patch)
        float s[4][4] = {};
#pragma unroll
        for (int d = 0; d < DHEAD; d += 4) {
            float4 q4[4], k4[4];
#pragma unroll
            for (int i = 0; i < 4; i++) q4[i] = *(const float4*)&Qs[(row + i) * FPAD + d];
#pragma unroll
            for (int j = 0; j < 4; j++) k4[j] = *(const float4*)&Ks[(col + j) * FPAD + d];
#pragma unroll
            for (int i = 0; i < 4; i++)
#pragma unroll
                for (int j = 0; j < 4; j++)
                    s[i][j] += q4[i].x * k4[j].x + q4[i].y * k4[j].y
                             + q4[i].z * k4[j].z + q4[i].w * k4[j].w;
        }
#pragma unroll
        for (int i = 0; i < 4; i++)
#pragma unroll
            for (int j = 0; j < 4; j++)
                Ss[(row + i) * FPAD + col + j] = s[i][j] * scale;
        __syncthreads();

        // online softmax: 4 threads per row, 16 cols each
        const int r = tid >> 2, part = tid & 3, c0 = part << 4;
        float mt = -1e30f;
#pragma unroll
        for (int c = 0; c < 16; c++) mt = fmaxf(mt, Ss[r * FPAD + c0 + c]);
        pm[(r << 2) + part] = mt;
        __syncthreads();

        float mnew = fmaxf(fmaxf(pm[r << 2], pm[(r << 2) + 1]),
                           fmaxf(pm[(r << 2) + 2], pm[(r << 2) + 3]));
        mnew = fmaxf(mnew, mrow[r]);
        float ssum = 0.f;
#pragma unroll
        for (int c = 0; c < 16; c++) {
            float p = __expf(Ss[r * FPAD + c0 + c] - mnew);
            Ss[r * FPAD + c0 + c] = p;
            ssum += p;
        }
        pl[(r << 2) + part] = ssum;
        __syncthreads();

        if (part == 0) {
            float a = __expf(mrow[r] - mnew);
            arow[r] = a;
            lrow[r] = lrow[r] * a
                    + pl[r << 2] + pl[(r << 2) + 1] + pl[(r << 2) + 2] + pl[(r << 2) + 3];
            mrow[r] = mnew;
        }
        __syncthreads();

        // rescale accumulators, then acc += P @ V
        float av[4];
#pragma unroll
        for (int i = 0; i < 4; i++) av[i] = arow[row + i];
#pragma unroll
        for (int i = 0; i < 4; i++)
#pragma unroll
            for (int j = 0; j < 4; j++)
                acc[i][j] *= av[i];

#pragma unroll 8
        for (int kk = 0; kk < 64; kk++) {
            float4 v4 = *(const float4*)&Vs[kk * FPAD + col];
            float p0 = Ss[(row + 0) * FPAD + kk];
            float p1 = Ss[(row + 1) * FPAD + kk];
            float p2 = Ss[(row + 2) * FPAD + kk];
            float p3 = Ss[(row + 3) * FPAD + kk];
            acc[0][0] += p0 * v4.x; acc[0][1] += p0 * v4.y; acc[0][2] += p0 * v4.z; acc[0][3] += p0 * v4.w;
            acc[1][0] += p1 * v4.x; acc[1][1] += p1 * v4.y; acc[1][2] += p1 * v4.z; acc[1][3] += p1 * v4.w;
            acc[2][0] += p2 * v4.x; acc[2][1] += p2 * v4.y; acc[2][2] += p2 * v4.z; acc[2][3] += p2 * v4.w;
            acc[3][0] += p3 * v4.x; acc[3][1] += p3 * v4.y; acc[3][2] += p3 * v4.z; acc[3][3] += p3 * v4.w;
        }
        __syncthreads();   // before overwriting K/V/S next tile
    }

    // epilogue: normalize and write to g_ao [m, 1024] with col = h*64 + d
    const int b = bh >> 4, h = bh & 15;
#pragma unroll
    for (int i = 0; i < 4; i++) {
        float inv = 1.f / lrow[row + i];
        float4 o;
        o.x = acc[i][0] * inv; o.y = acc[i][1] * inv;
        o.z = acc[i][2] * inv; o.w = acc[i][3] * inv;
        size_t m = (size_t)b * SEQ + (size_t)qt * 64 + row + i;
        *(float4*)(gout + m * D_MODEL + h * DHEAD + col) = o;
    }
}

// ---------------- launch --------------------------------------------------
extern "C" void kernel_launch(void* const* d_in, const int* in_sizes, int n_in,
                              void* d_out, int out_size)
{
    const float* x = (const float*)d_in[0];
    const float* W [4] = {(const float*)d_in[1],  (const float*)d_in[5],
                          (const float*)d_in[9],  (const float*)d_in[13]};
    const float* B [4] = {(const float*)d_in[2],  (const float*)d_in[6],
                          (const float*)d_in[10], (const float*)d_in[14]};
    const float* dW[4] = {(const float*)d_in[3],  (const float*)d_in[7],
                          (const float*)d_in[11], (const float*)d_in[15]};
    const float* dB[4] = {(const float*)d_in[4],  (const float*)d_in[8],
                          (const float*)d_in[12], (const float*)d_in[16]};
    float* out = (float*)d_out;

    // 1) merge LoRA weights
    for (int l = 0; l < 4; l++)
        merge_lora<<<(D_MODEL * D_MODEL) / 256, 256>>>(W[l], dW[l], dB[l], l);

    // 2) QKV projections (fused grid.z)
    {
        dim3 grid(D_MODEL / 128, M_TOTAL / 128, 3);
        gemm_qkv<<<grid, 256>>>(x, B[0], B[1], B[2]);
    }

    // 3) flash attention -> g_ao
    {
        static const int smem = (4 * 64 * FPAD + 3 * 64 + 2 * 256) * (int)sizeof(float);
        cudaFuncSetAttribute(flash_attn, cudaFuncAttributeMaxDynamicSharedMemorySize, smem);
        float* pao;
        cudaGetSymbolAddress((void**)&pao, g_ao);
        dim3 grid(SEQ / 64, BATCH * NHEAD);
        flash_attn<<<grid, 256, smem>>>(pao);
    }

    // 4) output projection -> d_out
    {
        dim3 grid(D_MODEL / 128, M_TOTAL / 128);
        gemm_o<<<grid, 256>>>(B[3], out);
    }
}

// round 3
// speedup vs baseline: 3.1630x; 3.1630x over previous
#include <cuda_runtime.h>
#include <cuda_bf16.h>
#include <cstdint>

#define D_MODEL 1024
#define NHEAD   16
#define DHEAD   64
#define SEQ     2048
#define BATCH   2
#define M_TOTAL (BATCH * SEQ)   /* 4096 */
#define RANK    32
#define KSPLIT  2048            /* [hi | lo] concatenated K storage */
#define K3      3072            /* virtual K: hi*hi + hi*lo + lo*hi */

// ---------------- device scratch ----------------
__device__ __nv_bfloat16 g_xs [(size_t)M_TOTAL * KSPLIT];       // x split [4096,2048]
__device__ __nv_bfloat16 g_w2 [(size_t)4 * D_MODEL * KSPLIT];   // merged W split
__device__ __nv_bfloat16 g_ao2[(size_t)M_TOTAL * KSPLIT];       // attn out split
__device__ __nv_bfloat16 g_qs [(size_t)BATCH * NHEAD * SEQ * 128]; // [bh][n][hi64|lo64]
__device__ __nv_bfloat16 g_ks [(size_t)BATCH * NHEAD * SEQ * 128];
__device__ __nv_bfloat16 g_vs [(size_t)BATCH * NHEAD * SEQ * 128];

// ---------------- PTX helpers (baseline compute_103 only) ----------------
__device__ __forceinline__ uint32_t smem_u32(const void* p) {
    uint32_t a;
    asm("{ .reg .u64 t; cvta.to.shared.u64 t, %1; cvt.u32.u64 %0, t; }" : "=r"(a) : "l"(p));
    return a;
}
__device__ __forceinline__ void cpa16(uint32_t dst, const void* src) {
    asm volatile("cp.async.cg.shared.global [%0], [%1], 16;" :: "r"(dst), "l"(src));
}
#define CP_COMMIT() asm volatile("cp.async.commit_group;" ::: "memory")
#define CP_WAIT(n)  asm volatile("cp.async.wait_group %0;" :: "n"(n) : "memory")

__device__ __forceinline__ void ldsm_x4(uint32_t (&r)[4], uint32_t addr) {
    asm volatile("ldmatrix.sync.aligned.m8n8.x4.shared.b16 {%0,%1,%2,%3}, [%4];"
                 : "=r"(r[0]), "=r"(r[1]), "=r"(r[2]), "=r"(r[3]) : "r"(addr));
}
__device__ __forceinline__ void ldsm_x4t(uint32_t (&r)[4], uint32_t addr) {
    asm volatile("ldmatrix.sync.aligned.m8n8.x4.trans.shared.b16 {%0,%1,%2,%3}, [%4];"
                 : "=r"(r[0]), "=r"(r[1]), "=r"(r[2]), "=r"(r[3]) : "r"(addr));
}
__device__ __forceinline__ void mma16816(float (&d)[4], const uint32_t (&a)[4],
                                         uint32_t b0, uint32_t b1) {
    asm volatile("mma.sync.aligned.m16n8k16.row.col.f32.bf16.bf16.f32 "
                 "{%0,%1,%2,%3}, {%4,%5,%6,%7}, {%8,%9}, {%0,%1,%2,%3};"
                 : "+f"(d[0]), "+f"(d[1]), "+f"(d[2]), "+f"(d[3])
                 : "r"(a[0]), "r"(a[1]), "r"(a[2]), "r"(a[3]), "r"(b0), "r"(b1));
}
__device__ __forceinline__ void split2(float v, __nv_bfloat16& h, __nv_bfloat16& l) {
    h = __float2bfloat16(v);
    l = __float2bfloat16(v - __bfloat162float(h));
}

// ---------------- LoRA merge + bf16 split ----------------
__global__ void merge_lora2(const float* __restrict__ W,
                            const float* __restrict__ dW,
                            const float* __restrict__ dB,
                            int layer)
{
    int e  = blockIdx.x * 256 + threadIdx.x;   // float4 index
    int n  = e >> 8;
    int kq = e & 255;
    float4 s = *(const float4*)(W + (size_t)n * D_MODEL + kq * 4);
    const float4* dW4 = (const float4*)dW;
#pragma unroll
    for (int r = 0; r < RANK; r++) {
        float b  = dB[n * RANK + r];
        float4 w = dW4[r * 256 + kq];
        s.x += b * w.x; s.y += b * w.y; s.z += b * w.z; s.w += b * w.w;
    }
    __nv_bfloat16 h0, h1, h2, h3, l0, l1, l2, l3;
    split2(s.x, h0, l0); split2(s.y, h1, l1);
    split2(s.z, h2, l2); split2(s.w, h3, l3);
    size_t rowoff = (size_t)(layer * D_MODEL + n) * KSPLIT;
    __nv_bfloat162* ph = (__nv_bfloat162*)(g_w2 + rowoff + kq * 4);
    __nv_bfloat162* pl = (__nv_bfloat162*)(g_w2 + rowoff + D_MODEL + kq * 4);
    ph[0] = __halves2bfloat162(h0, h1); ph[1] = __halves2bfloat162(h2, h3);
    pl[0] = __halves2bfloat162(l0, l1); pl[1] = __halves2bfloat162(l2, l3);
}

__global__ void prep_split(const float* __restrict__ src)
{
    int e   = blockIdx.x * 256 + threadIdx.x;
    int row = e >> 8;
    int kq  = e & 255;
    float4 s = *(const float4*)(src + (size_t)row * D_MODEL + kq * 4);
    __nv_bfloat16 h0, h1, h2, h3, l0, l1, l2, l3;
    split2(s.x, h0, l0); split2(s.y, h1, l1);
    split2(s.z, h2, l2); split2(s.w, h3, l3);
    size_t rowoff = (size_t)row * KSPLIT;
    __nv_bfloat162* ph = (__nv_bfloat162*)(g_xs + rowoff + kq * 4);
    __nv_bfloat162* pl = (__nv_bfloat162*)(g_xs + rowoff + D_MODEL + kq * 4);
    ph[0] = __halves2bfloat162(h0, h1); ph[1] = __halves2bfloat162(h2, h3);
    pl[0] = __halves2bfloat162(l0, l1); pl[1] = __halves2bfloat162(l2, l3);
}

// ---------------- HMMA GEMM: C[128,128] tile = A @ W^T (+bias) -------------
// virtual K=3072: kp<1024: Ahi*Whi; kp<2048: Ahi*Wlo; else Alo*Whi
#define GKC   64
#define GNCH  48
#define GROWB 144                  /* smem row: 64 bf16 (128B) + 16B pad */
#define GT_BYTES (128 * GROWB)     /* 18432 */
#define GSTAGE   (2 * GT_BYTES)    /* 36864 */
#define GSMEM    (2 * GSTAGE)      /* 73728 */

__global__ void __launch_bounds__(256)
gemm_hmma(const __nv_bfloat16* __restrict__ Abase,  // [*, KSPLIT]
          int mode, int layer_base,
          const float* __restrict__ b0, const float* __restrict__ b1,
          const float* __restrict__ b2, float* __restrict__ outO)
{
    extern __shared__ __align__(128) char smem[];
    const uint32_t sb = smem_u32(smem);
    const int tid = threadIdx.x, ln = tid & 31, w = tid >> 5;
    const int wm = w & 1, wn = w >> 1;     // warp grid 2(m) x 4(n)
    const int bx = blockIdx.x, by = blockIdx.y, z = blockIdx.z;
    const int layer = layer_base + z;

    const __nv_bfloat16* Arow = Abase + (size_t)(by * 128) * KSPLIT;
    const __nv_bfloat16* Wrow = g_w2 + ((size_t)layer * D_MODEL + bx * 128) * KSPLIT;

    float acc[4][4][4] = {};

    // chunk loader: 128 rows x 64 bf16 each for A and W (8 x 16B per row)
#define GLOAD(c) do {                                                          \
        int s_ = (c) & 1;                                                      \
        int kp_ = (c) * GKC;                                                   \
        int xA_ = (kp_ < 1024) ? kp_ : kp_ - 1024;                             \
        int xW_ = (kp_ < 2048) ? kp_ : kp_ - 2048;                             \
        uint32_t bA_ = sb + s_ * GSTAGE;                                       \
        uint32_t bW_ = bA_ + GT_BYTES;                                         \
        _Pragma("unroll")                                                      \
        for (int u_ = 0; u_ < 4; u_++) {                                       \
            int e_ = tid + u_ * 256;                                           \
            int row_ = e_ >> 3, seg_ = (e_ & 7) * 16;                          \
            cpa16(bA_ + row_ * GROWB + seg_,                                   \
                  (const char*)(Arow + (size_t)row_ * KSPLIT + xA_) + seg_);   \
            cpa16(bW_ + row_ * GROWB + seg_,                                   \
                  (const char*)(Wrow + (size_t)row_ * KSPLIT + xW_) + seg_);   \
        }                                                                      \
        CP_COMMIT();                                                           \
    } while (0)

    GLOAD(0);
    for (int c = 0; c < GNCH; c++) {
        if (c + 1 < GNCH) { GLOAD(c + 1); CP_WAIT(1); }
        else              { CP_WAIT(0); }
        __syncthreads();
        const uint32_t bA = sb + (c & 1) * GSTAGE;
        const uint32_t bW = bA + GT_BYTES;
#pragma unroll
        for (int ks = 0; ks < 4; ks++) {
            const int k0 = ks * 16;
            uint32_t afr[4][4];
#pragma unroll
            for (int i = 0; i < 4; i++) {
                int row = wm * 64 + i * 16 + (ln & 15);
                ldsm_x4(afr[i], bA + row * GROWB + (k0 + ((ln >> 4) << 3)) * 2);
            }
            uint32_t bfr[2][4];
#pragma unroll
            for (int j = 0; j < 2; j++) {
                int n = wn * 32 + j * 16 + (ln & 7) + ((ln & 16) ? 8 : 0);
                ldsm_x4(bfr[j], bW + n * GROWB + (k0 + ((ln & 8) ? 8 : 0)) * 2);
            }
#pragma unroll
            for (int i = 0; i < 4; i++)
#pragma unroll
                for (int jj = 0; jj < 4; jj++)
                    mma16816(acc[i][jj], afr[i], bfr[jj >> 1][(jj & 1) * 2],
                             bfr[jj >> 1][(jj & 1) * 2 + 1]);
        }
        __syncthreads();
    }

    // epilogue
    const float* bias = (z == 0) ? b0 : (z == 1) ? b1 : b2;
    __nv_bfloat16* qkv = (z == 0) ? g_qs : (z == 1) ? g_ks : g_vs;
#pragma unroll
    for (int i = 0; i < 4; i++) {
#pragma unroll
        for (int dl = 0; dl < 2; dl++) {
            const int m = by * 128 + wm * 64 + i * 16 + (ln >> 2) + dl * 8;
#pragma unroll
            for (int jj = 0; jj < 4; jj++) {
                const int cgl = bx * 128 + wn * 32 + jj * 8 + (ln & 3) * 2;
                float v0 = acc[i][jj][dl * 2 + 0] + bias[cgl];
                float v1 = acc[i][jj][dl * 2 + 1] + bias[cgl + 1];
                if (mode == 0) {
                    const int h = cgl >> 6, d = cgl & 63;
                    const int b = m >> 11, n = m & 2047;
                    __nv_bfloat16* base = qkv + ((size_t)(b * NHEAD + h) * SEQ + n) * 128;
                    __nv_bfloat16 h0, h1, l0v, l1v;
                    split2(v0, h0, l0v); split2(v1, h1, l1v);
                    *(__nv_bfloat162*)(base + d)      = __halves2bfloat162(h0, h1);
                    *(__nv_bfloat162*)(base + 64 + d) = __halves2bfloat162(l0v, l1v);
                } else {
                    float2 o; o.x = v0; o.y = v1;
                    *(float2*)(outO + (size_t)m * D_MODEL + cgl) = o;
                }
            }
        }
    }
}

// ---------------- Flash attention with HMMA --------------------------------
#define FP    68      /* Ss fp32 row stride (floats) */
#define BROW  272     /* bf16 tile row bytes: 128 data + 8 pad bf16 */
#define SM_Q  0
#define SM_K  17408
#define SM_V  34816
#define SM_P  52224
#define SM_S  69632
#define SM_SM 87040   /* mrow/lrow/arow/pm/pl */
#define ATT_SMEM (SM_SM + (64 * 3 + 512) * 4)   /* 89856 */

__global__ void __launch_bounds__(256)
flash_hmma()
{
    extern __shared__ __align__(128) char smem[];
    const uint32_t sb = smem_u32(smem);
    float* Ss   = (float*)(smem + SM_S);
    float* mrow = (float*)(smem + SM_SM);
    float* lrow = mrow + 64;
    float* arow = lrow + 64;
    float* pm   = arow + 64;
    float* pl   = pm + 256;

    const int tid = threadIdx.x, ln = tid & 31, w = tid >> 5;
    const int wm = w & 1, wn = w >> 1;     // warp grid 2(m) x 4(n)
    const int qt = blockIdx.x, bh = blockIdx.y;

    const __nv_bfloat16* qg = g_qs + ((size_t)bh * SEQ + qt * 64) * 128;
    const __nv_bfloat16* kg = g_ks + (size_t)bh * SEQ * 128;
    const __nv_bfloat16* vg = g_vs + (size_t)bh * SEQ * 128;

    // Q tile: 64 rows x 256B = 1024 x 16B
#pragma unroll
    for (int u = 0; u < 4; u++) {
        int e = tid + u * 256;
        int row = e >> 4, seg = (e & 15) * 16;
        cpa16(sb + SM_Q + row * BROW + seg, (const char*)(qg + (size_t)row * 128) + seg);
    }
    CP_COMMIT();
    if (tid < 64) { mrow[tid] = -1e30f; lrow[tid] = 0.f; }

    float acco[2][2][4] = {};

    for (int kt = 0; kt < SEQ / 64; kt++) {
        const __nv_bfloat16* kb = kg + (size_t)kt * 64 * 128;
        const __nv_bfloat16* vb = vg + (size_t)kt * 64 * 128;
#pragma unroll
        for (int u = 0; u < 4; u++) {
            int e = tid + u * 256;
            int row = e >> 4, seg = (e & 15) * 16;
            cpa16(sb + SM_K + row * BROW + seg, (const char*)(kb + (size_t)row * 128) + seg);
            cpa16(sb + SM_V + row * BROW + seg, (const char*)(vb + (size_t)row * 128) + seg);
        }
        CP_COMMIT();
        CP_WAIT(0);
        __syncthreads();

        // ---- S = Q K^T (3-term split), warp tile 32(m) x 16(n) ----
        float accs[2][2][4] = {};
#pragma unroll
        for (int s = 0; s < 12; s++) {
            int kq, kk;
            if (s < 4)      { kq = s * 16;            kk = s * 16; }
            else if (s < 8) { kq = (s - 4) * 16;      kk = 64 + (s - 4) * 16; }
            else            { kq = 64 + (s - 8) * 16; kk = (s - 8) * 16; }
            uint32_t afr[2][4];
#pragma unroll
            for (int i = 0; i < 2; i++) {
                int row = wm * 32 + i * 16 + (ln & 15);
                ldsm_x4(afr[i], sb + SM_Q + row * BROW + (kq + ((ln >> 4) << 3)) * 2);
            }
            uint32_t bfr[4];
            {
                int n = wn * 16 + (ln & 7) + ((ln & 16) ? 8 : 0);
                ldsm_x4(bfr, sb + SM_K + n * BROW + (kk + ((ln & 8) ? 8 : 0)) * 2);
            }
#pragma unroll
            for (int i = 0; i < 2; i++)
#pragma unroll
                for (int jj = 0; jj < 2; jj++)
                    mma16816(accs[i][jj], afr[i], bfr[jj * 2], bfr[jj * 2 + 1]);
        }
        // write S*scale to Ss
#pragma unroll
        for (int i = 0; i < 2; i++)
#pragma unroll
            for (int dl = 0; dl < 2; dl++)
#pragma unroll
                for (int jj = 0; jj < 2; jj++) {
                    int r = wm * 32 + i * 16 + (ln >> 2) + dl * 8;
                    int ci = wn * 16 + jj * 8 + (ln & 3) * 2;
                    Ss[r * FP + ci]     = accs[i][jj][dl * 2 + 0] * 0.125f;
                    Ss[r * FP + ci + 1] = accs[i][jj][dl * 2 + 1] * 0.125f;
                }
        __syncthreads();

        // ---- online softmax (4 threads per row, 16 cols each) + P split ----
        const int r = tid >> 2, part = tid & 3, c0 = part << 4;
        float mt = -1e30f;
#pragma unroll
        for (int c = 0; c < 16; c++) mt = fmaxf(mt, Ss[r * FP + c0 + c]);
        pm[(r << 2) + part] = mt;
        __syncthreads();

        float mnew = fmaxf(fmaxf(pm[r << 2], pm[(r << 2) + 1]),
                           fmaxf(pm[(r << 2) + 2], pm[(r << 2) + 3]));
        mnew = fmaxf(mnew, mrow[r]);
        float ssum = 0.f;
        __nv_bfloat16* Prow = (__nv_bfloat16*)(smem + SM_P + r * BROW);
#pragma unroll
        for (int c = 0; c < 16; c++) {
            float p = __expf(Ss[r * FP + c0 + c] - mnew);
            ssum += p;
            __nv_bfloat16 ph = __float2bfloat16(p);
            Prow[c0 + c]      = ph;
            Prow[64 + c0 + c] = __float2bfloat16(p - __bfloat162float(ph));
        }
        pl[(r << 2) + part] = ssum;
        __syncthreads();

        if (part == 0) {
            float a = __expf(mrow[r] - mnew);
            arow[r] = a;
            lrow[r] = lrow[r] * a
                    + pl[r << 2] + pl[(r << 2) + 1] + pl[(r << 2) + 2] + pl[(r << 2) + 3];
            mrow[r] = mnew;
        }
        __syncthreads();

        // ---- rescale acco ----
#pragma unroll
        for (int i = 0; i < 2; i++)
#pragma unroll
            for (int dl = 0; dl < 2; dl++) {
                float a = arow[wm * 32 + i * 16 + (ln >> 2) + dl * 8];
#pragma unroll
                for (int jj = 0; jj < 2; jj++) {
                    acco[i][jj][dl * 2 + 0] *= a;
                    acco[i][jj][dl * 2 + 1] *= a;
                }
            }

        // ---- out += P @ V (3-term split) ----
#pragma unroll
        for (int s = 0; s < 12; s++) {
            int kp, kb2, cb;
            if (s < 4)      { kp = s * 16;            kb2 = s * 16;       cb = 0; }
            else if (s < 8) { kp = 64 + (s - 4) * 16; kb2 = (s - 4) * 16; cb = 0; }
            else            { kp = (s - 8) * 16;      kb2 = (s - 8) * 16; cb = 64; }
            uint32_t afr[2][4];
#pragma unroll
            for (int i = 0; i < 2; i++) {
                int row = wm * 32 + i * 16 + (ln & 15);
                ldsm_x4(afr[i], sb + SM_P + row * BROW + (kp + ((ln >> 4) << 3)) * 2);
            }
            uint32_t bfr[4];
            {
                int krow = kb2 + (ln & 15);
                int ncol = cb + wn * 16 + ((ln & 16) ? 8 : 0);
                ldsm_x4t(bfr, sb + SM_V + krow * BROW + ncol * 2);
            }
#pragma unroll
            for (int i = 0; i < 2; i++)
#pragma unroll
                for (int jj = 0; jj < 2; jj++)
                    mma16816(acco[i][jj], afr[i], bfr[jj * 2], bfr[jj * 2 + 1]);
        }
        __syncthreads();
    }

    // ---- epilogue: normalize, split, write to g_ao2 ----
    const int b = bh >> 4, h = bh & 15;
#pragma unroll
    for (int i = 0; i < 2; i++)
#pragma unroll
        for (int dl = 0; dl < 2; dl++) {
            const int q = wm * 32 + i * 16 + (ln >> 2) + dl * 8;
            const float inv = 1.f / lrow[q];
            const size_t m = (size_t)b * SEQ + (size_t)qt * 64 + q;
#pragma unroll
            for (int jj = 0; jj < 2; jj++) {
                const int d = wn * 16 + jj * 8 + (ln & 3) * 2;
                float v0 = acco[i][jj][dl * 2 + 0] * inv;
                float v1 = acco[i][jj][dl * 2 + 1] * inv;
                __nv_bfloat16 h0, h1, l0v, l1v;
                split2(v0, h0, l0v); split2(v1, h1, l1v);
                const int col = h * 64 + d;
                *(__nv_bfloat162*)(g_ao2 + m * KSPLIT + col) =
                    __halves2bfloat162(h0, h1);
                *(__nv_bfloat162*)(g_ao2 + m * KSPLIT + 1024 + col) =
                    __halves2bfloat162(l0v, l1v);
            }
        }
}

// ---------------- launch --------------------------------------------------
extern "C" void kernel_launch(void* const* d_in, const int* in_sizes, int n_in,
                              void* d_out, int out_size)
{
    const float* x = (const float*)d_in[0];
    const float* W [4] = {(const float*)d_in[1],  (const float*)d_in[5],
                          (const float*)d_in[9],  (const float*)d_in[13]};
    const float* B [4] = {(const float*)d_in[2],  (const float*)d_in[6],
                          (const float*)d_in[10], (const float*)d_in[14]};
    const float* dW[4] = {(const float*)d_in[3],  (const float*)d_in[7],
                          (const float*)d_in[11], (const float*)d_in[15]};
    const float* dB[4] = {(const float*)d_in[4],  (const float*)d_in[8],
                          (const float*)d_in[12], (const float*)d_in[16]};
    float* out = (float*)d_out;

    void *pxs, *pao;
    cudaGetSymbolAddress(&pxs, g_xs);
    cudaGetSymbolAddress(&pao, g_ao2);

    // 1) LoRA merge + split
    for (int l = 0; l < 4; l++)
        merge_lora2<<<1024, 256>>>(W[l], dW[l], dB[l], l);

    // 2) x -> hi/lo split
    prep_split<<<4096, 256>>>(x);

    // 3) QKV projections (HMMA)
    cudaFuncSetAttribute(gemm_hmma, cudaFuncAttributeMaxDynamicSharedMemorySize, GSMEM);
    {
        dim3 grid(D_MODEL / 128, M_TOTAL / 128, 3);
        gemm_hmma<<<grid, 256, GSMEM>>>((const __nv_bfloat16*)pxs, 0, 0,
                                        B[0], B[1], B[2], nullptr);
    }

    // 4) flash attention (HMMA) -> g_ao2
    cudaFuncSetAttribute(flash_hmma, cudaFuncAttributeMaxDynamicSharedMemorySize, ATT_SMEM);
    {
        dim3 grid(SEQ / 64, BATCH * NHEAD);
        flash_hmma<<<grid, 256, ATT_SMEM>>>();
    }

    // 5) O projection (HMMA) -> d_out
    {
        dim3 grid(D_MODEL / 128, M_TOTAL / 128, 1);
        gemm_hmma<<<grid, 256, GSMEM>>>((const __nv_bfloat16*)pao, 1, 3,
                                        B[3], B[3], B[3], out);
    }
}

// round 4
// speedup vs baseline: 3.3735x; 1.0665x over previous
#include <cuda_runtime.h>
#include <cuda_bf16.h>
#include <cstdint>

#define D_MODEL 1024
#define NHEAD   16
#define DHEAD   64
#define SEQ     2048
#define BATCH   2
#define M_TOTAL (BATCH * SEQ)   /* 4096 */
#define RANK    32
#define KSPLIT  2048            /* [hi | lo] concatenated K storage */

// ---------------- device scratch ----------------
__device__ __nv_bfloat16 g_xs [(size_t)M_TOTAL * KSPLIT];
__device__ __nv_bfloat16 g_w2 [(size_t)4 * D_MODEL * KSPLIT];
__device__ __nv_bfloat16 g_ao2[(size_t)M_TOTAL * KSPLIT];
__device__ __nv_bfloat16 g_qs [(size_t)BATCH * NHEAD * SEQ * 128]; // [bh][n][hi64|lo64]
__device__ __nv_bfloat16 g_ks [(size_t)BATCH * NHEAD * SEQ * 128];
__device__ __nv_bfloat16 g_vs [(size_t)BATCH * NHEAD * SEQ * 128];

// ---------------- PTX helpers (baseline PTX only) ----------------
__device__ __forceinline__ uint32_t smem_u32(const void* p) {
    uint32_t a;
    asm("{ .reg .u64 t; cvta.to.shared.u64 t, %1; cvt.u32.u64 %0, t; }" : "=r"(a) : "l"(p));
    return a;
}
__device__ __forceinline__ void cpa16(uint32_t dst, const void* src) {
    asm volatile("cp.async.cg.shared.global [%0], [%1], 16;" :: "r"(dst), "l"(src));
}
#define CP_COMMIT() asm volatile("cp.async.commit_group;" ::: "memory")
#define CP_WAIT(n)  asm volatile("cp.async.wait_group %0;" :: "n"(n) : "memory")

__device__ __forceinline__ void ldsm_x4(uint32_t (&r)[4], uint32_t addr) {
    asm volatile("ldmatrix.sync.aligned.m8n8.x4.shared.b16 {%0,%1,%2,%3}, [%4];"
                 : "=r"(r[0]), "=r"(r[1]), "=r"(r[2]), "=r"(r[3]) : "r"(addr));
}
__device__ __forceinline__ void ldsm_x4t(uint32_t (&r)[4], uint32_t addr) {
    asm volatile("ldmatrix.sync.aligned.m8n8.x4.trans.shared.b16 {%0,%1,%2,%3}, [%4];"
                 : "=r"(r[0]), "=r"(r[1]), "=r"(r[2]), "=r"(r[3]) : "r"(addr));
}
__device__ __forceinline__ void mma16816(float (&d)[4], const uint32_t (&a)[4],
                                         uint32_t b0, uint32_t b1) {
    asm volatile("mma.sync.aligned.m16n8k16.row.col.f32.bf16.bf16.f32 "
                 "{%0,%1,%2,%3}, {%4,%5,%6,%7}, {%8,%9}, {%0,%1,%2,%3};"
                 : "+f"(d[0]), "+f"(d[1]), "+f"(d[2]), "+f"(d[3])
                 : "r"(a[0]), "r"(a[1]), "r"(a[2]), "r"(a[3]), "r"(b0), "r"(b1));
}
__device__ __forceinline__ void split2(float v, __nv_bfloat16& h, __nv_bfloat16& l) {
    h = __float2bfloat16(v);
    l = __float2bfloat16(v - __bfloat162float(h));
}

// ---------------- LoRA merge + bf16 split (all 4 layers, one launch) -------
__global__ void merge_lora2(const float* __restrict__ W0, const float* __restrict__ dW0, const float* __restrict__ dB0,
                            const float* __restrict__ W1, const float* __restrict__ dW1, const float* __restrict__ dB1,
                            const float* __restrict__ W2, const float* __restrict__ dW2, const float* __restrict__ dB2,
                            const float* __restrict__ W3, const float* __restrict__ dW3, const float* __restrict__ dB3)
{
    const int layer = blockIdx.z;
    const float* W  = (layer == 0) ? W0  : (layer == 1) ? W1  : (layer == 2) ? W2  : W3;
    const float* dW = (layer == 0) ? dW0 : (layer == 1) ? dW1 : (layer == 2) ? dW2 : dW3;
    const float* dB = (layer == 0) ? dB0 : (layer == 1) ? dB1 : (layer == 2) ? dB2 : dB3;

    int e  = blockIdx.x * 256 + threadIdx.x;   // float4 index
    int n  = e >> 8;
    int kq = e & 255;
    float4 s = *(const float4*)(W + (size_t)n * D_MODEL + kq * 4);
    const float4* dW4 = (const float4*)dW;
#pragma unroll
    for (int r = 0; r < RANK; r++) {
        float b  = dB[n * RANK + r];
        float4 w = dW4[r * 256 + kq];
        s.x += b * w.x; s.y += b * w.y; s.z += b * w.z; s.w += b * w.w;
    }
    __nv_bfloat16 h0, h1, h2, h3, l0, l1, l2, l3;
    split2(s.x, h0, l0); split2(s.y, h1, l1);
    split2(s.z, h2, l2); split2(s.w, h3, l3);
    size_t rowoff = (size_t)(layer * D_MODEL + n) * KSPLIT;
    __nv_bfloat162* ph = (__nv_bfloat162*)(g_w2 + rowoff + kq * 4);
    __nv_bfloat162* pl = (__nv_bfloat162*)(g_w2 + rowoff + D_MODEL + kq * 4);
    ph[0] = __halves2bfloat162(h0, h1); ph[1] = __halves2bfloat162(h2, h3);
    pl[0] = __halves2bfloat162(l0, l1); pl[1] = __halves2bfloat162(l2, l3);
}

__global__ void prep_split(const float* __restrict__ src)
{
    int e   = blockIdx.x * 256 + threadIdx.x;
    int row = e >> 8;
    int kq  = e & 255;
    float4 s = *(const float4*)(src + (size_t)row * D_MODEL + kq * 4);
    __nv_bfloat16 h0, h1, h2, h3, l0, l1, l2, l3;
    split2(s.x, h0, l0); split2(s.y, h1, l1);
    split2(s.z, h2, l2); split2(s.w, h3, l3);
    size_t rowoff = (size_t)row * KSPLIT;
    __nv_bfloat162* ph = (__nv_bfloat162*)(g_xs + rowoff + kq * 4);
    __nv_bfloat162* pl = (__nv_bfloat162*)(g_xs + rowoff + D_MODEL + kq * 4);
    ph[0] = __halves2bfloat162(h0, h1); ph[1] = __halves2bfloat162(h2, h3);
    pl[0] = __halves2bfloat162(l0, l1); pl[1] = __halves2bfloat162(l2, l3);
}

// ---------------- HMMA GEMM: C[128,128] tile = A @ W^T (+bias) -------------
// virtual K=3072: kp<1024: Ahi*Whi; kp<2048: Ahi*Wlo; else Alo*Whi
#define GKC   64
#define GNCH  48
#define GROWB 144                  /* smem row: 64 bf16 (128B) + 16B pad */
#define GT_BYTES (128 * GROWB)     /* 18432 */
#define GSTAGE   (2 * GT_BYTES)    /* 36864 */
#define GSTAGES  3
#define GSMEM    (GSTAGES * GSTAGE)  /* 110592 */

__global__ void __launch_bounds__(256, 2)
gemm_hmma(const __nv_bfloat16* __restrict__ Abase,  // [*, KSPLIT]
          int mode, int layer_base,
          const float* __restrict__ b0, const float* __restrict__ b1,
          const float* __restrict__ b2, float* __restrict__ outO)
{
    extern __shared__ __align__(128) char smem[];
    const uint32_t sb = smem_u32(smem);
    const int tid = threadIdx.x, ln = tid & 31, w = tid >> 5;
    const int wm = w & 1, wn = w >> 1;     // warp grid 2(m) x 4(n)
    const int bx = blockIdx.x, by = blockIdx.y, z = blockIdx.z;
    const int layer = layer_base + z;

    const __nv_bfloat16* Arow = Abase + (size_t)(by * 128) * KSPLIT;
    const __nv_bfloat16* Wrow = g_w2 + ((size_t)layer * D_MODEL + bx * 128) * KSPLIT;

    float acc[4][4][4] = {};

#define GLOAD(c) do {                                                          \
        int s_ = (c) % GSTAGES;                                                \
        int kp_ = (c) * GKC;                                                   \
        int xA_ = (kp_ < 1024) ? kp_ : kp_ - 1024;                             \
        int xW_ = (kp_ < 2048) ? kp_ : kp_ - 2048;                             \
        uint32_t bA_ = sb + s_ * GSTAGE;                                       \
        uint32_t bW_ = bA_ + GT_BYTES;                                         \
        _Pragma("unroll")                                                      \
        for (int u_ = 0; u_ < 4; u_++) {                                       \
            int e_ = tid + u_ * 256;                                           \
            int row_ = e_ >> 3, seg_ = (e_ & 7) * 16;                          \
            cpa16(bA_ + row_ * GROWB + seg_,                                   \
                  (const char*)(Arow + (size_t)row_ * KSPLIT + xA_) + seg_);   \
            cpa16(bW_ + row_ * GROWB + seg_,                                   \
                  (const char*)(Wrow + (size_t)row_ * KSPLIT + xW_) + seg_);   \
        }                                                                      \
        CP_COMMIT();                                                           \
    } while (0)

    GLOAD(0);
    GLOAD(1);
    for (int c = 0; c < GNCH; c++) {
        if (c + 2 < GNCH) { CP_WAIT(1); } else { CP_WAIT(0); }
        __syncthreads();
        if (c + 2 < GNCH) GLOAD(c + 2);

        const uint32_t bA = sb + (c % GSTAGES) * GSTAGE;
        const uint32_t bW = bA + GT_BYTES;
#pragma unroll
        for (int ks = 0; ks < 4; ks++) {
            const int k0 = ks * 16;
            uint32_t afr[4][4];
#pragma unroll
            for (int i = 0; i < 4; i++) {
                int row = wm * 64 + i * 16 + (ln & 15);
                ldsm_x4(afr[i], bA + row * GROWB + (k0 + ((ln >> 4) << 3)) * 2);
            }
            uint32_t bfr[2][4];
#pragma unroll
            for (int j = 0; j < 2; j++) {
                int n = wn * 32 + j * 16 + (ln & 7) + ((ln & 16) ? 8 : 0);
                ldsm_x4(bfr[j], bW + n * GROWB + (k0 + ((ln & 8) ? 8 : 0)) * 2);
            }
#pragma unroll
            for (int i = 0; i < 4; i++)
#pragma unroll
                for (int jj = 0; jj < 4; jj++)
                    mma16816(acc[i][jj], afr[i], bfr[jj >> 1][(jj & 1) * 2],
                             bfr[jj >> 1][(jj & 1) * 2 + 1]);
        }
    }

    // epilogue
    const float* bias = (z == 0) ? b0 : (z == 1) ? b1 : b2;
    __nv_bfloat16* qkv = (z == 0) ? g_qs : (z == 1) ? g_ks : g_vs;
    const float qscale = (mode == 0 && z == 0) ? 0.125f : 1.0f;  // fold 1/sqrt(64) into Q
#pragma unroll
    for (int i = 0; i < 4; i++) {
#pragma unroll
        for (int dl = 0; dl < 2; dl++) {
            const int m = by * 128 + wm * 64 + i * 16 + (ln >> 2) + dl * 8;
#pragma unroll
            for (int jj = 0; jj < 4; jj++) {
                const int cgl = bx * 128 + wn * 32 + jj * 8 + (ln & 3) * 2;
                float v0 = (acc[i][jj][dl * 2 + 0] + bias[cgl])     * qscale;
                float v1 = (acc[i][jj][dl * 2 + 1] + bias[cgl + 1]) * qscale;
                if (mode == 0) {
                    const int h = cgl >> 6, d = cgl & 63;
                    const int b = m >> 11, n = m & 2047;
                    __nv_bfloat16* base = qkv + ((size_t)(b * NHEAD + h) * SEQ + n) * 128;
                    __nv_bfloat16 h0, h1, l0v, l1v;
                    split2(v0, h0, l0v); split2(v1, h1, l1v);
                    *(__nv_bfloat162*)(base + d)      = __halves2bfloat162(h0, h1);
                    *(__nv_bfloat162*)(base + 64 + d) = __halves2bfloat162(l0v, l1v);
                } else {
                    float2 o; o.x = v0; o.y = v1;
                    *(float2*)(outO + (size_t)m * D_MODEL + cgl) = o;
                }
            }
        }
    }
}

// ---------------- Flash attention (HMMA, reg softmax, double-buffered) -----
#define BROW  272     /* bf16 tile row bytes: 128 data + 8 pad bf16 */
#define TILEB 17408   /* 64 * BROW */
#define SM_Q  0
#define SM_K0 17408
#define SM_K1 34816
#define SM_V0 52224
#define SM_V1 69632
#define SM_P  87040
#define SM_SCR 104448 /* mrow[64] lrow[64] arow[64] pm[256] pl[256] */
#define ATT_SMEM (SM_SCR + 704 * 4)   /* 107264 */
#define NT (SEQ / 64)

__global__ void __launch_bounds__(256, 2)
flash_hmma()
{
    extern __shared__ __align__(128) char smem[];
    const uint32_t sb = smem_u32(smem);
    float* mrow = (float*)(smem + SM_SCR);
    float* lrow = mrow + 64;
    float* arow = lrow + 64;
    float* pm   = arow + 64;
    float* pl   = pm + 256;

    const int tid = threadIdx.x, ln = tid & 31, w = tid >> 5;
    const int wm = w & 1, wn = w >> 1;     // warp grid 2(m) x 4(n)
    const int qt = blockIdx.x, bh = blockIdx.y;

    const __nv_bfloat16* qg = g_qs + ((size_t)bh * SEQ + qt * 64) * 128;
    const __nv_bfloat16* kg = g_ks + (size_t)bh * SEQ * 128;
    const __nv_bfloat16* vg = g_vs + (size_t)bh * SEQ * 128;

    // Q tile load (group 0)
#pragma unroll
    for (int u = 0; u < 4; u++) {
        int e = tid + u * 256;
        int row = e >> 4, seg = (e & 15) * 16;
        cpa16(sb + SM_Q + row * BROW + seg, (const char*)(qg + (size_t)row * 128) + seg);
    }
    CP_COMMIT();

#define ATT_LOAD(t) do {                                                       \
        int buf_ = (t) & 1;                                                    \
        const __nv_bfloat16* kb_ = kg + (size_t)(t) * 64 * 128;                \
        const __nv_bfloat16* vb_ = vg + (size_t)(t) * 64 * 128;                \
        uint32_t kd_ = sb + SM_K0 + buf_ * TILEB;                              \
        uint32_t vd_ = sb + SM_V0 + buf_ * TILEB;                              \
        _Pragma("unroll")                                                      \
        for (int u_ = 0; u_ < 4; u_++) {                                       \
            int e_ = tid + u_ * 256;                                           \
            int row_ = e_ >> 4, seg_ = (e_ & 15) * 16;                         \
            cpa16(kd_ + row_ * BROW + seg_,                                    \
                  (const char*)(kb_ + (size_t)row_ * 128) + seg_);             \
            cpa16(vd_ + row_ * BROW + seg_,                                    \
                  (const char*)(vb_ + (size_t)row_ * 128) + seg_);             \
        }                                                                      \
        CP_COMMIT();                                                           \
    } while (0)

    ATT_LOAD(0);
    if (tid < 64) { mrow[tid] = -1e30f; lrow[tid] = 0.f; }

    float acco[2][2][4] = {};

    for (int kt = 0; kt < NT; kt++) {
        CP_WAIT(0);
        __syncthreads();                       // tiles visible; prev iter done
        if (kt + 1 < NT) ATT_LOAD(kt + 1);     // overlaps with all compute below

        const uint32_t bK = sb + SM_K0 + (kt & 1) * TILEB;
        const uint32_t bV = sb + SM_V0 + (kt & 1) * TILEB;

        // ---- S = Q K^T (3-term split), accumulators stay in registers ----
        float accs[2][2][4] = {};
#pragma unroll
        for (int s = 0; s < 12; s++) {
            int kq, kk;
            if (s < 4)      { kq = s * 16;            kk = s * 16; }
            else if (s < 8) { kq = (s - 4) * 16;      kk = 64 + (s - 4) * 16; }
            else            { kq = 64 + (s - 8) * 16; kk = (s - 8) * 16; }
            uint32_t afr[2][4];
#pragma unroll
            for (int i = 0; i < 2; i++) {
                int row = wm * 32 + i * 16 + (ln & 15);
                ldsm_x4(afr[i], sb + SM_Q + row * BROW + (kq + ((ln >> 4) << 3)) * 2);
            }
            uint32_t bfr[4];
            {
                int n = wn * 16 + (ln & 7) + ((ln & 16) ? 8 : 0);
                ldsm_x4(bfr, bK + n * BROW + (kk + ((ln & 8) ? 8 : 0)) * 2);
            }
#pragma unroll
            for (int i = 0; i < 2; i++)
#pragma unroll
                for (int jj = 0; jj < 2; jj++)
                    mma16816(accs[i][jj], afr[i], bfr[jj * 2], bfr[jj * 2 + 1]);
        }

        // ---- row max: thread-local + shfl over lane quad, partials to pm ----
#pragma unroll
        for (int i = 0; i < 2; i++)
#pragma unroll
            for (int dl = 0; dl < 2; dl++) {
                float v = fmaxf(fmaxf(accs[i][0][dl * 2], accs[i][0][dl * 2 + 1]),
                                fmaxf(accs[i][1][dl * 2], accs[i][1][dl * 2 + 1]));
                v = fmaxf(v, __shfl_xor_sync(0xffffffffu, v, 1));
                v = fmaxf(v, __shfl_xor_sync(0xffffffffu, v, 2));
                if ((ln & 3) == 0) {
                    int row = wm * 32 + i * 16 + (ln >> 2) + dl * 8;
                    pm[row * 4 + wn] = v;
                }
            }
        __syncthreads();

        if (tid < 64) {
            int r = tid;
            float mnew = fmaxf(fmaxf(pm[r * 4], pm[r * 4 + 1]),
                               fmaxf(pm[r * 4 + 2], pm[r * 4 + 3]));
            mnew = fmaxf(mnew, mrow[r]);
            float a = __expf(mrow[r] - mnew);
            arow[r] = a;
            mrow[r] = mnew;
            lrow[r] *= a;
        }
        __syncthreads();

        // ---- exp on registers, write split P, row sums, rescale acco ----
#pragma unroll
        for (int i = 0; i < 2; i++)
#pragma unroll
            for (int dl = 0; dl < 2; dl++) {
                const int row = wm * 32 + i * 16 + (ln >> 2) + dl * 8;
                const float mn = mrow[row];
                const float a  = arow[row];
                float sum = 0.f;
#pragma unroll
                for (int jj = 0; jj < 2; jj++) {
                    float p0 = __expf(accs[i][jj][dl * 2 + 0] - mn);
                    float p1 = __expf(accs[i][jj][dl * 2 + 1] - mn);
                    sum += p0 + p1;
                    __nv_bfloat16 h0, l0v, h1, l1v;
                    split2(p0, h0, l0v); split2(p1, h1, l1v);
                    const int col = wn * 16 + jj * 8 + (ln & 3) * 2;
                    *(__nv_bfloat162*)(smem + SM_P + row * BROW + col * 2) =
                        __halves2bfloat162(h0, h1);
                    *(__nv_bfloat162*)(smem + SM_P + row * BROW + 128 + col * 2) =
                        __halves2bfloat162(l0v, l1v);
                    acco[i][jj][dl * 2 + 0] *= a;
                    acco[i][jj][dl * 2 + 1] *= a;
                }
                sum += __shfl_xor_sync(0xffffffffu, sum, 1);
                sum += __shfl_xor_sync(0xffffffffu, sum, 2);
                if ((ln & 3) == 0) pl[row * 4 + wn] = sum;
            }
        __syncthreads();

        if (tid < 64)
            lrow[tid] += pl[tid * 4] + pl[tid * 4 + 1] + pl[tid * 4 + 2] + pl[tid * 4 + 3];

        // ---- out += P @ V (3-term split) ----
#pragma unroll
        for (int s = 0; s < 12; s++) {
            int kp, kb2, cb;
            if (s < 4)      { kp = s * 16;            kb2 = s * 16;       cb = 0; }
            else if (s < 8) { kp = 64 + (s - 4) * 16; kb2 = (s - 4) * 16; cb = 0; }
            else            { kp = (s - 8) * 16;      kb2 = (s - 8) * 16; cb = 64; }
            uint32_t afr[2][4];
#pragma unroll
            for (int i = 0; i < 2; i++) {
                int row = wm * 32 + i * 16 + (ln & 15);
                ldsm_x4(afr[i], sb + SM_P + row * BROW + (kp + ((ln >> 4) << 3)) * 2);
            }
            uint32_t bfr[4];
            {
                int krow = kb2 + (ln & 15);
                int ncol = cb + wn * 16 + ((ln & 16) ? 8 : 0);
                ldsm_x4t(bfr, bV + krow * BROW + ncol * 2);
            }
#pragma unroll
            for (int i = 0; i < 2; i++)
#pragma unroll
                for (int jj = 0; jj < 2; jj++)
                    mma16816(acco[i][jj], afr[i], bfr[jj * 2], bfr[jj * 2 + 1]);
        }
        // no end-of-iter barrier needed: next iteration's top barrier protects
        // P/pm/pl reuse, and the in-flight load targets the opposite buffer.
    }
    __syncthreads();   // lrow final values visible

    // ---- epilogue: normalize, split, write to g_ao2 ----
    const int b = bh >> 4, h = bh & 15;
#pragma unroll
    for (int i = 0; i < 2; i++)
#pragma unroll
        for (int dl = 0; dl < 2; dl++) {
            const int q = wm * 32 + i * 16 + (ln >> 2) + dl * 8;
            const float inv = 1.f / lrow[q];
            const size_t m = (size_t)b * SEQ + (size_t)qt * 64 + q;
#pragma unroll
            for (int jj = 0; jj < 2; jj++) {
                const int d = wn * 16 + jj * 8 + (ln & 3) * 2;
                float v0 = acco[i][jj][dl * 2 + 0] * inv;
                float v1 = acco[i][jj][dl * 2 + 1] * inv;
                __nv_bfloat16 h0, h1, l0v, l1v;
                split2(v0, h0, l0v); split2(v1, h1, l1v);
                const int col = h * 64 + d;
                *(__nv_bfloat162*)(g_ao2 + m * KSPLIT + col) =
                    __halves2bfloat162(h0, h1);
                *(__nv_bfloat162*)(g_ao2 + m * KSPLIT + 1024 + col) =
                    __halves2bfloat162(l0v, l1v);
            }
        }
}

// ---------------- launch --------------------------------------------------
extern "C" void kernel_launch(void* const* d_in, const int* in_sizes, int n_in,
                              void* d_out, int out_size)
{
    const float* x = (const float*)d_in[0];
    const float* W [4] = {(const float*)d_in[1],  (const float*)d_in[5],
                          (const float*)d_in[9],  (const float*)d_in[13]};
    const float* B [4] = {(const float*)d_in[2],  (const float*)d_in[6],
                          (const float*)d_in[10], (const float*)d_in[14]};
    const float* dW[4] = {(const float*)d_in[3],  (const float*)d_in[7],
                          (const float*)d_in[11], (const float*)d_in[15]};
    const float* dB[4] = {(const float*)d_in[4],  (const float*)d_in[8],
                          (const float*)d_in[12], (const float*)d_in[16]};
    float* out = (float*)d_out;

    void *pxs, *pao;
    cudaGetSymbolAddress(&pxs, g_xs);
    cudaGetSymbolAddress(&pao, g_ao2);

    // 1) LoRA merge + split (one launch, 4 layers via grid.z)
    {
        dim3 grid(1024, 1, 4);
        merge_lora2<<<grid, 256>>>(W[0], dW[0], dB[0], W[1], dW[1], dB[1],
                                   W[2], dW[2], dB[2], W[3], dW[3], dB[3]);
    }

    // 2) x -> hi/lo split
    prep_split<<<4096, 256>>>(x);

    // 3) QKV projections (HMMA)
    cudaFuncSetAttribute(gemm_hmma, cudaFuncAttributeMaxDynamicSharedMemorySize, GSMEM);
    {
        dim3 grid(D_MODEL / 128, M_TOTAL / 128, 3);
        gemm_hmma<<<grid, 256, GSMEM>>>((const __nv_bfloat16*)pxs, 0, 0,
                                        B[0], B[1], B[2], nullptr);
    }

    // 4) flash attention (HMMA) -> g_ao2
    cudaFuncSetAttribute(flash_hmma, cudaFuncAttributeMaxDynamicSharedMemorySize, ATT_SMEM);
    {
        dim3 grid(SEQ / 64, BATCH * NHEAD);
        flash_hmma<<<grid, 256, ATT_SMEM>>>();
    }

    // 5) O projection (HMMA) -> d_out
    {
        dim3 grid(D_MODEL / 128, M_TOTAL / 128, 1);
        gemm_hmma<<<grid, 256, GSMEM>>>((const __nv_bfloat16*)pao, 1, 3,
                                        B[3], B[3], B[3], out);
    }
}

// round 5
// speedup vs baseline: 3.7031x; 1.0977x over previous
#include <cuda_runtime.h>
#include <cuda_bf16.h>
#include <cstdint>

#define D_MODEL 1024
#define NHEAD   16
#define DHEAD   64
#define SEQ     2048
#define BATCH   2
#define M_TOTAL (BATCH * SEQ)   /* 4096 */
#define RANK    32
#define KSPLIT  2048            /* [hi | lo] concatenated K storage */

// ---------------- device scratch ----------------
__device__ __nv_bfloat16 g_xs [(size_t)M_TOTAL * KSPLIT];
__device__ __nv_bfloat16 g_w2 [(size_t)4 * D_MODEL * KSPLIT];
__device__ __nv_bfloat16 g_ao2[(size_t)M_TOTAL * KSPLIT];
__device__ __nv_bfloat16 g_qs [(size_t)BATCH * NHEAD * SEQ * 128]; // [bh][n][hi64|lo64]
__device__ __nv_bfloat16 g_ks [(size_t)BATCH * NHEAD * SEQ * 128];
__device__ __nv_bfloat16 g_vs [(size_t)BATCH * NHEAD * SEQ * 128];

// ---------------- PTX helpers (baseline PTX only) ----------------
__device__ __forceinline__ uint32_t smem_u32(const void* p) {
    uint32_t a;
    asm("{ .reg .u64 t; cvta.to.shared.u64 t, %1; cvt.u32.u64 %0, t; }" : "=r"(a) : "l"(p));
    return a;
}
__device__ __forceinline__ void cpa16(uint32_t dst, const void* src) {
    asm volatile("cp.async.cg.shared.global [%0], [%1], 16;" :: "r"(dst), "l"(src));
}
#define CP_COMMIT() asm volatile("cp.async.commit_group;" ::: "memory")
#define CP_WAIT(n)  asm volatile("cp.async.wait_group %0;" :: "n"(n) : "memory")

__device__ __forceinline__ void ldsm_x4(uint32_t (&r)[4], uint32_t addr) {
    asm volatile("ldmatrix.sync.aligned.m8n8.x4.shared.b16 {%0,%1,%2,%3}, [%4];"
                 : "=r"(r[0]), "=r"(r[1]), "=r"(r[2]), "=r"(r[3]) : "r"(addr));
}
__device__ __forceinline__ void ldsm_x4t(uint32_t (&r)[4], uint32_t addr) {
    asm volatile("ldmatrix.sync.aligned.m8n8.x4.trans.shared.b16 {%0,%1,%2,%3}, [%4];"
                 : "=r"(r[0]), "=r"(r[1]), "=r"(r[2]), "=r"(r[3]) : "r"(addr));
}
__device__ __forceinline__ void mma16816(float (&d)[4], const uint32_t (&a)[4],
                                         uint32_t b0, uint32_t b1) {
    asm volatile("mma.sync.aligned.m16n8k16.row.col.f32.bf16.bf16.f32 "
                 "{%0,%1,%2,%3}, {%4,%5,%6,%7}, {%8,%9}, {%0,%1,%2,%3};"
                 : "+f"(d[0]), "+f"(d[1]), "+f"(d[2]), "+f"(d[3])
                 : "r"(a[0]), "r"(a[1]), "r"(a[2]), "r"(a[3]), "r"(b0), "r"(b1));
}
__device__ __forceinline__ void split2(float v, __nv_bfloat16& h, __nv_bfloat16& l) {
    h = __float2bfloat16(v);
    l = __float2bfloat16(v - __bfloat162float(h));
}
// pack (v0 -> lo, v1 -> hi) into bf16x2, producing hi and lo split parts
__device__ __forceinline__ void packsplit2(float v0, float v1, uint32_t& hi, uint32_t& lo) {
    __nv_bfloat16 h0, h1, l0, l1;
    split2(v0, h0, l0); split2(v1, h1, l1);
    __nv_bfloat162 th = __halves2bfloat162(h0, h1);
    __nv_bfloat162 tl = __halves2bfloat162(l0, l1);
    hi = reinterpret_cast<uint32_t&>(th);
    lo = reinterpret_cast<uint32_t&>(tl);
}

// ---------------- LoRA merge + bf16 split (all 4 layers, one launch) -------
__global__ void merge_lora2(const float* __restrict__ W0, const float* __restrict__ dW0, const float* __restrict__ dB0,
                            const float* __restrict__ W1, const float* __restrict__ dW1, const float* __restrict__ dB1,
                            const float* __restrict__ W2, const float* __restrict__ dW2, const float* __restrict__ dB2,
                            const float* __restrict__ W3, const float* __restrict__ dW3, const float* __restrict__ dB3)
{
    const int layer = blockIdx.z;
    const float* W  = (layer == 0) ? W0  : (layer == 1) ? W1  : (layer == 2) ? W2  : W3;
    const float* dW = (layer == 0) ? dW0 : (layer == 1) ? dW1 : (layer == 2) ? dW2 : dW3;
    const float* dB = (layer == 0) ? dB0 : (layer == 1) ? dB1 : (layer == 2) ? dB2 : dB3;

    int e  = blockIdx.x * 256 + threadIdx.x;
    int n  = e >> 8;
    int kq = e & 255;
    float4 s = *(const float4*)(W + (size_t)n * D_MODEL + kq * 4);
    const float4* dW4 = (const float4*)dW;
#pragma unroll
    for (int r = 0; r < RANK; r++) {
        float b  = dB[n * RANK + r];
        float4 w = dW4[r * 256 + kq];
        s.x += b * w.x; s.y += b * w.y; s.z += b * w.z; s.w += b * w.w;
    }
    __nv_bfloat16 h0, h1, h2, h3, l0, l1, l2, l3;
    split2(s.x, h0, l0); split2(s.y, h1, l1);
    split2(s.z, h2, l2); split2(s.w, h3, l3);
    size_t rowoff = (size_t)(layer * D_MODEL + n) * KSPLIT;
    __nv_bfloat162* ph = (__nv_bfloat162*)(g_w2 + rowoff + kq * 4);
    __nv_bfloat162* pl = (__nv_bfloat162*)(g_w2 + rowoff + D_MODEL + kq * 4);
    ph[0] = __halves2bfloat162(h0, h1); ph[1] = __halves2bfloat162(h2, h3);
    pl[0] = __halves2bfloat162(l0, l1); pl[1] = __halves2bfloat162(l2, l3);
}

__global__ void prep_split(const float* __restrict__ src)
{
    int e   = blockIdx.x * 256 + threadIdx.x;
    int row = e >> 8;
    int kq  = e & 255;
    float4 s = *(const float4*)(src + (size_t)row * D_MODEL + kq * 4);
    __nv_bfloat16 h0, h1, h2, h3, l0, l1, l2, l3;
    split2(s.x, h0, l0); split2(s.y, h1, l1);
    split2(s.z, h2, l2); split2(s.w, h3, l3);
    size_t rowoff = (size_t)row * KSPLIT;
    __nv_bfloat162* ph = (__nv_bfloat162*)(g_xs + rowoff + kq * 4);
    __nv_bfloat162* pl = (__nv_bfloat162*)(g_xs + rowoff + D_MODEL + kq * 4);
    ph[0] = __halves2bfloat162(h0, h1); ph[1] = __halves2bfloat162(h2, h3);
    pl[0] = __halves2bfloat162(l0, l1); pl[1] = __halves2bfloat162(l2, l3);
}

// ---------------- HMMA GEMM: C[128,128] tile = A @ W^T (+bias) -------------
#define GKC   64
#define GNCH  48
#define GROWB 144
#define GT_BYTES (128 * GROWB)
#define GSTAGE   (2 * GT_BYTES)
#define GSTAGES  3
#define GSMEM    (GSTAGES * GSTAGE)

__global__ void __launch_bounds__(256, 2)
gemm_hmma(const __nv_bfloat16* __restrict__ Abase,
          int mode, int layer_base,
          const float* __restrict__ b0, const float* __restrict__ b1,
          const float* __restrict__ b2, float* __restrict__ outO)
{
    extern __shared__ __align__(128) char smem[];
    const uint32_t sb = smem_u32(smem);
    const int tid = threadIdx.x, ln = tid & 31, w = tid >> 5;
    const int wm = w & 1, wn = w >> 1;
    const int bx = blockIdx.x, by = blockIdx.y, z = blockIdx.z;
    const int layer = layer_base + z;

    const __nv_bfloat16* Arow = Abase + (size_t)(by * 128) * KSPLIT;
    const __nv_bfloat16* Wrow = g_w2 + ((size_t)layer * D_MODEL + bx * 128) * KSPLIT;

    float acc[4][4][4] = {};

#define GLOAD(c) do {                                                          \
        int s_ = (c) % GSTAGES;                                                \
        int kp_ = (c) * GKC;                                                   \
        int xA_ = (kp_ < 1024) ? kp_ : kp_ - 1024;                             \
        int xW_ = (kp_ < 2048) ? kp_ : kp_ - 2048;                             \
        uint32_t bA_ = sb + s_ * GSTAGE;                                       \
        uint32_t bW_ = bA_ + GT_BYTES;                                         \
        _Pragma("unroll")                                                      \
        for (int u_ = 0; u_ < 4; u_++) {                                       \
            int e_ = tid + u_ * 256;                                           \
            int row_ = e_ >> 3, seg_ = (e_ & 7) * 16;                          \
            cpa16(bA_ + row_ * GROWB + seg_,                                   \
                  (const char*)(Arow + (size_t)row_ * KSPLIT + xA_) + seg_);   \
            cpa16(bW_ + row_ * GROWB + seg_,                                   \
                  (const char*)(Wrow + (size_t)row_ * KSPLIT + xW_) + seg_);   \
        }                                                                      \
        CP_COMMIT();                                                           \
    } while (0)

    GLOAD(0);
    GLOAD(1);
    for (int c = 0; c < GNCH; c++) {
        if (c + 2 < GNCH) { CP_WAIT(1); } else { CP_WAIT(0); }
        __syncthreads();
        if (c + 2 < GNCH) GLOAD(c + 2);

        const uint32_t bA = sb + (c % GSTAGES) * GSTAGE;
        const uint32_t bW = bA + GT_BYTES;
#pragma unroll
        for (int ks = 0; ks < 4; ks++) {
            const int k0 = ks * 16;
            uint32_t afr[4][4];
#pragma unroll
            for (int i = 0; i < 4; i++) {
                int row = wm * 64 + i * 16 + (ln & 15);
                ldsm_x4(afr[i], bA + row * GROWB + (k0 + ((ln >> 4) << 3)) * 2);
            }
            uint32_t bfr[2][4];
#pragma unroll
            for (int j = 0; j < 2; j++) {
                int n = wn * 32 + j * 16 + (ln & 7) + ((ln & 16) ? 8 : 0);
                ldsm_x4(bfr[j], bW + n * GROWB + (k0 + ((ln & 8) ? 8 : 0)) * 2);
            }
#pragma unroll
            for (int i = 0; i < 4; i++)
#pragma unroll
                for (int jj = 0; jj < 4; jj++)
                    mma16816(acc[i][jj], afr[i], bfr[jj >> 1][(jj & 1) * 2],
                             bfr[jj >> 1][(jj & 1) * 2 + 1]);
        }
    }

    const float* bias = (z == 0) ? b0 : (z == 1) ? b1 : b2;
    __nv_bfloat16* qkv = (z == 0) ? g_qs : (z == 1) ? g_ks : g_vs;
    const float qscale = (mode == 0 && z == 0) ? 0.125f : 1.0f;
#pragma unroll
    for (int i = 0; i < 4; i++) {
#pragma unroll
        for (int dl = 0; dl < 2; dl++) {
            const int m = by * 128 + wm * 64 + i * 16 + (ln >> 2) + dl * 8;
#pragma unroll
            for (int jj = 0; jj < 4; jj++) {
                const int cgl = bx * 128 + wn * 32 + jj * 8 + (ln & 3) * 2;
                float v0 = (acc[i][jj][dl * 2 + 0] + bias[cgl])     * qscale;
                float v1 = (acc[i][jj][dl * 2 + 1] + bias[cgl + 1]) * qscale;
                if (mode == 0) {
                    const int h = cgl >> 6, d = cgl & 63;
                    const int b = m >> 11, n = m & 2047;
                    __nv_bfloat16* base = qkv + ((size_t)(b * NHEAD + h) * SEQ + n) * 128;
                    __nv_bfloat16 h0, h1, l0v, l1v;
                    split2(v0, h0, l0v); split2(v1, h1, l1v);
                    *(__nv_bfloat162*)(base + d)      = __halves2bfloat162(h0, h1);
                    *(__nv_bfloat162*)(base + 64 + d) = __halves2bfloat162(l0v, l1v);
                } else {
                    float2 o; o.x = v0; o.y = v1;
                    *(float2*)(outO + (size_t)m * D_MODEL + cgl) = o;
                }
            }
        }
    }
}

// ---------------- Flash attention: FA2 warp-per-rowblock -------------------
// CTA: 128 q-rows, 8 warps x 16 rows each; warp owns FULL 64 k-cols.
// Softmax entirely warp-local; P repacked from S fragments in registers.
#define BROW  272
#define TILEB 17408                       /* 64 * BROW */
#define QROWS 128
#define SM_Q   0
#define QBYTES (QROWS * BROW)             /* 34816 */
#define SM_K0  QBYTES
#define SM_K1  (SM_K0 + TILEB)
#define SM_V0  (SM_K1 + TILEB)
#define SM_V1  (SM_V0 + TILEB)
#define ATT_SMEM (SM_V1 + TILEB)          /* 104448 */
#define NT (SEQ / 64)

__global__ void __launch_bounds__(256, 2)
flash_hmma()
{
    extern __shared__ __align__(128) char smem[];
    const uint32_t sb = smem_u32(smem);
    const int tid = threadIdx.x, ln = tid & 31, w = tid >> 5;
    const int qt = blockIdx.x, bh = blockIdx.y;

    const __nv_bfloat16* qg = g_qs + ((size_t)bh * SEQ + qt * QROWS) * 128;
    const __nv_bfloat16* kg = g_ks + (size_t)bh * SEQ * 128;
    const __nv_bfloat16* vg = g_vs + (size_t)bh * SEQ * 128;

    // Q tile: 128 rows x 256B = 2048 x 16B
#pragma unroll
    for (int u = 0; u < 8; u++) {
        int e = tid + u * 256;
        int row = e >> 4, seg = (e & 15) * 16;
        cpa16(sb + SM_Q + row * BROW + seg, (const char*)(qg + (size_t)row * 128) + seg);
    }
    CP_COMMIT();

#define ATT_LOAD(t) do {                                                       \
        int buf_ = (t) & 1;                                                    \
        const __nv_bfloat16* kb_ = kg + (size_t)(t) * 64 * 128;                \
        const __nv_bfloat16* vb_ = vg + (size_t)(t) * 64 * 128;                \
        uint32_t kd_ = sb + SM_K0 + buf_ * TILEB;                              \
        uint32_t vd_ = sb + SM_V0 + buf_ * TILEB;                              \
        _Pragma("unroll")                                                      \
        for (int u_ = 0; u_ < 4; u_++) {                                       \
            int e_ = tid + u_ * 256;                                           \
            int row_ = e_ >> 4, seg_ = (e_ & 15) * 16;                         \
            cpa16(kd_ + row_ * BROW + seg_,                                    \
                  (const char*)(kb_ + (size_t)row_ * 128) + seg_);             \
            cpa16(vd_ + row_ * BROW + seg_,                                    \
                  (const char*)(vb_ + (size_t)row_ * 128) + seg_);             \
        }                                                                      \
        CP_COMMIT();                                                           \
    } while (0)

    ATT_LOAD(0);
    CP_WAIT(0);
    __syncthreads();

    // resident Q-hi fragments (Q-lo streamed from smem inside the loop)
    const uint32_t qaddr = sb + SM_Q + (w * 16 + (ln & 15)) * BROW + (((ln >> 4) << 3)) * 2;
    uint32_t qhi[4][4];
#pragma unroll
    for (int s = 0; s < 4; s++)
        ldsm_x4(qhi[s], qaddr + (s * 16) * 2);

    const int krow8  = (ln & 7) + ((ln & 16) ? 8 : 0);
    const int kcol8  = (ln & 8) ? 8 : 0;
    const int vrow16 = ln & 15;
    const int vcol8  = (ln & 16) ? 8 : 0;

    float m0 = -1e30f, m1 = -1e30f, l0 = 0.f, l1 = 0.f;
    float acco[8][4] = {};

    for (int kt = 0; kt < NT; kt++) {
        if (kt > 0) { CP_WAIT(0); __syncthreads(); }
        if (kt + 1 < NT) ATT_LOAD(kt + 1);
        const uint32_t bK = sb + SM_K0 + (kt & 1) * TILEB;
        const uint32_t bV = sb + SM_V0 + (kt & 1) * TILEB;

        // ---- S = Q K^T (3-term split): K-hi slices serve Qhi and Qlo ----
        float accs[8][4] = {};
#pragma unroll
        for (int ks = 0; ks < 4; ks++) {
            uint32_t ql[4];
            ldsm_x4(ql, qaddr + (64 + ks * 16) * 2);
#pragma unroll
            for (int nbp = 0; nbp < 4; nbp++) {
                uint32_t kb[4];
                ldsm_x4(kb, bK + (nbp * 16 + krow8) * BROW + (ks * 16 + kcol8) * 2);
                mma16816(accs[2 * nbp],     qhi[ks], kb[0], kb[1]);
                mma16816(accs[2 * nbp + 1], qhi[ks], kb[2], kb[3]);
                mma16816(accs[2 * nbp],     ql,      kb[0], kb[1]);
                mma16816(accs[2 * nbp + 1], ql,      kb[2], kb[3]);
            }
        }
#pragma unroll
        for (int ks = 0; ks < 4; ks++) {
#pragma unroll
            for (int nbp = 0; nbp < 4; nbp++) {
                uint32_t kb[4];
                ldsm_x4(kb, bK + (nbp * 16 + krow8) * BROW + (64 + ks * 16 + kcol8) * 2);
                mma16816(accs[2 * nbp],     qhi[ks], kb[0], kb[1]);
                mma16816(accs[2 * nbp + 1], qhi[ks], kb[2], kb[3]);
            }
        }

        // ---- warp-local online softmax (rows r0 = ln>>2, r1 = r0+8) ----
        float mx0 = -1e30f, mx1 = -1e30f;
#pragma unroll
        for (int jj = 0; jj < 8; jj++) {
            mx0 = fmaxf(mx0, fmaxf(accs[jj][0], accs[jj][1]));
            mx1 = fmaxf(mx1, fmaxf(accs[jj][2], accs[jj][3]));
        }
        mx0 = fmaxf(mx0, __shfl_xor_sync(0xffffffffu, mx0, 1));
        mx0 = fmaxf(mx0, __shfl_xor_sync(0xffffffffu, mx0, 2));
        mx1 = fmaxf(mx1, __shfl_xor_sync(0xffffffffu, mx1, 1));
        mx1 = fmaxf(mx1, __shfl_xor_sync(0xffffffffu, mx1, 2));
        const float mn0 = fmaxf(m0, mx0), mn1 = fmaxf(m1, mx1);
        const float a0 = __expf(m0 - mn0), a1 = __expf(m1 - mn1);
        m0 = mn0; m1 = mn1;

        float s0 = 0.f, s1 = 0.f;
#pragma unroll
        for (int jj = 0; jj < 8; jj++) {
            accs[jj][0] = __expf(accs[jj][0] - mn0);
            accs[jj][1] = __expf(accs[jj][1] - mn0);
            accs[jj][2] = __expf(accs[jj][2] - mn1);
            accs[jj][3] = __expf(accs[jj][3] - mn1);
            s0 += accs[jj][0] + accs[jj][1];
            s1 += accs[jj][2] + accs[jj][3];
        }
        s0 += __shfl_xor_sync(0xffffffffu, s0, 1);
        s0 += __shfl_xor_sync(0xffffffffu, s0, 2);
        s1 += __shfl_xor_sync(0xffffffffu, s1, 1);
        s1 += __shfl_xor_sync(0xffffffffu, s1, 2);
        l0 = l0 * a0 + s0;
        l1 = l1 * a1 + s1;
#pragma unroll
        for (int jj = 0; jj < 8; jj++) {
            acco[jj][0] *= a0; acco[jj][1] *= a0;
            acco[jj][2] *= a1; acco[jj][3] *= a1;
        }

        // ---- out += P @ V: P fragments repacked from S regs (no smem) ----
#pragma unroll
        for (int ks = 0; ks < 4; ks++) {
            uint32_t phi[4], plo[4];
            packsplit2(accs[2 * ks][0],     accs[2 * ks][1],     phi[0], plo[0]);
            packsplit2(accs[2 * ks][2],     accs[2 * ks][3],     phi[1], plo[1]);
            packsplit2(accs[2 * ks + 1][0], accs[2 * ks + 1][1], phi[2], plo[2]);
            packsplit2(accs[2 * ks + 1][2], accs[2 * ks + 1][3], phi[3], plo[3]);
#pragma unroll
            for (int nbp = 0; nbp < 4; nbp++) {
                uint32_t vb[4];
                ldsm_x4t(vb, bV + (ks * 16 + vrow16) * BROW + (nbp * 16 + vcol8) * 2);
                mma16816(acco[2 * nbp],     phi, vb[0], vb[1]);
                mma16816(acco[2 * nbp + 1], phi, vb[2], vb[3]);
                mma16816(acco[2 * nbp],     plo, vb[0], vb[1]);
                mma16816(acco[2 * nbp + 1], plo, vb[2], vb[3]);
            }
#pragma unroll
            for (int nbp = 0; nbp < 4; nbp++) {
                uint32_t vb[4];
                ldsm_x4t(vb, bV + (ks * 16 + vrow16) * BROW + (64 + nbp * 16 + vcol8) * 2);
                mma16816(acco[2 * nbp],     phi, vb[0], vb[1]);
                mma16816(acco[2 * nbp + 1], phi, vb[2], vb[3]);
            }
        }
    }

    // ---- epilogue: normalize, split, write to g_ao2 ----
    const int b = bh >> 4, h = bh & 15;
    const int q = ln >> 2, t4 = ln & 3;
    const float inv0 = 1.f / l0, inv1 = 1.f / l1;
    const size_t n0 = (size_t)qt * QROWS + w * 16 + q;
    const size_t mg0 = (size_t)b * SEQ + n0;
    const size_t mg1 = mg0 + 8;
#pragma unroll
    for (int jj = 0; jj < 8; jj++) {
        const int col = h * 64 + jj * 8 + t4 * 2;
        uint32_t hi, lo;
        packsplit2(acco[jj][0] * inv0, acco[jj][1] * inv0, hi, lo);
        *(uint32_t*)(g_ao2 + mg0 * KSPLIT + col)        = hi;
        *(uint32_t*)(g_ao2 + mg0 * KSPLIT + 1024 + col) = lo;
        packsplit2(acco[jj][2] * inv1, acco[jj][3] * inv1, hi, lo);
        *(uint32_t*)(g_ao2 + mg1 * KSPLIT + col)        = hi;
        *(uint32_t*)(g_ao2 + mg1 * KSPLIT + 1024 + col) = lo;
    }
}

// ---------------- launch --------------------------------------------------
extern "C" void kernel_launch(void* const* d_in, const int* in_sizes, int n_in,
                              void* d_out, int out_size)
{
    const float* x = (const float*)d_in[0];
    const float* W [4] = {(const float*)d_in[1],  (const float*)d_in[5],
                          (const float*)d_in[9],  (const float*)d_in[13]};
    const float* B [4] = {(const float*)d_in[2],  (const float*)d_in[6],
                          (const float*)d_in[10], (const float*)d_in[14]};
    const float* dW[4] = {(const float*)d_in[3],  (const float*)d_in[7],
                          (const float*)d_in[11], (const float*)d_in[15]};
    const float* dB[4] = {(const float*)d_in[4],  (const float*)d_in[8],
                          (const float*)d_in[12], (const float*)d_in[16]};
    float* out = (float*)d_out;

    void *pxs, *pao;
    cudaGetSymbolAddress(&pxs, g_xs);
    cudaGetSymbolAddress(&pao, g_ao2);

    // 1) LoRA merge + split (one launch, 4 layers via grid.z)
    {
        dim3 grid(1024, 1, 4);
        merge_lora2<<<grid, 256>>>(W[0], dW[0], dB[0], W[1], dW[1], dB[1],
                                   W[2], dW[2], dB[2], W[3], dW[3], dB[3]);
    }

    // 2) x -> hi/lo split
    prep_split<<<4096, 256>>>(x);

    // 3) QKV projections (HMMA)
    cudaFuncSetAttribute(gemm_hmma, cudaFuncAttributeMaxDynamicSharedMemorySize, GSMEM);
    {
        dim3 grid(D_MODEL / 128, M_TOTAL / 128, 3);
        gemm_hmma<<<grid, 256, GSMEM>>>((const __nv_bfloat16*)pxs, 0, 0,
                                        B[0], B[1], B[2], nullptr);
    }

    // 4) flash attention (HMMA, FA2 layout) -> g_ao2
    cudaFuncSetAttribute(flash_hmma, cudaFuncAttributeMaxDynamicSharedMemorySize, ATT_SMEM);
    {
        dim3 grid(SEQ / QROWS, BATCH * NHEAD);
        flash_hmma<<<grid, 256, ATT_SMEM>>>();
    }

    // 5) O projection (HMMA) -> d_out
    {
        dim3 grid(D_MODEL / 128, M_TOTAL / 128, 1);
        gemm_hmma<<<grid, 256, GSMEM>>>((const __nv_bfloat16*)pao, 1, 3,
                                        B[3], B[3], B[3], out);
    }
}

// round 6
// speedup vs baseline: 4.4604x; 1.2045x over previous
#include <cuda_runtime.h>
#include <cuda_bf16.h>
#include <cuda_fp16.h>
#include <cstdint>

#define D_MODEL 1024
#define NHEAD   16
#define DHEAD   64
#define SEQ     2048
#define BATCH   2
#define M_TOTAL (BATCH * SEQ)   /* 4096 */
#define RANK    32
#define KSPLIT  2048            /* [hi | lo] concatenated K storage */

// ---------------- device scratch ----------------
__device__ __nv_bfloat16 g_xs [(size_t)M_TOTAL * KSPLIT];
__device__ __nv_bfloat16 g_w2 [(size_t)4 * D_MODEL * KSPLIT];
__device__ __nv_bfloat16 g_ao2[(size_t)M_TOTAL * KSPLIT];
__device__ __half g_qh [(size_t)BATCH * NHEAD * SEQ * 128];  // [bh][n][hi64|lo64] fp16
__device__ __half g_kh [(size_t)BATCH * NHEAD * SEQ * 64];   // [bh][n][64] single fp16
__device__ __half g_vh [(size_t)BATCH * NHEAD * SEQ * 128];  // [bh][n][hi64|lo64] fp16

// ---------------- PTX helpers (baseline PTX only) ----------------
__device__ __forceinline__ uint32_t smem_u32(const void* p) {
    uint32_t a;
    asm("{ .reg .u64 t; cvta.to.shared.u64 t, %1; cvt.u32.u64 %0, t; }" : "=r"(a) : "l"(p));
    return a;
}
__device__ __forceinline__ void cpa16(uint32_t dst, const void* src) {
    asm volatile("cp.async.cg.shared.global [%0], [%1], 16;" :: "r"(dst), "l"(src));
}
#define CP_COMMIT() asm volatile("cp.async.commit_group;" ::: "memory")
#define CP_WAIT(n)  asm volatile("cp.async.wait_group %0;" :: "n"(n) : "memory")

__device__ __forceinline__ void ldsm_x4(uint32_t (&r)[4], uint32_t addr) {
    asm volatile("ldmatrix.sync.aligned.m8n8.x4.shared.b16 {%0,%1,%2,%3}, [%4];"
                 : "=r"(r[0]), "=r"(r[1]), "=r"(r[2]), "=r"(r[3]) : "r"(addr));
}
__device__ __forceinline__ void ldsm_x4t(uint32_t (&r)[4], uint32_t addr) {
    asm volatile("ldmatrix.sync.aligned.m8n8.x4.trans.shared.b16 {%0,%1,%2,%3}, [%4];"
                 : "=r"(r[0]), "=r"(r[1]), "=r"(r[2]), "=r"(r[3]) : "r"(addr));
}
// bf16 mma (projection GEMMs)
__device__ __forceinline__ void mma16816(float (&d)[4], const uint32_t (&a)[4],
                                         uint32_t b0, uint32_t b1) {
    asm volatile("mma.sync.aligned.m16n8k16.row.col.f32.bf16.bf16.f32 "
                 "{%0,%1,%2,%3}, {%4,%5,%6,%7}, {%8,%9}, {%0,%1,%2,%3};"
                 : "+f"(d[0]), "+f"(d[1]), "+f"(d[2]), "+f"(d[3])
                 : "r"(a[0]), "r"(a[1]), "r"(a[2]), "r"(a[3]), "r"(b0), "r"(b1));
}
// fp16 mma (attention)
__device__ __forceinline__ void mma16816h(float (&d)[4], const uint32_t (&a)[4],
                                          uint32_t b0, uint32_t b1) {
    asm volatile("mma.sync.aligned.m16n8k16.row.col.f32.f16.f16.f32 "
                 "{%0,%1,%2,%3}, {%4,%5,%6,%7}, {%8,%9}, {%0,%1,%2,%3};"
                 : "+f"(d[0]), "+f"(d[1]), "+f"(d[2]), "+f"(d[3])
                 : "r"(a[0]), "r"(a[1]), "r"(a[2]), "r"(a[3]), "r"(b0), "r"(b1));
}
__device__ __forceinline__ void split2(float v, __nv_bfloat16& h, __nv_bfloat16& l) {
    h = __float2bfloat16(v);
    l = __float2bfloat16(v - __bfloat162float(h));
}
__device__ __forceinline__ void split2h(float v, __half& h, __half& l) {
    h = __float2half(v);
    l = __float2half(v - __half2float(h));
}
__device__ __forceinline__ void packsplit2(float v0, float v1, uint32_t& hi, uint32_t& lo) {
    __nv_bfloat16 h0, h1, l0, l1;
    split2(v0, h0, l0); split2(v1, h1, l1);
    __nv_bfloat162 th = __halves2bfloat162(h0, h1);
    __nv_bfloat162 tl = __halves2bfloat162(l0, l1);
    hi = reinterpret_cast<uint32_t&>(th);
    lo = reinterpret_cast<uint32_t&>(tl);
}
__device__ __forceinline__ uint32_t packh2(float v0, float v1) {
    __half2 t = __floats2half2_rn(v0, v1);
    return reinterpret_cast<uint32_t&>(t);
}

// ---------------- LoRA merge + bf16 split (all 4 layers, one launch) -------
__global__ void merge_lora2(const float* __restrict__ W0, const float* __restrict__ dW0, const float* __restrict__ dB0,
                            const float* __restrict__ W1, const float* __restrict__ dW1, const float* __restrict__ dB1,
                            const float* __restrict__ W2, const float* __restrict__ dW2, const float* __restrict__ dB2,
                            const float* __restrict__ W3, const float* __restrict__ dW3, const float* __restrict__ dB3)
{
    const int layer = blockIdx.z;
    const float* W  = (layer == 0) ? W0  : (layer == 1) ? W1  : (layer == 2) ? W2  : W3;
    const float* dW = (layer == 0) ? dW0 : (layer == 1) ? dW1 : (layer == 2) ? dW2 : dW3;
    const float* dB = (layer == 0) ? dB0 : (layer == 1) ? dB1 : (layer == 2) ? dB2 : dB3;

    int e  = blockIdx.x * 256 + threadIdx.x;
    int n  = e >> 8;
    int kq = e & 255;
    float4 s = *(const float4*)(W + (size_t)n * D_MODEL + kq * 4);
    const float4* dW4 = (const float4*)dW;
#pragma unroll
    for (int r = 0; r < RANK; r++) {
        float b  = dB[n * RANK + r];
        float4 w = dW4[r * 256 + kq];
        s.x += b * w.x; s.y += b * w.y; s.z += b * w.z; s.w += b * w.w;
    }
    __nv_bfloat16 h0, h1, h2, h3, l0, l1, l2, l3;
    split2(s.x, h0, l0); split2(s.y, h1, l1);
    split2(s.z, h2, l2); split2(s.w, h3, l3);
    size_t rowoff = (size_t)(layer * D_MODEL + n) * KSPLIT;
    __nv_bfloat162* ph = (__nv_bfloat162*)(g_w2 + rowoff + kq * 4);
    __nv_bfloat162* pl = (__nv_bfloat162*)(g_w2 + rowoff + D_MODEL + kq * 4);
    ph[0] = __halves2bfloat162(h0, h1); ph[1] = __halves2bfloat162(h2, h3);
    pl[0] = __halves2bfloat162(l0, l1); pl[1] = __halves2bfloat162(l2, l3);
}

__global__ void prep_split(const float* __restrict__ src)
{
    int e   = blockIdx.x * 256 + threadIdx.x;
    int row = e >> 8;
    int kq  = e & 255;
    float4 s = *(const float4*)(src + (size_t)row * D_MODEL + kq * 4);
    __nv_bfloat16 h0, h1, h2, h3, l0, l1, l2, l3;
    split2(s.x, h0, l0); split2(s.y, h1, l1);
    split2(s.z, h2, l2); split2(s.w, h3, l3);
    size_t rowoff = (size_t)row * KSPLIT;
    __nv_bfloat162* ph = (__nv_bfloat162*)(g_xs + rowoff + kq * 4);
    __nv_bfloat162* pl = (__nv_bfloat162*)(g_xs + rowoff + D_MODEL + kq * 4);
    ph[0] = __halves2bfloat162(h0, h1); ph[1] = __halves2bfloat162(h2, h3);
    pl[0] = __halves2bfloat162(l0, l1); pl[1] = __halves2bfloat162(l2, l3);
}

// ---------------- HMMA GEMM: C[128,128] tile = A @ W^T (+bias) -------------
#define GKC   64
#define GNCH  48
#define GROWB 144
#define GT_BYTES (128 * GROWB)
#define GSTAGE   (2 * GT_BYTES)
#define GSTAGES  3
#define GSMEM    (GSTAGES * GSTAGE)

__global__ void __launch_bounds__(256, 2)
gemm_hmma(const __nv_bfloat16* __restrict__ Abase,
          int mode, int layer_base,
          const float* __restrict__ b0, const float* __restrict__ b1,
          const float* __restrict__ b2, float* __restrict__ outO)
{
    extern __shared__ __align__(128) char smem[];
    const uint32_t sb = smem_u32(smem);
    const int tid = threadIdx.x, ln = tid & 31, w = tid >> 5;
    const int wm = w & 1, wn = w >> 1;
    const int bx = blockIdx.x, by = blockIdx.y, z = blockIdx.z;
    const int layer = layer_base + z;

    const __nv_bfloat16* Arow = Abase + (size_t)(by * 128) * KSPLIT;
    const __nv_bfloat16* Wrow = g_w2 + ((size_t)layer * D_MODEL + bx * 128) * KSPLIT;

    float acc[4][4][4] = {};

#define GLOAD(c) do {                                                          \
        int s_ = (c) % GSTAGES;                                                \
        int kp_ = (c) * GKC;                                                   \
        int xA_ = (kp_ < 1024) ? kp_ : kp_ - 1024;                             \
        int xW_ = (kp_ < 2048) ? kp_ : kp_ - 2048;                             \
        uint32_t bA_ = sb + s_ * GSTAGE;                                       \
        uint32_t bW_ = bA_ + GT_BYTES;                                         \
        _Pragma("unroll")                                                      \
        for (int u_ = 0; u_ < 4; u_++) {                                       \
            int e_ = tid + u_ * 256;                                           \
            int row_ = e_ >> 3, seg_ = (e_ & 7) * 16;                          \
            cpa16(bA_ + row_ * GROWB + seg_,                                   \
                  (const char*)(Arow + (size_t)row_ * KSPLIT + xA_) + seg_);   \
            cpa16(bW_ + row_ * GROWB + seg_,                                   \
                  (const char*)(Wrow + (size_t)row_ * KSPLIT + xW_) + seg_);   \
        }                                                                      \
        CP_COMMIT();                                                           \
    } while (0)

    GLOAD(0);
    GLOAD(1);
    for (int c = 0; c < GNCH; c++) {
        if (c + 2 < GNCH) { CP_WAIT(1); } else { CP_WAIT(0); }
        __syncthreads();
        if (c + 2 < GNCH) GLOAD(c + 2);

        const uint32_t bA = sb + (c % GSTAGES) * GSTAGE;
        const uint32_t bW = bA + GT_BYTES;
#pragma unroll
        for (int ks = 0; ks < 4; ks++) {
            const int k0 = ks * 16;
            uint32_t afr[4][4];
#pragma unroll
            for (int i = 0; i < 4; i++) {
                int row = wm * 64 + i * 16 + (ln & 15);
                ldsm_x4(afr[i], bA + row * GROWB + (k0 + ((ln >> 4) << 3)) * 2);
            }
            uint32_t bfr[2][4];
#pragma unroll
            for (int j = 0; j < 2; j++) {
                int n = wn * 32 + j * 16 + (ln & 7) + ((ln & 16) ? 8 : 0);
                ldsm_x4(bfr[j], bW + n * GROWB + (k0 + ((ln & 8) ? 8 : 0)) * 2);
            }
#pragma unroll
            for (int i = 0; i < 4; i++)
#pragma unroll
                for (int jj = 0; jj < 4; jj++)
                    mma16816(acc[i][jj], afr[i], bfr[jj >> 1][(jj & 1) * 2],
                             bfr[jj >> 1][(jj & 1) * 2 + 1]);
        }
    }

    const float* bias = (z == 0) ? b0 : (z == 1) ? b1 : b2;
    const float qscale = (mode == 0 && z == 0) ? 0.125f : 1.0f;
#pragma unroll
    for (int i = 0; i < 4; i++) {
#pragma unroll
        for (int dl = 0; dl < 2; dl++) {
            const int m = by * 128 + wm * 64 + i * 16 + (ln >> 2) + dl * 8;
#pragma unroll
            for (int jj = 0; jj < 4; jj++) {
                const int cgl = bx * 128 + wn * 32 + jj * 8 + (ln & 3) * 2;
                float v0 = (acc[i][jj][dl * 2 + 0] + bias[cgl])     * qscale;
                float v1 = (acc[i][jj][dl * 2 + 1] + bias[cgl + 1]) * qscale;
                if (mode == 0) {
                    const int h = cgl >> 6, d = cgl & 63;
                    const int b = m >> 11, n = m & 2047;
                    const size_t rowb = (size_t)(b * NHEAD + h) * SEQ + n;
                    if (z == 1) {
                        // K: single fp16
                        __half2 t = __floats2half2_rn(v0, v1);
                        *(__half2*)(g_kh + rowb * 64 + d) = t;
                    } else {
                        // Q (scaled) / V: fp16 hi/lo split
                        __half* base = ((z == 0) ? g_qh : g_vh) + rowb * 128 + d;
                        __half h0, h1, l0v, l1v;
                        split2h(v0, h0, l0v); split2h(v1, h1, l1v);
                        *(__half2*)(base)      = __halves2half2(h0, h1);
                        *(__half2*)(base + 64) = __halves2half2(l0v, l1v);
                    }
                } else {
                    float2 o; o.x = v0; o.y = v1;
                    *(float2*)(outO + (size_t)m * D_MODEL + cgl) = o;
                }
            }
        }
    }
}

// ---------------- Flash attention: FA2, fp16 2-term split ------------------
// CTA: 128 q-rows, 8 warps x 16 rows; warp owns full 64 k-cols.
// S = (Qhi+Qlo) @ K^T  (K single fp16);  O += Phi @ (Vhi+Vlo)  (P single fp16)
#define QROWB 272                         /* 128 fp16 + 8 pad */
#define KROWB 144                         /* 64 fp16 + 8 pad */
#define VROWB 272
#define KTILEB (64 * KROWB)               /* 9216 */
#define VTILEB (64 * VROWB)               /* 17408 */
#define QROWS 128
#define SM_Q   0
#define SM_K0  (QROWS * QROWB)            /* 34816 */
#define SM_V0  (SM_K0 + 2 * KTILEB)       /* 53248 */
#define ATT_SMEM (SM_V0 + 2 * VTILEB)     /* 88064 */
#define NT (SEQ / 64)

__global__ void __launch_bounds__(256, 2)
flash_hmma()
{
    extern __shared__ __align__(128) char smem[];
    const uint32_t sb = smem_u32(smem);
    const int tid = threadIdx.x, ln = tid & 31, w = tid >> 5;
    const int qt = blockIdx.x, bh = blockIdx.y;

    const __half* qg = g_qh + ((size_t)bh * SEQ + qt * QROWS) * 128;
    const __half* kg = g_kh + (size_t)bh * SEQ * 64;
    const __half* vg = g_vh + (size_t)bh * SEQ * 128;

    // Q tile: 128 rows x 256B
#pragma unroll
    for (int u = 0; u < 8; u++) {
        int e = tid + u * 256;
        int row = e >> 4, seg = (e & 15) * 16;
        cpa16(sb + SM_Q + row * QROWB + seg, (const char*)(qg + (size_t)row * 128) + seg);
    }
    CP_COMMIT();

#define ATT_LOAD(t) do {                                                       \
        int buf_ = (t) & 1;                                                    \
        const __half* kb_ = kg + (size_t)(t) * 64 * 64;                        \
        const __half* vb_ = vg + (size_t)(t) * 64 * 128;                       \
        uint32_t kd_ = sb + SM_K0 + buf_ * KTILEB;                             \
        uint32_t vd_ = sb + SM_V0 + buf_ * VTILEB;                             \
        _Pragma("unroll")                                                      \
        for (int u_ = 0; u_ < 2; u_++) {                                       \
            int e_ = tid + u_ * 256;                                           \
            int row_ = e_ >> 3, seg_ = (e_ & 7) * 16;                          \
            cpa16(kd_ + row_ * KROWB + seg_,                                   \
                  (const char*)(kb_ + (size_t)row_ * 64) + seg_);              \
        }                                                                      \
        _Pragma("unroll")                                                      \
        for (int u_ = 0; u_ < 4; u_++) {                                       \
            int e_ = tid + u_ * 256;                                           \
            int row_ = e_ >> 4, seg_ = (e_ & 15) * 16;                         \
            cpa16(vd_ + row_ * VROWB + seg_,                                   \
                  (const char*)(vb_ + (size_t)row_ * 128) + seg_);             \
        }                                                                      \
        CP_COMMIT();                                                           \
    } while (0)

    ATT_LOAD(0);
    CP_WAIT(0);
    __syncthreads();

    // resident Q-hi fragments; Q-lo streamed per k-step
    const uint32_t qaddr = sb + SM_Q + (w * 16 + (ln & 15)) * QROWB + (((ln >> 4) << 3)) * 2;
    uint32_t qhi[4][4];
#pragma unroll
    for (int s = 0; s < 4; s++)
        ldsm_x4(qhi[s], qaddr + (s * 16) * 2);

    const int krow8  = (ln & 7) + ((ln & 16) ? 8 : 0);
    const int kcol8  = (ln & 8) ? 8 : 0;
    const int vrow16 = ln & 15;
    const int vcol8  = (ln & 16) ? 8 : 0;

    float m0 = -1e30f, m1 = -1e30f, l0 = 0.f, l1 = 0.f;
    float acco[8][4] = {};

    for (int kt = 0; kt < NT; kt++) {
        if (kt > 0) { CP_WAIT(0); __syncthreads(); }
        if (kt + 1 < NT) ATT_LOAD(kt + 1);
        const uint32_t bK = sb + SM_K0 + (kt & 1) * KTILEB;
        const uint32_t bV = sb + SM_V0 + (kt & 1) * VTILEB;

        // ---- S = (Qhi + Qlo) K^T: 2 terms, K fragments shared ----
        float accs[8][4] = {};
#pragma unroll
        for (int ks = 0; ks < 4; ks++) {
            uint32_t ql[4];
            ldsm_x4(ql, qaddr + (64 + ks * 16) * 2);
#pragma unroll
            for (int nbp = 0; nbp < 4; nbp++) {
                uint32_t kb[4];
                ldsm_x4(kb, bK + (nbp * 16 + krow8) * KROWB + (ks * 16 + kcol8) * 2);
                mma16816h(accs[2 * nbp],     qhi[ks], kb[0], kb[1]);
                mma16816h(accs[2 * nbp + 1], qhi[ks], kb[2], kb[3]);
                mma16816h(accs[2 * nbp],     ql,      kb[0], kb[1]);
                mma16816h(accs[2 * nbp + 1], ql,      kb[2], kb[3]);
            }
        }

        // ---- warp-local online softmax ----
        float mx0 = -1e30f, mx1 = -1e30f;
#pragma unroll
        for (int jj = 0; jj < 8; jj++) {
            mx0 = fmaxf(mx0, fmaxf(accs[jj][0], accs[jj][1]));
            mx1 = fmaxf(mx1, fmaxf(accs[jj][2], accs[jj][3]));
        }
        mx0 = fmaxf(mx0, __shfl_xor_sync(0xffffffffu, mx0, 1));
        mx0 = fmaxf(mx0, __shfl_xor_sync(0xffffffffu, mx0, 2));
        mx1 = fmaxf(mx1, __shfl_xor_sync(0xffffffffu, mx1, 1));
        mx1 = fmaxf(mx1, __shfl_xor_sync(0xffffffffu, mx1, 2));
        const float mn0 = fmaxf(m0, mx0), mn1 = fmaxf(m1, mx1);
        const float a0 = __expf(m0 - mn0), a1 = __expf(m1 - mn1);
        m0 = mn0; m1 = mn1;

        float s0 = 0.f, s1 = 0.f;
#pragma unroll
        for (int jj = 0; jj < 8; jj++) {
            accs[jj][0] = __expf(accs[jj][0] - mn0);
            accs[jj][1] = __expf(accs[jj][1] - mn0);
            accs[jj][2] = __expf(accs[jj][2] - mn1);
            accs[jj][3] = __expf(accs[jj][3] - mn1);
            s0 += accs[jj][0] + accs[jj][1];
            s1 += accs[jj][2] + accs[jj][3];
        }
        s0 += __shfl_xor_sync(0xffffffffu, s0, 1);
        s0 += __shfl_xor_sync(0xffffffffu, s0, 2);
        s1 += __shfl_xor_sync(0xffffffffu, s1, 1);
        s1 += __shfl_xor_sync(0xffffffffu, s1, 2);
        l0 = l0 * a0 + s0;
        l1 = l1 * a1 + s1;
#pragma unroll
        for (int jj = 0; jj < 8; jj++) {
            acco[jj][0] *= a0; acco[jj][1] *= a0;
            acco[jj][2] *= a1; acco[jj][3] *= a1;
        }

        // ---- O += Phi @ (Vhi + Vlo): P single fp16, repacked in regs ----
#pragma unroll
        for (int ks = 0; ks < 4; ks++) {
            uint32_t phi[4];
            phi[0] = packh2(accs[2 * ks][0],     accs[2 * ks][1]);
            phi[1] = packh2(accs[2 * ks][2],     accs[2 * ks][3]);
            phi[2] = packh2(accs[2 * ks + 1][0], accs[2 * ks + 1][1]);
            phi[3] = packh2(accs[2 * ks + 1][2], accs[2 * ks + 1][3]);
#pragma unroll
            for (int nbp = 0; nbp < 4; nbp++) {
                uint32_t vb[4];
                ldsm_x4t(vb, bV + (ks * 16 + vrow16) * VROWB + (nbp * 16 + vcol8) * 2);
                mma16816h(acco[2 * nbp],     phi, vb[0], vb[1]);
                mma16816h(acco[2 * nbp + 1], phi, vb[2], vb[3]);
            }
#pragma unroll
            for (int nbp = 0; nbp < 4; nbp++) {
                uint32_t vb[4];
                ldsm_x4t(vb, bV + (ks * 16 + vrow16) * VROWB + (64 + nbp * 16 + vcol8) * 2);
                mma16816h(acco[2 * nbp],     phi, vb[0], vb[1]);
                mma16816h(acco[2 * nbp + 1], phi, vb[2], vb[3]);
            }
        }
    }

    // ---- epilogue: normalize, bf16 split, write to g_ao2 ----
    const int b = bh >> 4, h = bh & 15;
    const int q = ln >> 2, t4 = ln & 3;
    const float inv0 = 1.f / l0, inv1 = 1.f / l1;
    const size_t n0 = (size_t)qt * QROWS + w * 16 + q;
    const size_t mg0 = (size_t)b * SEQ + n0;
    const size_t mg1 = mg0 + 8;
#pragma unroll
    for (int jj = 0; jj < 8; jj++) {
        const int col = h * 64 + jj * 8 + t4 * 2;
        uint32_t hi, lo;
        packsplit2(acco[jj][0] * inv0, acco[jj][1] * inv0, hi, lo);
        *(uint32_t*)(g_ao2 + mg0 * KSPLIT + col)        = hi;
        *(uint32_t*)(g_ao2 + mg0 * KSPLIT + 1024 + col) = lo;
        packsplit2(acco[jj][2] * inv1, acco[jj][3] * inv1, hi, lo);
        *(uint32_t*)(g_ao2 + mg1 * KSPLIT + col)        = hi;
        *(uint32_t*)(g_ao2 + mg1 * KSPLIT + 1024 + col) = lo;
    }
}

// ---------------- launch --------------------------------------------------
extern "C" void kernel_launch(void* const* d_in, const int* in_sizes, int n_in,
                              void* d_out, int out_size)
{
    const float* x = (const float*)d_in[0];
    const float* W [4] = {(const float*)d_in[1],  (const float*)d_in[5],
                          (const float*)d_in[9],  (const float*)d_in[13]};
    const float* B [4] = {(const float*)d_in[2],  (const float*)d_in[6],
                          (const float*)d_in[10], (const float*)d_in[14]};
    const float* dW[4] = {(const float*)d_in[3],  (const float*)d_in[7],
                          (const float*)d_in[11], (const float*)d_in[15]};
    const float* dB[4] = {(const float*)d_in[4],  (const float*)d_in[8],
                          (const float*)d_in[12], (const float*)d_in[16]};
    float* out = (float*)d_out;

    void *pxs, *pao;
    cudaGetSymbolAddress(&pxs, g_xs);
    cudaGetSymbolAddress(&pao, g_ao2);

    // 1) LoRA merge + split (one launch, 4 layers via grid.z)
    {
        dim3 grid(1024, 1, 4);
        merge_lora2<<<grid, 256>>>(W[0], dW[0], dB[0], W[1], dW[1], dB[1],
                                   W[2], dW[2], dB[2], W[3], dW[3], dB[3]);
    }

    // 2) x -> hi/lo split
    prep_split<<<4096, 256>>>(x);

    // 3) QKV projections (HMMA bf16 3-term)
    cudaFuncSetAttribute(gemm_hmma, cudaFuncAttributeMaxDynamicSharedMemorySize, GSMEM);
    {
        dim3 grid(D_MODEL / 128, M_TOTAL / 128, 3);
        gemm_hmma<<<grid, 256, GSMEM>>>((const __nv_bfloat16*)pxs, 0, 0,
                                        B[0], B[1], B[2], nullptr);
    }

    // 4) flash attention (fp16 2-term) -> g_ao2
    cudaFuncSetAttribute(flash_hmma, cudaFuncAttributeMaxDynamicSharedMemorySize, ATT_SMEM);
    {
        dim3 grid(SEQ / QROWS, BATCH * NHEAD);
        flash_hmma<<<grid, 256, ATT_SMEM>>>();
    }

    // 5) O projection (HMMA bf16 3-term) -> d_out
    {
        dim3 grid(D_MODEL / 128, M_TOTAL / 128, 1);
        gemm_hmma<<<grid, 256, GSMEM>>>((const __nv_bfloat16*)pao, 1, 3,
                                        B[3], B[3], B[3], out);
    }
}

// round 7
// speedup vs baseline: 6.1391x; 1.3764x over previous
#include <cuda_runtime.h>
#include <cuda_bf16.h>
#include <cuda_fp16.h>
#include <cstdint>

#define D_MODEL 1024
#define NHEAD   16
#define DHEAD   64
#define SEQ     2048
#define BATCH   2
#define M_TOTAL (BATCH * SEQ)   /* 4096 */
#define RANK    32
#define ASPLIT  2048            /* activation storage: [hi | lo] fp16 */

// ---------------- device scratch ----------------
__device__ __half g_xs [(size_t)M_TOTAL * ASPLIT];          // x split fp16
__device__ __half g_w2 [(size_t)4 * D_MODEL * D_MODEL];     // merged W single fp16
__device__ __half g_ao2[(size_t)M_TOTAL * ASPLIT];          // attn out split fp16
__device__ __half g_qh [(size_t)BATCH * NHEAD * SEQ * 128]; // [bh][n][hi64|lo64]
__device__ __half g_kh [(size_t)BATCH * NHEAD * SEQ * 64];  // single fp16
__device__ __half g_vh [(size_t)BATCH * NHEAD * SEQ * 64];  // single fp16

// ---------------- PTX helpers (baseline PTX only) ----------------
__device__ __forceinline__ uint32_t smem_u32(const void* p) {
    uint32_t a;
    asm("{ .reg .u64 t; cvta.to.shared.u64 t, %1; cvt.u32.u64 %0, t; }" : "=r"(a) : "l"(p));
    return a;
}
__device__ __forceinline__ void cpa16(uint32_t dst, const void* src) {
    asm volatile("cp.async.cg.shared.global [%0], [%1], 16;" :: "r"(dst), "l"(src));
}
#define CP_COMMIT() asm volatile("cp.async.commit_group;" ::: "memory")
#define CP_WAIT(n)  asm volatile("cp.async.wait_group %0;" :: "n"(n) : "memory")

__device__ __forceinline__ void ldsm_x4(uint32_t (&r)[4], uint32_t addr) {
    asm volatile("ldmatrix.sync.aligned.m8n8.x4.shared.b16 {%0,%1,%2,%3}, [%4];"
                 : "=r"(r[0]), "=r"(r[1]), "=r"(r[2]), "=r"(r[3]) : "r"(addr));
}
__device__ __forceinline__ void ldsm_x4t(uint32_t (&r)[4], uint32_t addr) {
    asm volatile("ldmatrix.sync.aligned.m8n8.x4.trans.shared.b16 {%0,%1,%2,%3}, [%4];"
                 : "=r"(r[0]), "=r"(r[1]), "=r"(r[2]), "=r"(r[3]) : "r"(addr));
}
__device__ __forceinline__ void mma16816h(float (&d)[4], const uint32_t (&a)[4],
                                          uint32_t b0, uint32_t b1) {
    asm volatile("mma.sync.aligned.m16n8k16.row.col.f32.f16.f16.f32 "
                 "{%0,%1,%2,%3}, {%4,%5,%6,%7}, {%8,%9}, {%0,%1,%2,%3};"
                 : "+f"(d[0]), "+f"(d[1]), "+f"(d[2]), "+f"(d[3])
                 : "r"(a[0]), "r"(a[1]), "r"(a[2]), "r"(a[3]), "r"(b0), "r"(b1));
}
__device__ __forceinline__ void split2h(float v, __half& h, __half& l) {
    h = __float2half(v);
    l = __float2half(v - __half2float(h));
}
__device__ __forceinline__ void packsplit2h(float v0, float v1, uint32_t& hi, uint32_t& lo) {
    __half h0, h1, l0, l1;
    split2h(v0, h0, l0); split2h(v1, h1, l1);
    __half2 th = __halves2half2(h0, h1);
    __half2 tl = __halves2half2(l0, l1);
    hi = reinterpret_cast<uint32_t&>(th);
    lo = reinterpret_cast<uint32_t&>(tl);
}
__device__ __forceinline__ uint32_t packh2(float v0, float v1) {
    __half2 t = __floats2half2_rn(v0, v1);
    return reinterpret_cast<uint32_t&>(t);
}

// ---------------- LoRA merge -> single fp16 (all 4 layers, one launch) -----
__global__ void merge_lora2(const float* __restrict__ W0, const float* __restrict__ dW0, const float* __restrict__ dB0,
                            const float* __restrict__ W1, const float* __restrict__ dW1, const float* __restrict__ dB1,
                            const float* __restrict__ W2, const float* __restrict__ dW2, const float* __restrict__ dB2,
                            const float* __restrict__ W3, const float* __restrict__ dW3, const float* __restrict__ dB3)
{
    const int layer = blockIdx.z;
    const float* W  = (layer == 0) ? W0  : (layer == 1) ? W1  : (layer == 2) ? W2  : W3;
    const float* dW = (layer == 0) ? dW0 : (layer == 1) ? dW1 : (layer == 2) ? dW2 : dW3;
    const float* dB = (layer == 0) ? dB0 : (layer == 1) ? dB1 : (layer == 2) ? dB2 : dB3;

    int e  = blockIdx.x * 256 + threadIdx.x;
    int n  = e >> 8;
    int kq = e & 255;
    float4 s = *(const float4*)(W + (size_t)n * D_MODEL + kq * 4);
    const float4* dW4 = (const float4*)dW;
#pragma unroll
    for (int r = 0; r < RANK; r++) {
        float b  = dB[n * RANK + r];
        float4 w = dW4[r * 256 + kq];
        s.x += b * w.x; s.y += b * w.y; s.z += b * w.z; s.w += b * w.w;
    }
    __half2* p = (__half2*)(g_w2 + (size_t)(layer * D_MODEL + n) * D_MODEL + kq * 4);
    p[0] = __floats2half2_rn(s.x, s.y);
    p[1] = __floats2half2_rn(s.z, s.w);
}

// ---------------- x -> fp16 hi/lo split ----------------
__global__ void prep_split(const float* __restrict__ src)
{
    int e   = blockIdx.x * 256 + threadIdx.x;
    int row = e >> 8;
    int kq  = e & 255;
    float4 s = *(const float4*)(src + (size_t)row * D_MODEL + kq * 4);
    __half h0, h1, h2, h3, l0, l1, l2, l3;
    split2h(s.x, h0, l0); split2h(s.y, h1, l1);
    split2h(s.z, h2, l2); split2h(s.w, h3, l3);
    size_t rowoff = (size_t)row * ASPLIT;
    __half2* ph = (__half2*)(g_xs + rowoff + kq * 4);
    __half2* pl = (__half2*)(g_xs + rowoff + D_MODEL + kq * 4);
    ph[0] = __halves2half2(h0, h1); ph[1] = __halves2half2(h2, h3);
    pl[0] = __halves2half2(l0, l1); pl[1] = __halves2half2(l2, l3);
}

// ---------------- HMMA GEMM: C[128,128] = A @ W^T (+bias), fp16 2-term -----
// virtual K=2048: A = [hi|lo] storage indexed directly; W indexed mod 1024
#define GKC   64
#define GNCH  32
#define GROWB 144
#define GT_BYTES (128 * GROWB)
#define GSTAGE   (2 * GT_BYTES)
#define GSTAGES  3
#define GSMEM    (GSTAGES * GSTAGE)

__global__ void __launch_bounds__(256, 2)
gemm_hmma(const __half* __restrict__ Abase,  // [*, ASPLIT]
          int mode, int layer_base,
          const float* __restrict__ b0, const float* __restrict__ b1,
          const float* __restrict__ b2, float* __restrict__ outO)
{
    extern __shared__ __align__(128) char smem[];
    const uint32_t sb = smem_u32(smem);
    const int tid = threadIdx.x, ln = tid & 31, w = tid >> 5;
    const int wm = w & 1, wn = w >> 1;
    const int bx = blockIdx.x, by = blockIdx.y, z = blockIdx.z;
    const int layer = layer_base + z;

    const __half* Arow = Abase + (size_t)(by * 128) * ASPLIT;
    const __half* Wrow = g_w2 + ((size_t)layer * D_MODEL + bx * 128) * D_MODEL;

    float acc[4][4][4] = {};

#define GLOAD(c) do {                                                          \
        int s_ = (c) % GSTAGES;                                                \
        int xA_ = (c) * GKC;                                                   \
        int xW_ = ((c) * GKC) & 1023;                                          \
        uint32_t bA_ = sb + s_ * GSTAGE;                                       \
        uint32_t bW_ = bA_ + GT_BYTES;                                         \
        _Pragma("unroll")                                                      \
        for (int u_ = 0; u_ < 4; u_++) {                                       \
            int e_ = tid + u_ * 256;                                           \
            int row_ = e_ >> 3, seg_ = (e_ & 7) * 16;                          \
            cpa16(bA_ + row_ * GROWB + seg_,                                   \
                  (const char*)(Arow + (size_t)row_ * ASPLIT + xA_) + seg_);   \
            cpa16(bW_ + row_ * GROWB + seg_,                                   \
                  (const char*)(Wrow + (size_t)row_ * D_MODEL + xW_) + seg_);  \
        }                                                                      \
        CP_COMMIT();                                                           \
    } while (0)

    GLOAD(0);
    GLOAD(1);
    for (int c = 0; c < GNCH; c++) {
        if (c + 2 < GNCH) { CP_WAIT(1); } else { CP_WAIT(0); }
        __syncthreads();
        if (c + 2 < GNCH) GLOAD(c + 2);

        const uint32_t bA = sb + (c % GSTAGES) * GSTAGE;
        const uint32_t bW = bA + GT_BYTES;
#pragma unroll
        for (int ks = 0; ks < 4; ks++) {
            const int k0 = ks * 16;
            uint32_t afr[4][4];
#pragma unroll
            for (int i = 0; i < 4; i++) {
                int row = wm * 64 + i * 16 + (ln & 15);
                ldsm_x4(afr[i], bA + row * GROWB + (k0 + ((ln >> 4) << 3)) * 2);
            }
            uint32_t bfr[2][4];
#pragma unroll
            for (int j = 0; j < 2; j++) {
                int n = wn * 32 + j * 16 + (ln & 7) + ((ln & 16) ? 8 : 0);
                ldsm_x4(bfr[j], bW + n * GROWB + (k0 + ((ln & 8) ? 8 : 0)) * 2);
            }
#pragma unroll
            for (int i = 0; i < 4; i++)
#pragma unroll
                for (int jj = 0; jj < 4; jj++)
                    mma16816h(acc[i][jj], afr[i], bfr[jj >> 1][(jj & 1) * 2],
                              bfr[jj >> 1][(jj & 1) * 2 + 1]);
        }
    }

    const float* bias = (z == 0) ? b0 : (z == 1) ? b1 : b2;
    const float qscale = (mode == 0 && z == 0) ? 0.125f : 1.0f;
#pragma unroll
    for (int i = 0; i < 4; i++) {
#pragma unroll
        for (int dl = 0; dl < 2; dl++) {
            const int m = by * 128 + wm * 64 + i * 16 + (ln >> 2) + dl * 8;
#pragma unroll
            for (int jj = 0; jj < 4; jj++) {
                const int cgl = bx * 128 + wn * 32 + jj * 8 + (ln & 3) * 2;
                float v0 = (acc[i][jj][dl * 2 + 0] + bias[cgl])     * qscale;
                float v1 = (acc[i][jj][dl * 2 + 1] + bias[cgl + 1]) * qscale;
                if (mode == 0) {
                    const int h = cgl >> 6, d = cgl & 63;
                    const int b = m >> 11, n = m & 2047;
                    const size_t rowb = (size_t)(b * NHEAD + h) * SEQ + n;
                    if (z == 0) {
                        // Q (scaled): fp16 hi/lo split
                        __half h0, h1, l0v, l1v;
                        split2h(v0, h0, l0v); split2h(v1, h1, l1v);
                        __half* base = g_qh + rowb * 128 + d;
                        *(__half2*)(base)      = __halves2half2(h0, h1);
                        *(__half2*)(base + 64) = __halves2half2(l0v, l1v);
                    } else {
                        // K, V: single fp16
                        __half* base = ((z == 1) ? g_kh : g_vh) + rowb * 64 + d;
                        *(__half2*)base = __floats2half2_rn(v0, v1);
                    }
                } else {
                    float2 o; o.x = v0; o.y = v1;
                    *(float2*)(outO + (size_t)m * D_MODEL + cgl) = o;
                }
            }
        }
    }
}

// ---------------- Flash attention: FA2, fp16, V single ---------------------
// S = (Qhi+Qlo) @ K^T  (K single);  O += P @ V  (P single, V single)
#define QROWB 272                         /* 128 fp16 + 8 pad */
#define KROWB 144                         /* 64 fp16 + 8 pad */
#define KTILEB (64 * KROWB)               /* 9216 */
#define QROWS 128
#define SM_Q   0
#define SM_K0  (QROWS * QROWB)            /* 34816 */
#define SM_V0  (SM_K0 + 2 * KTILEB)       /* 53248 */
#define ATT_SMEM (SM_V0 + 2 * KTILEB)     /* 71680 */
#define NT (SEQ / 64)

__global__ void __launch_bounds__(256, 2)
flash_hmma()
{
    extern __shared__ __align__(128) char smem[];
    const uint32_t sb = smem_u32(smem);
    const int tid = threadIdx.x, ln = tid & 31, w = tid >> 5;
    const int qt = blockIdx.x, bh = blockIdx.y;

    const __half* qg = g_qh + ((size_t)bh * SEQ + qt * QROWS) * 128;
    const __half* kg = g_kh + (size_t)bh * SEQ * 64;
    const __half* vg = g_vh + (size_t)bh * SEQ * 64;

    // Q tile: 128 rows x 256B
#pragma unroll
    for (int u = 0; u < 8; u++) {
        int e = tid + u * 256;
        int row = e >> 4, seg = (e & 15) * 16;
        cpa16(sb + SM_Q + row * QROWB + seg, (const char*)(qg + (size_t)row * 128) + seg);
    }
    CP_COMMIT();

#define ATT_LOAD(t) do {                                                       \
        int buf_ = (t) & 1;                                                    \
        const __half* kb_ = kg + (size_t)(t) * 64 * 64;                        \
        const __half* vb_ = vg + (size_t)(t) * 64 * 64;                        \
        uint32_t kd_ = sb + SM_K0 + buf_ * KTILEB;                             \
        uint32_t vd_ = sb + SM_V0 + buf_ * KTILEB;                             \
        _Pragma("unroll")                                                      \
        for (int u_ = 0; u_ < 2; u_++) {                                       \
            int e_ = tid + u_ * 256;                                           \
            int row_ = e_ >> 3, seg_ = (e_ & 7) * 16;                          \
            cpa16(kd_ + row_ * KROWB + seg_,                                   \
                  (const char*)(kb_ + (size_t)row_ * 64) + seg_);              \
            cpa16(vd_ + row_ * KROWB + seg_,                                   \
                  (const char*)(vb_ + (size_t)row_ * 64) + seg_);              \
        }                                                                      \
        CP_COMMIT();                                                           \
    } while (0)

    ATT_LOAD(0);
    CP_WAIT(0);
    __syncthreads();

    // resident Q-hi fragments; Q-lo streamed per k-step
    const uint32_t qaddr = sb + SM_Q + (w * 16 + (ln & 15)) * QROWB + (((ln >> 4) << 3)) * 2;
    uint32_t qhi[4][4];
#pragma unroll
    for (int s = 0; s < 4; s++)
        ldsm_x4(qhi[s], qaddr + (s * 16) * 2);

    const int krow8  = (ln & 7) + ((ln & 16) ? 8 : 0);
    const int kcol8  = (ln & 8) ? 8 : 0;
    const int vrow16 = ln & 15;
    const int vcol8  = (ln & 16) ? 8 : 0;

    float m0 = -1e30f, m1 = -1e30f, l0 = 0.f, l1 = 0.f;
    float acco[8][4] = {};

    for (int kt = 0; kt < NT; kt++) {
        if (kt > 0) { CP_WAIT(0); __syncthreads(); }
        if (kt + 1 < NT) ATT_LOAD(kt + 1);
        const uint32_t bK = sb + SM_K0 + (kt & 1) * KTILEB;
        const uint32_t bV = sb + SM_V0 + (kt & 1) * KTILEB;

        // ---- S = (Qhi + Qlo) K^T: K fragments shared between terms ----
        float accs[8][4] = {};
#pragma unroll
        for (int ks = 0; ks < 4; ks++) {
            uint32_t ql[4];
            ldsm_x4(ql, qaddr + (64 + ks * 16) * 2);
#pragma unroll
            for (int nbp = 0; nbp < 4; nbp++) {
                uint32_t kb[4];
                ldsm_x4(kb, bK + (nbp * 16 + krow8) * KROWB + (ks * 16 + kcol8) * 2);
                mma16816h(accs[2 * nbp],     qhi[ks], kb[0], kb[1]);
                mma16816h(accs[2 * nbp + 1], qhi[ks], kb[2], kb[3]);
                mma16816h(accs[2 * nbp],     ql,      kb[0], kb[1]);
                mma16816h(accs[2 * nbp + 1], ql,      kb[2], kb[3]);
            }
        }

        // ---- warp-local online softmax ----
        float mx0 = -1e30f, mx1 = -1e30f;
#pragma unroll
        for (int jj = 0; jj < 8; jj++) {
            mx0 = fmaxf(mx0, fmaxf(accs[jj][0], accs[jj][1]));
            mx1 = fmaxf(mx1, fmaxf(accs[jj][2], accs[jj][3]));
        }
        mx0 = fmaxf(mx0, __shfl_xor_sync(0xffffffffu, mx0, 1));
        mx0 = fmaxf(mx0, __shfl_xor_sync(0xffffffffu, mx0, 2));
        mx1 = fmaxf(mx1, __shfl_xor_sync(0xffffffffu, mx1, 1));
        mx1 = fmaxf(mx1, __shfl_xor_sync(0xffffffffu, mx1, 2));
        const float mn0 = fmaxf(m0, mx0), mn1 = fmaxf(m1, mx1);
        const float a0 = __expf(m0 - mn0), a1 = __expf(m1 - mn1);
        m0 = mn0; m1 = mn1;

        float s0 = 0.f, s1 = 0.f;
#pragma unroll
        for (int jj = 0; jj < 8; jj++) {
            accs[jj][0] = __expf(accs[jj][0] - mn0);
            accs[jj][1] = __expf(accs[jj][1] - mn0);
            accs[jj][2] = __expf(accs[jj][2] - mn1);
            accs[jj][3] = __expf(accs[jj][3] - mn1);
            s0 += accs[jj][0] + accs[jj][1];
            s1 += accs[jj][2] + accs[jj][3];
        }
        s0 += __shfl_xor_sync(0xffffffffu, s0, 1);
        s0 += __shfl_xor_sync(0xffffffffu, s0, 2);
        s1 += __shfl_xor_sync(0xffffffffu, s1, 1);
        s1 += __shfl_xor_sync(0xffffffffu, s1, 2);
        l0 = l0 * a0 + s0;
        l1 = l1 * a1 + s1;
#pragma unroll
        for (int jj = 0; jj < 8; jj++) {
            acco[jj][0] *= a0; acco[jj][1] *= a0;
            acco[jj][2] *= a1; acco[jj][3] *= a1;
        }

        // ---- O += P @ V: single term (P fp16, V single fp16) ----
#pragma unroll
        for (int ks = 0; ks < 4; ks++) {
            uint32_t phi[4];
            phi[0] = packh2(accs[2 * ks][0],     accs[2 * ks][1]);
            phi[1] = packh2(accs[2 * ks][2],     accs[2 * ks][3]);
            phi[2] = packh2(accs[2 * ks + 1][0], accs[2 * ks + 1][1]);
            phi[3] = packh2(accs[2 * ks + 1][2], accs[2 * ks + 1][3]);
#pragma unroll
            for (int nbp = 0; nbp < 4; nbp++) {
                uint32_t vb[4];
                ldsm_x4t(vb, bV + (ks * 16 + vrow16) * KROWB + (nbp * 16 + vcol8) * 2);
                mma16816h(acco[2 * nbp],     phi, vb[0], vb[1]);
                mma16816h(acco[2 * nbp + 1], phi, vb[2], vb[3]);
            }
        }
    }

    // ---- epilogue: normalize, fp16 split, write to g_ao2 ----
    const int b = bh >> 4, h = bh & 15;
    const int q = ln >> 2, t4 = ln & 3;
    const float inv0 = 1.f / l0, inv1 = 1.f / l1;
    const size_t n0 = (size_t)qt * QROWS + w * 16 + q;
    const size_t mg0 = (size_t)b * SEQ + n0;
    const size_t mg1 = mg0 + 8;
#pragma unroll
    for (int jj = 0; jj < 8; jj++) {
        const int col = h * 64 + jj * 8 + t4 * 2;
        uint32_t hi, lo;
        packsplit2h(acco[jj][0] * inv0, acco[jj][1] * inv0, hi, lo);
        *(uint32_t*)(g_ao2 + mg0 * ASPLIT + col)        = hi;
        *(uint32_t*)(g_ao2 + mg0 * ASPLIT + 1024 + col) = lo;
        packsplit2h(acco[jj][2] * inv1, acco[jj][3] * inv1, hi, lo);
        *(uint32_t*)(g_ao2 + mg1 * ASPLIT + col)        = hi;
        *(uint32_t*)(g_ao2 + mg1 * ASPLIT + 1024 + col) = lo;
    }
}

// ---------------- launch --------------------------------------------------
extern "C" void kernel_launch(void* const* d_in, const int* in_sizes, int n_in,
                              void* d_out, int out_size)
{
    const float* x = (const float*)d_in[0];
    const float* W [4] = {(const float*)d_in[1],  (const float*)d_in[5],
                          (const float*)d_in[9],  (const float*)d_in[13]};
    const float* B [4] = {(const float*)d_in[2],  (const float*)d_in[6],
                          (const float*)d_in[10], (const float*)d_in[14]};
    const float* dW[4] = {(const float*)d_in[3],  (const float*)d_in[7],
                          (const float*)d_in[11], (const float*)d_in[15]};
    const float* dB[4] = {(const float*)d_in[4],  (const float*)d_in[8],
                          (const float*)d_in[12], (const float*)d_in[16]};
    float* out = (float*)d_out;

    void *pxs, *pao;
    cudaGetSymbolAddress(&pxs, g_xs);
    cudaGetSymbolAddress(&pao, g_ao2);

    // 1) LoRA merge -> single fp16 (one launch, 4 layers)
    {
        dim3 grid(1024, 1, 4);
        merge_lora2<<<grid, 256>>>(W[0], dW[0], dB[0], W[1], dW[1], dB[1],
                                   W[2], dW[2], dB[2], W[3], dW[3], dB[3]);
    }

    // 2) x -> fp16 hi/lo split
    prep_split<<<4096, 256>>>(x);

    // 3) QKV projections (fp16 2-term HMMA)
    cudaFuncSetAttribute(gemm_hmma, cudaFuncAttributeMaxDynamicSharedMemorySize, GSMEM);
    {
        dim3 grid(D_MODEL / 128, M_TOTAL / 128, 3);
        gemm_hmma<<<grid, 256, GSMEM>>>((const __half*)pxs, 0, 0,
                                        B[0], B[1], B[2], nullptr);
    }

    // 4) flash attention (fp16, V single) -> g_ao2
    cudaFuncSetAttribute(flash_hmma, cudaFuncAttributeMaxDynamicSharedMemorySize, ATT_SMEM);
    {
        dim3 grid(SEQ / QROWS, BATCH * NHEAD);
        flash_hmma<<<grid, 256, ATT_SMEM>>>();
    }

    // 5) O projection (fp16 2-term HMMA) -> d_out
    {
        dim3 grid(D_MODEL / 128, M_TOTAL / 128, 1);
        gemm_hmma<<<grid, 256, GSMEM>>>((const __half*)pao, 1, 3,
                                        B[3], B[3], B[3], out);
    }
}

// round 8
// speedup vs baseline: 7.0777x; 1.1529x over previous
#include <cuda_runtime.h>
#include <cuda_bf16.h>
#include <cuda_fp16.h>
#include <cstdint>

#define D_MODEL 1024
#define NHEAD   16
#define DHEAD   64
#define SEQ     2048
#define BATCH   2
#define M_TOTAL (BATCH * SEQ)   /* 4096 */
#define RANK    32
#define ASPLIT  2048            /* activation storage: [hi | lo] fp16 */

// ---------------- device scratch ----------------
__device__ __half g_xs [(size_t)M_TOTAL * ASPLIT];          // x split fp16
__device__ __half g_w2 [(size_t)4 * D_MODEL * D_MODEL];     // merged W single fp16
__device__ __half g_ao2[(size_t)M_TOTAL * ASPLIT];          // attn out split fp16
__device__ __half g_qh [(size_t)BATCH * NHEAD * SEQ * 64];  // single fp16 (scaled)
__device__ __half g_kh [(size_t)BATCH * NHEAD * SEQ * 64];  // single fp16
__device__ __half g_vh [(size_t)BATCH * NHEAD * SEQ * 64];  // single fp16

// ---------------- PTX helpers (baseline PTX only) ----------------
__device__ __forceinline__ uint32_t smem_u32(const void* p) {
    uint32_t a;
    asm("{ .reg .u64 t; cvta.to.shared.u64 t, %1; cvt.u32.u64 %0, t; }" : "=r"(a) : "l"(p));
    return a;
}
__device__ __forceinline__ void cpa16(uint32_t dst, const void* src) {
    asm volatile("cp.async.cg.shared.global [%0], [%1], 16;" :: "r"(dst), "l"(src));
}
#define CP_COMMIT() asm volatile("cp.async.commit_group;" ::: "memory")
#define CP_WAIT(n)  asm volatile("cp.async.wait_group %0;" :: "n"(n) : "memory")

__device__ __forceinline__ void ldsm_x4(uint32_t (&r)[4], uint32_t addr) {
    asm volatile("ldmatrix.sync.aligned.m8n8.x4.shared.b16 {%0,%1,%2,%3}, [%4];"
                 : "=r"(r[0]), "=r"(r[1]), "=r"(r[2]), "=r"(r[3]) : "r"(addr));
}
__device__ __forceinline__ void ldsm_x4t(uint32_t (&r)[4], uint32_t addr) {
    asm volatile("ldmatrix.sync.aligned.m8n8.x4.trans.shared.b16 {%0,%1,%2,%3}, [%4];"
                 : "=r"(r[0]), "=r"(r[1]), "=r"(r[2]), "=r"(r[3]) : "r"(addr));
}
__device__ __forceinline__ void mma16816h(float (&d)[4], const uint32_t (&a)[4],
                                          uint32_t b0, uint32_t b1) {
    asm volatile("mma.sync.aligned.m16n8k16.row.col.f32.f16.f16.f32 "
                 "{%0,%1,%2,%3}, {%4,%5,%6,%7}, {%8,%9}, {%0,%1,%2,%3};"
                 : "+f"(d[0]), "+f"(d[1]), "+f"(d[2]), "+f"(d[3])
                 : "r"(a[0]), "r"(a[1]), "r"(a[2]), "r"(a[3]), "r"(b0), "r"(b1));
}
__device__ __forceinline__ void split2h(float v, __half& h, __half& l) {
    h = __float2half(v);
    l = __float2half(v - __half2float(h));
}
__device__ __forceinline__ void packsplit2h(float v0, float v1, uint32_t& hi, uint32_t& lo) {
    __half h0, h1, l0, l1;
    split2h(v0, h0, l0); split2h(v1, h1, l1);
    __half2 th = __halves2half2(h0, h1);
    __half2 tl = __halves2half2(l0, l1);
    hi = reinterpret_cast<uint32_t&>(th);
    lo = reinterpret_cast<uint32_t&>(tl);
}
__device__ __forceinline__ uint32_t packh2(float v0, float v1) {
    __half2 t = __floats2half2_rn(v0, v1);
    return reinterpret_cast<uint32_t&>(t);
}

// ---------------- LoRA merge -> single fp16 (all 4 layers, one launch) -----
__global__ void merge_lora2(const float* __restrict__ W0, const float* __restrict__ dW0, const float* __restrict__ dB0,
                            const float* __restrict__ W1, const float* __restrict__ dW1, const float* __restrict__ dB1,
                            const float* __restrict__ W2, const float* __restrict__ dW2, const float* __restrict__ dB2,
                            const float* __restrict__ W3, const float* __restrict__ dW3, const float* __restrict__ dB3)
{
    const int layer = blockIdx.z;
    const float* W  = (layer == 0) ? W0  : (layer == 1) ? W1  : (layer == 2) ? W2  : W3;
    const float* dW = (layer == 0) ? dW0 : (layer == 1) ? dW1 : (layer == 2) ? dW2 : dW3;
    const float* dB = (layer == 0) ? dB0 : (layer == 1) ? dB1 : (layer == 2) ? dB2 : dB3;

    int e  = blockIdx.x * 256 + threadIdx.x;
    int n  = e >> 8;
    int kq = e & 255;
    float4 s = *(const float4*)(W + (size_t)n * D_MODEL + kq * 4);
    const float4* dW4 = (const float4*)dW;
#pragma unroll
    for (int r = 0; r < RANK; r++) {
        float b  = dB[n * RANK + r];
        float4 w = dW4[r * 256 + kq];
        s.x += b * w.x; s.y += b * w.y; s.z += b * w.z; s.w += b * w.w;
    }
    __half2* p = (__half2*)(g_w2 + (size_t)(layer * D_MODEL + n) * D_MODEL + kq * 4);
    p[0] = __floats2half2_rn(s.x, s.y);
    p[1] = __floats2half2_rn(s.z, s.w);
}

// ---------------- x -> fp16 hi/lo split ----------------
__global__ void prep_split(const float* __restrict__ src)
{
    int e   = blockIdx.x * 256 + threadIdx.x;
    int row = e >> 8;
    int kq  = e & 255;
    float4 s = *(const float4*)(src + (size_t)row * D_MODEL + kq * 4);
    __half h0, h1, h2, h3, l0, l1, l2, l3;
    split2h(s.x, h0, l0); split2h(s.y, h1, l1);
    split2h(s.z, h2, l2); split2h(s.w, h3, l3);
    size_t rowoff = (size_t)row * ASPLIT;
    __half2* ph = (__half2*)(g_xs + rowoff + kq * 4);
    __half2* pl = (__half2*)(g_xs + rowoff + D_MODEL + kq * 4);
    ph[0] = __halves2half2(h0, h1); ph[1] = __halves2half2(h2, h3);
    pl[0] = __halves2half2(l0, l1); pl[1] = __halves2half2(l2, l3);
}

// ---------------- HMMA GEMM: C[128,128] = A @ W^T (+bias) ------------------
// 16 chunks over physical K=1024; each stage holds {A-hi, A-lo, W}.
// W loaded ONCE per chunk and consumed by both A-terms.
#define GKC   64
#define GNCH  16
#define GROWB 144
#define GT_BYTES (128 * GROWB)      /* 18432 */
#define GSTAGE   (3 * GT_BYTES)     /* 55296: Ahi | Alo | W */
#define GSMEM    (2 * GSTAGE)       /* 110592, 2 CTAs/SM */

__global__ void __launch_bounds__(256, 2)
gemm_hmma(const __half* __restrict__ Abase,  // [*, ASPLIT]
          int mode, int layer_base,
          const float* __restrict__ b0, const float* __restrict__ b1,
          const float* __restrict__ b2, float* __restrict__ outO)
{
    extern __shared__ __align__(128) char smem[];
    const uint32_t sb = smem_u32(smem);
    const int tid = threadIdx.x, ln = tid & 31, w = tid >> 5;
    const int wm = w & 1, wn = w >> 1;
    const int bx = blockIdx.x, by = blockIdx.y, z = blockIdx.z;
    const int layer = layer_base + z;

    const __half* Arow = Abase + (size_t)(by * 128) * ASPLIT;
    const __half* Wrow = g_w2 + ((size_t)layer * D_MODEL + bx * 128) * D_MODEL;

    float acc[4][4][4] = {};

#define GLOAD(c) do {                                                          \
        int s_ = (c) & 1;                                                      \
        int x_ = (c) * GKC;                                                    \
        uint32_t bAh_ = sb + s_ * GSTAGE;                                      \
        uint32_t bAl_ = bAh_ + GT_BYTES;                                       \
        uint32_t bW_  = bAl_ + GT_BYTES;                                       \
        _Pragma("unroll")                                                      \
        for (int u_ = 0; u_ < 4; u_++) {                                       \
            int e_ = tid + u_ * 256;                                           \
            int row_ = e_ >> 3, seg_ = (e_ & 7) * 16;                          \
            cpa16(bAh_ + row_ * GROWB + seg_,                                  \
                  (const char*)(Arow + (size_t)row_ * ASPLIT + x_) + seg_);    \
            cpa16(bAl_ + row_ * GROWB + seg_,                                  \
                  (const char*)(Arow + (size_t)row_ * ASPLIT + 1024 + x_) + seg_); \
            cpa16(bW_ + row_ * GROWB + seg_,                                   \
                  (const char*)(Wrow + (size_t)row_ * D_MODEL + x_) + seg_);   \
        }                                                                      \
        CP_COMMIT();                                                           \
    } while (0)

    GLOAD(0);
    for (int c = 0; c < GNCH; c++) {
        CP_WAIT(0);
        __syncthreads();                 // stage c ready; all warps done with c-1
        if (c + 1 < GNCH) GLOAD(c + 1);  // overlaps with compute below

        const uint32_t bAh = sb + (c & 1) * GSTAGE;
        const uint32_t bAl = bAh + GT_BYTES;
        const uint32_t bW  = bAl + GT_BYTES;
#pragma unroll
        for (int ks = 0; ks < 4; ks++) {
            const int k0 = ks * 16;
            const uint32_t aoff = (k0 + ((ln >> 4) << 3)) * 2;
            uint32_t afh[4][4], afl[4][4];
#pragma unroll
            for (int i = 0; i < 4; i++) {
                int row = wm * 64 + i * 16 + (ln & 15);
                ldsm_x4(afh[i], bAh + row * GROWB + aoff);
                ldsm_x4(afl[i], bAl + row * GROWB + aoff);
            }
            uint32_t bfr[2][4];
#pragma unroll
            for (int j = 0; j < 2; j++) {
                int n = wn * 32 + j * 16 + (ln & 7) + ((ln & 16) ? 8 : 0);
                ldsm_x4(bfr[j], bW + n * GROWB + (k0 + ((ln & 8) ? 8 : 0)) * 2);
            }
#pragma unroll
            for (int i = 0; i < 4; i++)
#pragma unroll
                for (int jj = 0; jj < 4; jj++) {
                    mma16816h(acc[i][jj], afh[i], bfr[jj >> 1][(jj & 1) * 2],
                              bfr[jj >> 1][(jj & 1) * 2 + 1]);
                    mma16816h(acc[i][jj], afl[i], bfr[jj >> 1][(jj & 1) * 2],
                              bfr[jj >> 1][(jj & 1) * 2 + 1]);
                }
        }
    }

    const float* bias = (z == 0) ? b0 : (z == 1) ? b1 : b2;
    const float qscale = (mode == 0 && z == 0) ? 0.125f : 1.0f;
#pragma unroll
    for (int i = 0; i < 4; i++) {
#pragma unroll
        for (int dl = 0; dl < 2; dl++) {
            const int m = by * 128 + wm * 64 + i * 16 + (ln >> 2) + dl * 8;
#pragma unroll
            for (int jj = 0; jj < 4; jj++) {
                const int cgl = bx * 128 + wn * 32 + jj * 8 + (ln & 3) * 2;
                float v0 = (acc[i][jj][dl * 2 + 0] + bias[cgl])     * qscale;
                float v1 = (acc[i][jj][dl * 2 + 1] + bias[cgl + 1]) * qscale;
                if (mode == 0) {
                    const int h = cgl >> 6, d = cgl & 63;
                    const int b = m >> 11, n = m & 2047;
                    const size_t rowb = (size_t)(b * NHEAD + h) * SEQ + n;
                    __half* base = ((z == 0) ? g_qh : (z == 1) ? g_kh : g_vh)
                                   + rowb * 64 + d;
                    *(__half2*)base = __floats2half2_rn(v0, v1);
                } else {
                    float2 o; o.x = v0; o.y = v1;
                    *(float2*)(outO + (size_t)m * D_MODEL + cgl) = o;
                }
            }
        }
    }
}

// ---------------- Flash attention: FA2, all operands single fp16 -----------
// S = Q @ K^T;  O += P @ V.  Q fragments fully register-resident.
#define KROWB 144                         /* 64 fp16 + 8 pad */
#define KTILEB (64 * KROWB)               /* 9216 */
#define QROWS 128
#define SM_Q   0
#define QBYTES (QROWS * KROWB)            /* 18432 */
#define SM_K0  QBYTES
#define SM_V0  (SM_K0 + 2 * KTILEB)       /* 36864 */
#define ATT_SMEM (SM_V0 + 2 * KTILEB)     /* 55296 */
#define NT (SEQ / 64)

__global__ void __launch_bounds__(256, 2)
flash_hmma()
{
    extern __shared__ __align__(128) char smem[];
    const uint32_t sb = smem_u32(smem);
    const int tid = threadIdx.x, ln = tid & 31, w = tid >> 5;
    const int qt = blockIdx.x, bh = blockIdx.y;

    const __half* qg = g_qh + ((size_t)bh * SEQ + qt * QROWS) * 64;
    const __half* kg = g_kh + (size_t)bh * SEQ * 64;
    const __half* vg = g_vh + (size_t)bh * SEQ * 64;

    // Q tile: 128 rows x 128B = 1024 x 16B
#pragma unroll
    for (int u = 0; u < 4; u++) {
        int e = tid + u * 256;
        int row = e >> 3, seg = (e & 7) * 16;
        cpa16(sb + SM_Q + row * KROWB + seg, (const char*)(qg + (size_t)row * 64) + seg);
    }
    CP_COMMIT();

#define ATT_LOAD(t) do {                                                       \
        int buf_ = (t) & 1;                                                    \
        const __half* kb_ = kg + (size_t)(t) * 64 * 64;                        \
        const __half* vb_ = vg + (size_t)(t) * 64 * 64;                        \
        uint32_t kd_ = sb + SM_K0 + buf_ * KTILEB;                             \
        uint32_t vd_ = sb + SM_V0 + buf_ * KTILEB;                             \
        _Pragma("unroll")                                                      \
        for (int u_ = 0; u_ < 2; u_++) {                                       \
            int e_ = tid + u_ * 256;                                           \
            int row_ = e_ >> 3, seg_ = (e_ & 7) * 16;                          \
            cpa16(kd_ + row_ * KROWB + seg_,                                   \
                  (const char*)(kb_ + (size_t)row_ * 64) + seg_);              \
            cpa16(vd_ + row_ * KROWB + seg_,                                   \
                  (const char*)(vb_ + (size_t)row_ * 64) + seg_);              \
        }                                                                      \
        CP_COMMIT();                                                           \
    } while (0)

    ATT_LOAD(0);
    CP_WAIT(0);
    __syncthreads();

    // fully resident Q fragments
    const uint32_t qaddr = sb + SM_Q + (w * 16 + (ln & 15)) * KROWB + (((ln >> 4) << 3)) * 2;
    uint32_t qf[4][4];
#pragma unroll
    for (int s = 0; s < 4; s++)
        ldsm_x4(qf[s], qaddr + (s * 16) * 2);

    const int krow8  = (ln & 7) + ((ln & 16) ? 8 : 0);
    const int kcol8  = (ln & 8) ? 8 : 0;
    const int vrow16 = ln & 15;
    const int vcol8  = (ln & 16) ? 8 : 0;

    float m0 = -1e30f, m1 = -1e30f, l0 = 0.f, l1 = 0.f;
    float acco[8][4] = {};

    for (int kt = 0; kt < NT; kt++) {
        if (kt > 0) { CP_WAIT(0); __syncthreads(); }
        if (kt + 1 < NT) ATT_LOAD(kt + 1);
        const uint32_t bK = sb + SM_K0 + (kt & 1) * KTILEB;
        const uint32_t bV = sb + SM_V0 + (kt & 1) * KTILEB;

        // ---- S = Q K^T: single term ----
        float accs[8][4] = {};
#pragma unroll
        for (int ks = 0; ks < 4; ks++) {
#pragma unroll
            for (int nbp = 0; nbp < 4; nbp++) {
                uint32_t kb[4];
                ldsm_x4(kb, bK + (nbp * 16 + krow8) * KROWB + (ks * 16 + kcol8) * 2);
                mma16816h(accs[2 * nbp],     qf[ks], kb[0], kb[1]);
                mma16816h(accs[2 * nbp + 1], qf[ks], kb[2], kb[3]);
            }
        }

        // ---- warp-local online softmax ----
        float mx0 = -1e30f, mx1 = -1e30f;
#pragma unroll
        for (int jj = 0; jj < 8; jj++) {
            mx0 = fmaxf(mx0, fmaxf(accs[jj][0], accs[jj][1]));
            mx1 = fmaxf(mx1, fmaxf(accs[jj][2], accs[jj][3]));
        }
        mx0 = fmaxf(mx0, __shfl_xor_sync(0xffffffffu, mx0, 1));
        mx0 = fmaxf(mx0, __shfl_xor_sync(0xffffffffu, mx0, 2));
        mx1 = fmaxf(mx1, __shfl_xor_sync(0xffffffffu, mx1, 1));
        mx1 = fmaxf(mx1, __shfl_xor_sync(0xffffffffu, mx1, 2));
        const float mn0 = fmaxf(m0, mx0), mn1 = fmaxf(m1, mx1);
        const float a0 = __expf(m0 - mn0), a1 = __expf(m1 - mn1);
        m0 = mn0; m1 = mn1;

        float s0 = 0.f, s1 = 0.f;
#pragma unroll
        for (int jj = 0; jj < 8; jj++) {
            accs[jj][0] = __expf(accs[jj][0] - mn0);
            accs[jj][1] = __expf(accs[jj][1] - mn0);
            accs[jj][2] = __expf(accs[jj][2] - mn1);
            accs[jj][3] = __expf(accs[jj][3] - mn1);
            s0 += accs[jj][0] + accs[jj][1];
            s1 += accs[jj][2] + accs[jj][3];
        }
        s0 += __shfl_xor_sync(0xffffffffu, s0, 1);
        s0 += __shfl_xor_sync(0xffffffffu, s0, 2);
        s1 += __shfl_xor_sync(0xffffffffu, s1, 1);
        s1 += __shfl_xor_sync(0xffffffffu, s1, 2);
        l0 = l0 * a0 + s0;
        l1 = l1 * a1 + s1;
#pragma unroll
        for (int jj = 0; jj < 8; jj++) {
            acco[jj][0] *= a0; acco[jj][1] *= a0;
            acco[jj][2] *= a1; acco[jj][3] *= a1;
        }

        // ---- O += P @ V: P fp16, V single fp16 ----
#pragma unroll
        for (int ks = 0; ks < 4; ks++) {
            uint32_t phi[4];
            phi[0] = packh2(accs[2 * ks][0],     accs[2 * ks][1]);
            phi[1] = packh2(accs[2 * ks][2],     accs[2 * ks][3]);
            phi[2] = packh2(accs[2 * ks + 1][0], accs[2 * ks + 1][1]);
            phi[3] = packh2(accs[2 * ks + 1][2], accs[2 * ks + 1][3]);
#pragma unroll
            for (int nbp = 0; nbp < 4; nbp++) {
                uint32_t vb[4];
                ldsm_x4t(vb, bV + (ks * 16 + vrow16) * KROWB + (nbp * 16 + vcol8) * 2);
                mma16816h(acco[2 * nbp],     phi, vb[0], vb[1]);
                mma16816h(acco[2 * nbp + 1], phi, vb[2], vb[3]);
            }
        }
    }

    // ---- epilogue: normalize, fp16 split, write to g_ao2 (2-term) ----
    const int b = bh >> 4, h = bh & 15;
    const int q = ln >> 2, t4 = ln & 3;
    const float inv0 = 1.f / l0, inv1 = 1.f / l1;
    const size_t n0 = (size_t)qt * QROWS + w * 16 + q;
    const size_t mg0 = (size_t)b * SEQ + n0;
    const size_t mg1 = mg0 + 8;
#pragma unroll
    for (int jj = 0; jj < 8; jj++) {
        const int col = h * 64 + jj * 8 + t4 * 2;
        uint32_t hi, lo;
        packsplit2h(acco[jj][0] * inv0, acco[jj][1] * inv0, hi, lo);
        *(uint32_t*)(g_ao2 + mg0 * ASPLIT + col)        = hi;
        *(uint32_t*)(g_ao2 + mg0 * ASPLIT + 1024 + col) = lo;
        packsplit2h(acco[jj][2] * inv1, acco[jj][3] * inv1, hi, lo);
        *(uint32_t*)(g_ao2 + mg1 * ASPLIT + col)        = hi;
        *(uint32_t*)(g_ao2 + mg1 * ASPLIT + 1024 + col) = lo;
    }
}

// ---------------- launch --------------------------------------------------
extern "C" void kernel_launch(void* const* d_in, const int* in_sizes, int n_in,
                              void* d_out, int out_size)
{
    const float* x = (const float*)d_in[0];
    const float* W [4] = {(const float*)d_in[1],  (const float*)d_in[5],
                          (const float*)d_in[9],  (const float*)d_in[13]};
    const float* B [4] = {(const float*)d_in[2],  (const float*)d_in[6],
                          (const float*)d_in[10], (const float*)d_in[14]};
    const float* dW[4] = {(const float*)d_in[3],  (const float*)d_in[7],
                          (const float*)d_in[11], (const float*)d_in[15]};
    const float* dB[4] = {(const float*)d_in[4],  (const float*)d_in[8],
                          (const float*)d_in[12], (const float*)d_in[16]};
    float* out = (float*)d_out;

    void *pxs, *pao;
    cudaGetSymbolAddress(&pxs, g_xs);
    cudaGetSymbolAddress(&pao, g_ao2);

    // 1) LoRA merge -> single fp16 (one launch, 4 layers)
    {
        dim3 grid(1024, 1, 4);
        merge_lora2<<<grid, 256>>>(W[0], dW[0], dB[0], W[1], dW[1], dB[1],
                                   W[2], dW[2], dB[2], W[3], dW[3], dB[3]);
    }

    // 2) x -> fp16 hi/lo split
    prep_split<<<4096, 256>>>(x);

    // 3) QKV projections (fp16 2-term, W loaded once per chunk)
    cudaFuncSetAttribute(gemm_hmma, cudaFuncAttributeMaxDynamicSharedMemorySize, GSMEM);
    {
        dim3 grid(D_MODEL / 128, M_TOTAL / 128, 3);
        gemm_hmma<<<grid, 256, GSMEM>>>((const __half*)pxs, 0, 0,
                                        B[0], B[1], B[2], nullptr);
    }

    // 4) flash attention (all single fp16) -> g_ao2
    cudaFuncSetAttribute(flash_hmma, cudaFuncAttributeMaxDynamicSharedMemorySize, ATT_SMEM);
    {
        dim3 grid(SEQ / QROWS, BATCH * NHEAD);
        flash_hmma<<<grid, 256, ATT_SMEM>>>();
    }

    // 5) O projection (fp16 2-term) -> d_out
    {
        dim3 grid(D_MODEL / 128, M_TOTAL / 128, 1);
        gemm_hmma<<<grid, 256, GSMEM>>>((const __half*)pao, 1, 3,
                                        B[3], B[3], B[3], out);
    }
}

// round 9
// speedup vs baseline: 8.7512x; 1.2365x over previous
#include <cuda_runtime.h>
#include <cuda_fp16.h>
#include <cstdint>

#define D_MODEL 1024
#define NHEAD   16
#define DHEAD   64
#define SEQ     2048
#define BATCH   2
#define M_TOTAL (BATCH * SEQ)   /* 4096 */
#define RANK    32

// ---------------- device scratch (all single fp16) ----------------
__device__ __half g_xh [(size_t)M_TOTAL * D_MODEL];         // x fp16
__device__ __half g_w2 [(size_t)4 * D_MODEL * D_MODEL];     // merged W fp16
__device__ __half g_ao [(size_t)M_TOTAL * D_MODEL];         // attn out fp16
__device__ __half g_qh [(size_t)BATCH * NHEAD * SEQ * 64];  // scaled Q fp16
__device__ __half g_kh [(size_t)BATCH * NHEAD * SEQ * 64];
__device__ __half g_vh [(size_t)BATCH * NHEAD * SEQ * 64];

// ---------------- PTX helpers (baseline PTX only) ----------------
__device__ __forceinline__ uint32_t smem_u32(const void* p) {
    uint32_t a;
    asm("{ .reg .u64 t; cvta.to.shared.u64 t, %1; cvt.u32.u64 %0, t; }" : "=r"(a) : "l"(p));
    return a;
}
__device__ __forceinline__ void cpa16(uint32_t dst, const void* src) {
    asm volatile("cp.async.cg.shared.global [%0], [%1], 16;" :: "r"(dst), "l"(src));
}
#define CP_COMMIT() asm volatile("cp.async.commit_group;" ::: "memory")
#define CP_WAIT(n)  asm volatile("cp.async.wait_group %0;" :: "n"(n) : "memory")

__device__ __forceinline__ void ldsm_x4(uint32_t (&r)[4], uint32_t addr) {
    asm volatile("ldmatrix.sync.aligned.m8n8.x4.shared.b16 {%0,%1,%2,%3}, [%4];"
                 : "=r"(r[0]), "=r"(r[1]), "=r"(r[2]), "=r"(r[3]) : "r"(addr));
}
__device__ __forceinline__ void ldsm_x4t(uint32_t (&r)[4], uint32_t addr) {
    asm volatile("ldmatrix.sync.aligned.m8n8.x4.trans.shared.b16 {%0,%1,%2,%3}, [%4];"
                 : "=r"(r[0]), "=r"(r[1]), "=r"(r[2]), "=r"(r[3]) : "r"(addr));
}
__device__ __forceinline__ void mma16816h(float (&d)[4], const uint32_t (&a)[4],
                                          uint32_t b0, uint32_t b1) {
    asm volatile("mma.sync.aligned.m16n8k16.row.col.f32.f16.f16.f32 "
                 "{%0,%1,%2,%3}, {%4,%5,%6,%7}, {%8,%9}, {%0,%1,%2,%3};"
                 : "+f"(d[0]), "+f"(d[1]), "+f"(d[2]), "+f"(d[3])
                 : "r"(a[0]), "r"(a[1]), "r"(a[2]), "r"(a[3]), "r"(b0), "r"(b1));
}
__device__ __forceinline__ uint32_t packh2(float v0, float v1) {
    __half2 t = __floats2half2_rn(v0, v1);
    return reinterpret_cast<uint32_t&>(t);
}

// ---------------- LoRA merge -> single fp16 (all 4 layers, one launch) -----
__global__ void merge_lora2(const float* __restrict__ W0, const float* __restrict__ dW0, const float* __restrict__ dB0,
                            const float* __restrict__ W1, const float* __restrict__ dW1, const float* __restrict__ dB1,
                            const float* __restrict__ W2, const float* __restrict__ dW2, const float* __restrict__ dB2,
                            const float* __restrict__ W3, const float* __restrict__ dW3, const float* __restrict__ dB3)
{
    const int layer = blockIdx.z;
    const float* W  = (layer == 0) ? W0  : (layer == 1) ? W1  : (layer == 2) ? W2  : W3;
    const float* dW = (layer == 0) ? dW0 : (layer == 1) ? dW1 : (layer == 2) ? dW2 : dW3;
    const float* dB = (layer == 0) ? dB0 : (layer == 1) ? dB1 : (layer == 2) ? dB2 : dB3;

    int e  = blockIdx.x * 256 + threadIdx.x;
    int n  = e >> 8;
    int kq = e & 255;
    float4 s = *(const float4*)(W + (size_t)n * D_MODEL + kq * 4);
    const float4* dW4 = (const float4*)dW;
#pragma unroll
    for (int r = 0; r < RANK; r++) {
        float b  = dB[n * RANK + r];
        float4 w = dW4[r * 256 + kq];
        s.x += b * w.x; s.y += b * w.y; s.z += b * w.z; s.w += b * w.w;
    }
    __half2* p = (__half2*)(g_w2 + (size_t)(layer * D_MODEL + n) * D_MODEL + kq * 4);
    p[0] = __floats2half2_rn(s.x, s.y);
    p[1] = __floats2half2_rn(s.z, s.w);
}

// ---------------- x -> single fp16 ----------------
__global__ void prep_h(const float* __restrict__ src)
{
    int e = blockIdx.x * 256 + threadIdx.x;     // float4 index
    float4 s = *(const float4*)(src + (size_t)e * 4);
    __half2* p = (__half2*)(g_xh + (size_t)e * 4);
    p[0] = __floats2half2_rn(s.x, s.y);
    p[1] = __floats2half2_rn(s.z, s.w);
}

// ---------------- HMMA GEMM: C[128,128] = A @ W^T (+bias), single fp16 -----
#define GKC   64
#define GNCH  16
#define GROWB 144
#define GT_BYTES (128 * GROWB)      /* 18432 */
#define GSTAGE   (2 * GT_BYTES)     /* 36864: A | W */
#define GSTAGES  3
#define GSMEM    (GSTAGES * GSTAGE) /* 110592, 2 CTAs/SM */

__global__ void __launch_bounds__(256, 2)
gemm_hmma(const __half* __restrict__ Abase,  // [*, D_MODEL]
          int mode, int layer_base,
          const float* __restrict__ b0, const float* __restrict__ b1,
          const float* __restrict__ b2, float* __restrict__ outO)
{
    extern __shared__ __align__(128) char smem[];
    const uint32_t sb = smem_u32(smem);
    const int tid = threadIdx.x, ln = tid & 31, w = tid >> 5;
    const int wm = w & 1, wn = w >> 1;
    const int bx = blockIdx.x, by = blockIdx.y, z = blockIdx.z;
    const int layer = layer_base + z;

    const __half* Arow = Abase + (size_t)(by * 128) * D_MODEL;
    const __half* Wrow = g_w2 + ((size_t)layer * D_MODEL + bx * 128) * D_MODEL;

    float acc[4][4][4] = {};

#define GLOAD(c) do {                                                          \
        int s_ = (c) % GSTAGES;                                                \
        int x_ = (c) * GKC;                                                    \
        uint32_t bA_ = sb + s_ * GSTAGE;                                       \
        uint32_t bW_ = bA_ + GT_BYTES;                                         \
        _Pragma("unroll")                                                      \
        for (int u_ = 0; u_ < 4; u_++) {                                       \
            int e_ = tid + u_ * 256;                                           \
            int row_ = e_ >> 3, seg_ = (e_ & 7) * 16;                          \
            cpa16(bA_ + row_ * GROWB + seg_,                                   \
                  (const char*)(Arow + (size_t)row_ * D_MODEL + x_) + seg_);   \
            cpa16(bW_ + row_ * GROWB + seg_,                                   \
                  (const char*)(Wrow + (size_t)row_ * D_MODEL + x_) + seg_);   \
        }                                                                      \
        CP_COMMIT();                                                           \
    } while (0)

    GLOAD(0);
    GLOAD(1);
    for (int c = 0; c < GNCH; c++) {
        if (c + 2 < GNCH) { CP_WAIT(1); } else { CP_WAIT(0); }
        __syncthreads();
        if (c + 2 < GNCH) GLOAD(c + 2);

        const uint32_t bA = sb + (c % GSTAGES) * GSTAGE;
        const uint32_t bW = bA + GT_BYTES;
#pragma unroll
        for (int ks = 0; ks < 4; ks++) {
            const int k0 = ks * 16;
            uint32_t afr[4][4];
#pragma unroll
            for (int i = 0; i < 4; i++) {
                int row = wm * 64 + i * 16 + (ln & 15);
                ldsm_x4(afr[i], bA + row * GROWB + (k0 + ((ln >> 4) << 3)) * 2);
            }
            uint32_t bfr[2][4];
#pragma unroll
            for (int j = 0; j < 2; j++) {
                int n = wn * 32 + j * 16 + (ln & 7) + ((ln & 16) ? 8 : 0);
                ldsm_x4(bfr[j], bW + n * GROWB + (k0 + ((ln & 8) ? 8 : 0)) * 2);
            }
#pragma unroll
            for (int i = 0; i < 4; i++)
#pragma unroll
                for (int jj = 0; jj < 4; jj++)
                    mma16816h(acc[i][jj], afr[i], bfr[jj >> 1][(jj & 1) * 2],
                              bfr[jj >> 1][(jj & 1) * 2 + 1]);
        }
    }

    const float* bias = (z == 0) ? b0 : (z == 1) ? b1 : b2;
    const float qscale = (mode == 0 && z == 0) ? 0.125f : 1.0f;
#pragma unroll
    for (int i = 0; i < 4; i++) {
#pragma unroll
        for (int dl = 0; dl < 2; dl++) {
            const int m = by * 128 + wm * 64 + i * 16 + (ln >> 2) + dl * 8;
#pragma unroll
            for (int jj = 0; jj < 4; jj++) {
                const int cgl = bx * 128 + wn * 32 + jj * 8 + (ln & 3) * 2;
                float v0 = (acc[i][jj][dl * 2 + 0] + bias[cgl])     * qscale;
                float v1 = (acc[i][jj][dl * 2 + 1] + bias[cgl + 1]) * qscale;
                if (mode == 0) {
                    const int h = cgl >> 6, d = cgl & 63;
                    const int b = m >> 11, n = m & 2047;
                    const size_t rowb = (size_t)(b * NHEAD + h) * SEQ + n;
                    __half* base = ((z == 0) ? g_qh : (z == 1) ? g_kh : g_vh)
                                   + rowb * 64 + d;
                    *(__half2*)base = __floats2half2_rn(v0, v1);
                } else {
                    float2 o; o.x = v0; o.y = v1;
                    *(float2*)(outO + (size_t)m * D_MODEL + cgl) = o;
                }
            }
        }
    }
}

// ---------------- Flash attention: FA2, all single fp16 --------------------
#define KROWB 144                         /* 64 fp16 + 8 pad */
#define KTILEB (64 * KROWB)               /* 9216 */
#define QROWS 128
#define SM_Q   0
#define QBYTES (QROWS * KROWB)            /* 18432 */
#define SM_K0  QBYTES
#define SM_V0  (SM_K0 + 2 * KTILEB)
#define ATT_SMEM (SM_V0 + 2 * KTILEB)     /* 55296 */
#define NT (SEQ / 64)

__global__ void __launch_bounds__(256, 2)
flash_hmma()
{
    extern __shared__ __align__(128) char smem[];
    const uint32_t sb = smem_u32(smem);
    const int tid = threadIdx.x, ln = tid & 31, w = tid >> 5;
    const int qt = blockIdx.x, bh = blockIdx.y;

    const __half* qg = g_qh + ((size_t)bh * SEQ + qt * QROWS) * 64;
    const __half* kg = g_kh + (size_t)bh * SEQ * 64;
    const __half* vg = g_vh + (size_t)bh * SEQ * 64;

#pragma unroll
    for (int u = 0; u < 4; u++) {
        int e = tid + u * 256;
        int row = e >> 3, seg = (e & 7) * 16;
        cpa16(sb + SM_Q + row * KROWB + seg, (const char*)(qg + (size_t)row * 64) + seg);
    }
    CP_COMMIT();

#define ATT_LOAD(t) do {                                                       \
        int buf_ = (t) & 1;                                                    \
        const __half* kb_ = kg + (size_t)(t) * 64 * 64;                        \
        const __half* vb_ = vg + (size_t)(t) * 64 * 64;                        \
        uint32_t kd_ = sb + SM_K0 + buf_ * KTILEB;                             \
        uint32_t vd_ = sb + SM_V0 + buf_ * KTILEB;                             \
        _Pragma("unroll")                                                      \
        for (int u_ = 0; u_ < 2; u_++) {                                       \
            int e_ = tid + u_ * 256;                                           \
            int row_ = e_ >> 3, seg_ = (e_ & 7) * 16;                          \
            cpa16(kd_ + row_ * KROWB + seg_,                                   \
                  (const char*)(kb_ + (size_t)row_ * 64) + seg_);              \
            cpa16(vd_ + row_ * KROWB + seg_,                                   \
                  (const char*)(vb_ + (size_t)row_ * 64) + seg_);              \
        }                                                                      \
        CP_COMMIT();                                                           \
    } while (0)

    ATT_LOAD(0);
    CP_WAIT(0);
    __syncthreads();

    const uint32_t qaddr = sb + SM_Q + (w * 16 + (ln & 15)) * KROWB + (((ln >> 4) << 3)) * 2;
    uint32_t qf[4][4];
#pragma unroll
    for (int s = 0; s < 4; s++)
        ldsm_x4(qf[s], qaddr + (s * 16) * 2);

    const int krow8  = (ln & 7) + ((ln & 16) ? 8 : 0);
    const int kcol8  = (ln & 8) ? 8 : 0;
    const int vrow16 = ln & 15;
    const int vcol8  = (ln & 16) ? 8 : 0;

    float m0 = -1e30f, m1 = -1e30f, l0 = 0.f, l1 = 0.f;
    float acco[8][4] = {};

    for (int kt = 0; kt < NT; kt++) {
        if (kt > 0) { CP_WAIT(0); __syncthreads(); }
        if (kt + 1 < NT) ATT_LOAD(kt + 1);
        const uint32_t bK = sb + SM_K0 + (kt & 1) * KTILEB;
        const uint32_t bV = sb + SM_V0 + (kt & 1) * KTILEB;

        // ---- S = Q K^T ----
        float accs[8][4] = {};
#pragma unroll
        for (int ks = 0; ks < 4; ks++) {
#pragma unroll
            for (int nbp = 0; nbp < 4; nbp++) {
                uint32_t kb[4];
                ldsm_x4(kb, bK + (nbp * 16 + krow8) * KROWB + (ks * 16 + kcol8) * 2);
                mma16816h(accs[2 * nbp],     qf[ks], kb[0], kb[1]);
                mma16816h(accs[2 * nbp + 1], qf[ks], kb[2], kb[3]);
            }
        }

        // ---- warp-local online softmax ----
        float mx0 = -1e30f, mx1 = -1e30f;
#pragma unroll
        for (int jj = 0; jj < 8; jj++) {
            mx0 = fmaxf(mx0, fmaxf(accs[jj][0], accs[jj][1]));
            mx1 = fmaxf(mx1, fmaxf(accs[jj][2], accs[jj][3]));
        }
        mx0 = fmaxf(mx0, __shfl_xor_sync(0xffffffffu, mx0, 1));
        mx0 = fmaxf(mx0, __shfl_xor_sync(0xffffffffu, mx0, 2));
        mx1 = fmaxf(mx1, __shfl_xor_sync(0xffffffffu, mx1, 1));
        mx1 = fmaxf(mx1, __shfl_xor_sync(0xffffffffu, mx1, 2));

        // correction factors; skip exp + rescale when the running max held
        float a0 = 1.f, a1 = 1.f;
        bool resc = false;
        if (mx0 > m0) { a0 = __expf(m0 - mx0); m0 = mx0; resc = true; }
        if (mx1 > m1) { a1 = __expf(m1 - mx1); m1 = mx1; resc = true; }

        float s0 = 0.f, s1 = 0.f;
#pragma unroll
        for (int jj = 0; jj < 8; jj++) {
            accs[jj][0] = __expf(accs[jj][0] - m0);
            accs[jj][1] = __expf(accs[jj][1] - m0);
            accs[jj][2] = __expf(accs[jj][2] - m1);
            accs[jj][3] = __expf(accs[jj][3] - m1);
            s0 += accs[jj][0] + accs[jj][1];
            s1 += accs[jj][2] + accs[jj][3];
        }
        s0 += __shfl_xor_sync(0xffffffffu, s0, 1);
        s0 += __shfl_xor_sync(0xffffffffu, s0, 2);
        s1 += __shfl_xor_sync(0xffffffffu, s1, 1);
        s1 += __shfl_xor_sync(0xffffffffu, s1, 2);
        l0 = l0 * a0 + s0;
        l1 = l1 * a1 + s1;
        if (resc) {
#pragma unroll
            for (int jj = 0; jj < 8; jj++) {
                acco[jj][0] *= a0; acco[jj][1] *= a0;
                acco[jj][2] *= a1; acco[jj][3] *= a1;
            }
        }

        // ---- O += P @ V ----
#pragma unroll
        for (int ks = 0; ks < 4; ks++) {
            uint32_t phi[4];
            phi[0] = packh2(accs[2 * ks][0],     accs[2 * ks][1]);
            phi[1] = packh2(accs[2 * ks][2],     accs[2 * ks][3]);
            phi[2] = packh2(accs[2 * ks + 1][0], accs[2 * ks + 1][1]);
            phi[3] = packh2(accs[2 * ks + 1][2], accs[2 * ks + 1][3]);
#pragma unroll
            for (int nbp = 0; nbp < 4; nbp++) {
                uint32_t vb[4];
                ldsm_x4t(vb, bV + (ks * 16 + vrow16) * KROWB + (nbp * 16 + vcol8) * 2);
                mma16816h(acco[2 * nbp],     phi, vb[0], vb[1]);
                mma16816h(acco[2 * nbp + 1], phi, vb[2], vb[3]);
            }
        }
    }

    // ---- epilogue: normalize, write single fp16 to g_ao ----
    const int b = bh >> 4, h = bh & 15;
    const int q = ln >> 2, t4 = ln & 3;
    const float inv0 = 1.f / l0, inv1 = 1.f / l1;
    const size_t n0 = (size_t)qt * QROWS + w * 16 + q;
    const size_t mg0 = (size_t)b * SEQ + n0;
    const size_t mg1 = mg0 + 8;
#pragma unroll
    for (int jj = 0; jj < 8; jj++) {
        const int col = h * 64 + jj * 8 + t4 * 2;
        *(uint32_t*)(g_ao + mg0 * D_MODEL + col) =
            packh2(acco[jj][0] * inv0, acco[jj][1] * inv0);
        *(uint32_t*)(g_ao + mg1 * D_MODEL + col) =
            packh2(acco[jj][2] * inv1, acco[jj][3] * inv1);
    }
}

// ---------------- launch --------------------------------------------------
extern "C" void kernel_launch(void* const* d_in, const int* in_sizes, int n_in,
                              void* d_out, int out_size)
{
    const float* x = (const float*)d_in[0];
    const float* W [4] = {(const float*)d_in[1],  (const float*)d_in[5],
                          (const float*)d_in[9],  (const float*)d_in[13]};
    const float* B [4] = {(const float*)d_in[2],  (const float*)d_in[6],
                          (const float*)d_in[10], (const float*)d_in[14]};
    const float* dW[4] = {(const float*)d_in[3],  (const float*)d_in[7],
                          (const float*)d_in[11], (const float*)d_in[15]};
    const float* dB[4] = {(const float*)d_in[4],  (const float*)d_in[8],
                          (const float*)d_in[12], (const float*)d_in[16]};
    float* out = (float*)d_out;

    void *pxh, *pao;
    cudaGetSymbolAddress(&pxh, g_xh);
    cudaGetSymbolAddress(&pao, g_ao);

    // 1) LoRA merge -> single fp16 (one launch, 4 layers)
    {
        dim3 grid(1024, 1, 4);
        merge_lora2<<<grid, 256>>>(W[0], dW[0], dB[0], W[1], dW[1], dB[1],
                                   W[2], dW[2], dB[2], W[3], dW[3], dB[3]);
    }

    // 2) x -> fp16
    prep_h<<<4096, 256>>>(x);

    // 3) QKV projections (single fp16, 3-stage pipeline)
    cudaFuncSetAttribute(gemm_hmma, cudaFuncAttributeMaxDynamicSharedMemorySize, GSMEM);
    {
        dim3 grid(D_MODEL / 128, M_TOTAL / 128, 3);
        gemm_hmma<<<grid, 256, GSMEM>>>((const __half*)pxh, 0, 0,
                                        B[0], B[1], B[2], nullptr);
    }

    // 4) flash attention -> g_ao
    cudaFuncSetAttribute(flash_hmma, cudaFuncAttributeMaxDynamicSharedMemorySize, ATT_SMEM);
    {
        dim3 grid(SEQ / QROWS, BATCH * NHEAD);
        flash_hmma<<<grid, 256, ATT_SMEM>>>();
    }

    // 5) O projection -> d_out
    {
        dim3 grid(D_MODEL / 128, M_TOTAL / 128, 1);
        gemm_hmma<<<grid, 256, GSMEM>>>((const __half*)pao, 1, 3,
                                        B[3], B[3], B[3], out);
    }
}

// round 10
// speedup vs baseline: 9.3236x; 1.0654x over previous
#include <cuda_runtime.h>
#include <cuda_fp16.h>
#include <cstdint>

#define D_MODEL 1024
#define NHEAD   16
#define DHEAD   64
#define SEQ     2048
#define BATCH   2
#define M_TOTAL (BATCH * SEQ)   /* 4096 */
#define RANK    32

// ---------------- device scratch (all single fp16) ----------------
__device__ __half g_xh [(size_t)M_TOTAL * D_MODEL];         // x fp16
__device__ __half g_w2 [(size_t)4 * D_MODEL * D_MODEL];     // merged W fp16
__device__ __half g_ao [(size_t)M_TOTAL * D_MODEL];         // attn out fp16
__device__ __half g_qh [(size_t)BATCH * NHEAD * SEQ * 64];  // Q scaled by 0.125*log2e
__device__ __half g_kh [(size_t)BATCH * NHEAD * SEQ * 64];
__device__ __half g_vh [(size_t)BATCH * NHEAD * SEQ * 64];

// ---------------- PTX helpers (baseline PTX only) ----------------
__device__ __forceinline__ uint32_t smem_u32(const void* p) {
    uint32_t a;
    asm("{ .reg .u64 t; cvta.to.shared.u64 t, %1; cvt.u32.u64 %0, t; }" : "=r"(a) : "l"(p));
    return a;
}
__device__ __forceinline__ void cpa16(uint32_t dst, const void* src) {
    asm volatile("cp.async.cg.shared.global [%0], [%1], 16;" :: "r"(dst), "l"(src));
}
#define CP_COMMIT() asm volatile("cp.async.commit_group;" ::: "memory")
#define CP_WAIT(n)  asm volatile("cp.async.wait_group %0;" :: "n"(n) : "memory")

__device__ __forceinline__ void ldsm_x4(uint32_t (&r)[4], uint32_t addr) {
    asm volatile("ldmatrix.sync.aligned.m8n8.x4.shared.b16 {%0,%1,%2,%3}, [%4];"
                 : "=r"(r[0]), "=r"(r[1]), "=r"(r[2]), "=r"(r[3]) : "r"(addr));
}
__device__ __forceinline__ void ldsm_x4t(uint32_t (&r)[4], uint32_t addr) {
    asm volatile("ldmatrix.sync.aligned.m8n8.x4.trans.shared.b16 {%0,%1,%2,%3}, [%4];"
                 : "=r"(r[0]), "=r"(r[1]), "=r"(r[2]), "=r"(r[3]) : "r"(addr));
}
__device__ __forceinline__ void mma16816h(float (&d)[4], const uint32_t (&a)[4],
                                          uint32_t b0, uint32_t b1) {
    asm volatile("mma.sync.aligned.m16n8k16.row.col.f32.f16.f16.f32 "
                 "{%0,%1,%2,%3}, {%4,%5,%6,%7}, {%8,%9}, {%0,%1,%2,%3};"
                 : "+f"(d[0]), "+f"(d[1]), "+f"(d[2]), "+f"(d[3])
                 : "r"(a[0]), "r"(a[1]), "r"(a[2]), "r"(a[3]), "r"(b0), "r"(b1));
}
__device__ __forceinline__ uint32_t packh2(float v0, float v1) {
    __half2 t = __floats2half2_rn(v0, v1);
    return reinterpret_cast<uint32_t&>(t);
}
// raw hardware exp2 (softmax runs in log2 domain; log2e folded into Q scale)
__device__ __forceinline__ float ex2(float x) {
    float y;
    asm("ex2.approx.ftz.f32 %0, %1;" : "=f"(y) : "f"(x));
    return y;
}

// ---------------- LoRA merge -> single fp16 (all 4 layers, one launch) -----
__global__ void merge_lora2(const float* __restrict__ W0, const float* __restrict__ dW0, const float* __restrict__ dB0,
                            const float* __restrict__ W1, const float* __restrict__ dW1, const float* __restrict__ dB1,
                            const float* __restrict__ W2, const float* __restrict__ dW2, const float* __restrict__ dB2,
                            const float* __restrict__ W3, const float* __restrict__ dW3, const float* __restrict__ dB3)
{
    const int layer = blockIdx.z;
    const float* W  = (layer == 0) ? W0  : (layer == 1) ? W1  : (layer == 2) ? W2  : W3;
    const float* dW = (layer == 0) ? dW0 : (layer == 1) ? dW1 : (layer == 2) ? dW2 : dW3;
    const float* dB = (layer == 0) ? dB0 : (layer == 1) ? dB1 : (layer == 2) ? dB2 : dB3;

    int e  = blockIdx.x * 256 + threadIdx.x;
    int n  = e >> 8;
    int kq = e & 255;
    float4 s = *(const float4*)(W + (size_t)n * D_MODEL + kq * 4);
    const float4* dW4 = (const float4*)dW;
#pragma unroll
    for (int r = 0; r < RANK; r++) {
        float b  = dB[n * RANK + r];
        float4 w = dW4[r * 256 + kq];
        s.x += b * w.x; s.y += b * w.y; s.z += b * w.z; s.w += b * w.w;
    }
    __half2* p = (__half2*)(g_w2 + (size_t)(layer * D_MODEL + n) * D_MODEL + kq * 4);
    p[0] = __floats2half2_rn(s.x, s.y);
    p[1] = __floats2half2_rn(s.z, s.w);
}

// ---------------- x -> single fp16 ----------------
__global__ void prep_h(const float* __restrict__ src)
{
    int e = blockIdx.x * 256 + threadIdx.x;
    float4 s = *(const float4*)(src + (size_t)e * 4);
    __half2* p = (__half2*)(g_xh + (size_t)e * 4);
    p[0] = __floats2half2_rn(s.x, s.y);
    p[1] = __floats2half2_rn(s.z, s.w);
}

// ---------------- HMMA GEMM: C[128,128] = A @ W^T (+bias), single fp16 -----
#define GKC   64
#define GNCH  16
#define GROWB 144
#define GT_BYTES (128 * GROWB)      /* 18432 */
#define GSTAGE   (2 * GT_BYTES)     /* 36864: A | W */
#define GSTAGES  3
#define GSMEM    (GSTAGES * GSTAGE) /* 110592, 2 CTAs/SM */

__global__ void __launch_bounds__(256, 2)
gemm_hmma(const __half* __restrict__ Abase,
          int mode, int layer_base,
          const float* __restrict__ b0, const float* __restrict__ b1,
          const float* __restrict__ b2, float* __restrict__ outO)
{
    extern __shared__ __align__(128) char smem[];
    const uint32_t sb = smem_u32(smem);
    const int tid = threadIdx.x, ln = tid & 31, w = tid >> 5;
    const int wm = w & 1, wn = w >> 1;
    const int bx = blockIdx.x, by = blockIdx.y, z = blockIdx.z;
    const int layer = layer_base + z;

    const __half* Arow = Abase + (size_t)(by * 128) * D_MODEL;
    const __half* Wrow = g_w2 + ((size_t)layer * D_MODEL + bx * 128) * D_MODEL;

    float acc[4][4][4] = {};

#define GLOAD(c) do {                                                          \
        int s_ = (c) % GSTAGES;                                                \
        int x_ = (c) * GKC;                                                    \
        uint32_t bA_ = sb + s_ * GSTAGE;                                       \
        uint32_t bW_ = bA_ + GT_BYTES;                                         \
        _Pragma("unroll")                                                      \
        for (int u_ = 0; u_ < 4; u_++) {                                       \
            int e_ = tid + u_ * 256;                                           \
            int row_ = e_ >> 3, seg_ = (e_ & 7) * 16;                          \
            cpa16(bA_ + row_ * GROWB + seg_,                                   \
                  (const char*)(Arow + (size_t)row_ * D_MODEL + x_) + seg_);   \
            cpa16(bW_ + row_ * GROWB + seg_,                                   \
                  (const char*)(Wrow + (size_t)row_ * D_MODEL + x_) + seg_);   \
        }                                                                      \
        CP_COMMIT();                                                           \
    } while (0)

    GLOAD(0);
    GLOAD(1);
    for (int c = 0; c < GNCH; c++) {
        if (c + 2 < GNCH) { CP_WAIT(1); } else { CP_WAIT(0); }
        __syncthreads();
        if (c + 2 < GNCH) GLOAD(c + 2);

        const uint32_t bA = sb + (c % GSTAGES) * GSTAGE;
        const uint32_t bW = bA + GT_BYTES;
#pragma unroll
        for (int ks = 0; ks < 4; ks++) {
            const int k0 = ks * 16;
            uint32_t afr[4][4];
#pragma unroll
            for (int i = 0; i < 4; i++) {
                int row = wm * 64 + i * 16 + (ln & 15);
                ldsm_x4(afr[i], bA + row * GROWB + (k0 + ((ln >> 4) << 3)) * 2);
            }
            uint32_t bfr[2][4];
#pragma unroll
            for (int j = 0; j < 2; j++) {
                int n = wn * 32 + j * 16 + (ln & 7) + ((ln & 16) ? 8 : 0);
                ldsm_x4(bfr[j], bW + n * GROWB + (k0 + ((ln & 8) ? 8 : 0)) * 2);
            }
#pragma unroll
            for (int i = 0; i < 4; i++)
#pragma unroll
                for (int jj = 0; jj < 4; jj++)
                    mma16816h(acc[i][jj], afr[i], bfr[jj >> 1][(jj & 1) * 2],
                              bfr[jj >> 1][(jj & 1) * 2 + 1]);
        }
    }

    const float* bias = (z == 0) ? b0 : (z == 1) ? b1 : b2;
    // Q carries 1/sqrt(64) * log2(e) so softmax can run in base-2 domain
    const float qscale = (mode == 0 && z == 0) ? 0.125f * 1.4426950408889634f : 1.0f;
#pragma unroll
    for (int i = 0; i < 4; i++) {
#pragma unroll
        for (int dl = 0; dl < 2; dl++) {
            const int m = by * 128 + wm * 64 + i * 16 + (ln >> 2) + dl * 8;
#pragma unroll
            for (int jj = 0; jj < 4; jj++) {
                const int cgl = bx * 128 + wn * 32 + jj * 8 + (ln & 3) * 2;
                float v0 = (acc[i][jj][dl * 2 + 0] + bias[cgl])     * qscale;
                float v1 = (acc[i][jj][dl * 2 + 1] + bias[cgl + 1]) * qscale;
                if (mode == 0) {
                    const int h = cgl >> 6, d = cgl & 63;
                    const int b = m >> 11, n = m & 2047;
                    const size_t rowb = (size_t)(b * NHEAD + h) * SEQ + n;
                    __half* base = ((z == 0) ? g_qh : (z == 1) ? g_kh : g_vh)
                                   + rowb * 64 + d;
                    *(__half2*)base = __floats2half2_rn(v0, v1);
                } else {
                    float2 o; o.x = v0; o.y = v1;
                    *(float2*)(outO + (size_t)m * D_MODEL + cgl) = o;
                }
            }
        }
    }
}

// ---------------- Flash attention: FA2, single fp16, base-2 softmax --------
// K/V loaded in 128-row super-tiles (2 compute halves per barrier).
#define KROWB 144                         /* 64 fp16 + 8 pad */
#define KHALF (64 * KROWB)                /* 9216 per 64-row half */
#define KTILE2 (2 * KHALF)                /* 18432 per 128-row super-tile */
#define QROWS 128
#define SM_Q   0
#define QBYTES (QROWS * KROWB)            /* 18432 */
#define SM_K0  QBYTES
#define SM_V0  (SM_K0 + 2 * KTILE2)       /* +36864 */
#define ATT_SMEM (SM_V0 + 2 * KTILE2)     /* 92160, 2 CTAs/SM */
#define NT2 (SEQ / 128)                   /* 16 super-tiles */

__global__ void __launch_bounds__(256, 2)
flash_hmma()
{
    extern __shared__ __align__(128) char smem[];
    const uint32_t sb = smem_u32(smem);
    const int tid = threadIdx.x, ln = tid & 31, w = tid >> 5;
    const int qt = blockIdx.x, bh = blockIdx.y;

    const __half* qg = g_qh + ((size_t)bh * SEQ + qt * QROWS) * 64;
    const __half* kg = g_kh + (size_t)bh * SEQ * 64;
    const __half* vg = g_vh + (size_t)bh * SEQ * 64;

#pragma unroll
    for (int u = 0; u < 4; u++) {
        int e = tid + u * 256;
        int row = e >> 3, seg = (e & 7) * 16;
        cpa16(sb + SM_Q + row * KROWB + seg, (const char*)(qg + (size_t)row * 64) + seg);
    }
    CP_COMMIT();

// load a 128-row super-tile of K and V
#define ATT_LOAD(t) do {                                                       \
        int buf_ = (t) & 1;                                                    \
        const __half* kb_ = kg + (size_t)(t) * 128 * 64;                       \
        const __half* vb_ = vg + (size_t)(t) * 128 * 64;                       \
        uint32_t kd_ = sb + SM_K0 + buf_ * KTILE2;                             \
        uint32_t vd_ = sb + SM_V0 + buf_ * KTILE2;                             \
        _Pragma("unroll")                                                      \
        for (int u_ = 0; u_ < 4; u_++) {                                       \
            int e_ = tid + u_ * 256;                                           \
            int row_ = e_ >> 3, seg_ = (e_ & 7) * 16;                          \
            cpa16(kd_ + row_ * KROWB + seg_,                                   \
                  (const char*)(kb_ + (size_t)row_ * 64) + seg_);              \
            cpa16(vd_ + row_ * KROWB + seg_,                                   \
                  (const char*)(vb_ + (size_t)row_ * 64) + seg_);              \
        }                                                                      \
        CP_COMMIT();                                                           \
    } while (0)

    ATT_LOAD(0);
    CP_WAIT(0);
    __syncthreads();

    const uint32_t qaddr = sb + SM_Q + (w * 16 + (ln & 15)) * KROWB + (((ln >> 4) << 3)) * 2;
    uint32_t qf[4][4];
#pragma unroll
    for (int s = 0; s < 4; s++)
        ldsm_x4(qf[s], qaddr + (s * 16) * 2);

    const int krow8  = (ln & 7) + ((ln & 16) ? 8 : 0);
    const int kcol8  = (ln & 8) ? 8 : 0;
    const int vrow16 = ln & 15;
    const int vcol8  = (ln & 16) ? 8 : 0;

    float m0 = -1e30f, m1 = -1e30f, l0 = 0.f, l1 = 0.f;
    float acco[8][4] = {};

    for (int kt = 0; kt < NT2; kt++) {
        if (kt > 0) { CP_WAIT(0); __syncthreads(); }
        if (kt + 1 < NT2) ATT_LOAD(kt + 1);

#pragma unroll
        for (int half = 0; half < 2; half++) {
            const uint32_t bK = sb + SM_K0 + (kt & 1) * KTILE2 + half * KHALF;
            const uint32_t bV = sb + SM_V0 + (kt & 1) * KTILE2 + half * KHALF;

            // ---- S = Q K^T ----
            float accs[8][4] = {};
#pragma unroll
            for (int ks = 0; ks < 4; ks++) {
#pragma unroll
                for (int nbp = 0; nbp < 4; nbp++) {
                    uint32_t kb[4];
                    ldsm_x4(kb, bK + (nbp * 16 + krow8) * KROWB + (ks * 16 + kcol8) * 2);
                    mma16816h(accs[2 * nbp],     qf[ks], kb[0], kb[1]);
                    mma16816h(accs[2 * nbp + 1], qf[ks], kb[2], kb[3]);
                }
            }

            // ---- warp-local online softmax (base-2 domain) ----
            float mx0 = -1e30f, mx1 = -1e30f;
#pragma unroll
            for (int jj = 0; jj < 8; jj++) {
                mx0 = fmaxf(mx0, fmaxf(accs[jj][0], accs[jj][1]));
                mx1 = fmaxf(mx1, fmaxf(accs[jj][2], accs[jj][3]));
            }
            mx0 = fmaxf(mx0, __shfl_xor_sync(0xffffffffu, mx0, 1));
            mx0 = fmaxf(mx0, __shfl_xor_sync(0xffffffffu, mx0, 2));
            mx1 = fmaxf(mx1, __shfl_xor_sync(0xffffffffu, mx1, 1));
            mx1 = fmaxf(mx1, __shfl_xor_sync(0xffffffffu, mx1, 2));
            const float mn0 = fmaxf(m0, mx0), mn1 = fmaxf(m1, mx1);
            const float a0 = ex2(m0 - mn0), a1 = ex2(m1 - mn1);
            m0 = mn0; m1 = mn1;

            float s0 = 0.f, s1 = 0.f;
#pragma unroll
            for (int jj = 0; jj < 8; jj++) {
                accs[jj][0] = ex2(accs[jj][0] - mn0);
                accs[jj][1] = ex2(accs[jj][1] - mn0);
                accs[jj][2] = ex2(accs[jj][2] - mn1);
                accs[jj][3] = ex2(accs[jj][3] - mn1);
                s0 += accs[jj][0] + accs[jj][1];
                s1 += accs[jj][2] + accs[jj][3];
            }
            s0 += __shfl_xor_sync(0xffffffffu, s0, 1);
            s0 += __shfl_xor_sync(0xffffffffu, s0, 2);
            s1 += __shfl_xor_sync(0xffffffffu, s1, 1);
            s1 += __shfl_xor_sync(0xffffffffu, s1, 2);
            l0 = l0 * a0 + s0;
            l1 = l1 * a1 + s1;
#pragma unroll
            for (int jj = 0; jj < 8; jj++) {
                acco[jj][0] *= a0; acco[jj][1] *= a0;
                acco[jj][2] *= a1; acco[jj][3] *= a1;
            }

            // ---- O += P @ V ----
#pragma unroll
            for (int ks = 0; ks < 4; ks++) {
                uint32_t phi[4];
                phi[0] = packh2(accs[2 * ks][0],     accs[2 * ks][1]);
                phi[1] = packh2(accs[2 * ks][2],     accs[2 * ks][3]);
                phi[2] = packh2(accs[2 * ks + 1][0], accs[2 * ks + 1][1]);
                phi[3] = packh2(accs[2 * ks + 1][2], accs[2 * ks + 1][3]);
#pragma unroll
                for (int nbp = 0; nbp < 4; nbp++) {
                    uint32_t vb[4];
                    ldsm_x4t(vb, bV + (ks * 16 + vrow16) * KROWB + (nbp * 16 + vcol8) * 2);
                    mma16816h(acco[2 * nbp],     phi, vb[0], vb[1]);
                    mma16816h(acco[2 * nbp + 1], phi, vb[2], vb[3]);
                }
            }
        }
    }

    // ---- epilogue: normalize, write single fp16 to g_ao ----
    const int b = bh >> 4, h = bh & 15;
    const int q = ln >> 2, t4 = ln & 3;
    const float inv0 = 1.f / l0, inv1 = 1.f / l1;
    const size_t n0 = (size_t)qt * QROWS + w * 16 + q;
    const size_t mg0 = (size_t)b * SEQ + n0;
    const size_t mg1 = mg0 + 8;
#pragma unroll
    for (int jj = 0; jj < 8; jj++) {
        const int col = h * 64 + jj * 8 + t4 * 2;
        *(uint32_t*)(g_ao + mg0 * D_MODEL + col) =
            packh2(acco[jj][0] * inv0, acco[jj][1] * inv0);
        *(uint32_t*)(g_ao + mg1 * D_MODEL + col) =
            packh2(acco[jj][2] * inv1, acco[jj][3] * inv1);
    }
}

// ---------------- launch --------------------------------------------------
extern "C" void kernel_launch(void* const* d_in, const int* in_sizes, int n_in,
                              void* d_out, int out_size)
{
    const float* x = (const float*)d_in[0];
    const float* W [4] = {(const float*)d_in[1],  (const float*)d_in[5],
                          (const float*)d_in[9],  (const float*)d_in[13]};
    const float* B [4] = {(const float*)d_in[2],  (const float*)d_in[6],
                          (const float*)d_in[10], (const float*)d_in[14]};
    const float* dW[4] = {(const float*)d_in[3],  (const float*)d_in[7],
                          (const float*)d_in[11], (const float*)d_in[15]};
    const float* dB[4] = {(const float*)d_in[4],  (const float*)d_in[8],
                          (const float*)d_in[12], (const float*)d_in[16]};
    float* out = (float*)d_out;

    void *pxh, *pao;
    cudaGetSymbolAddress(&pxh, g_xh);
    cudaGetSymbolAddress(&pao, g_ao);

    // 1) LoRA merge -> single fp16 (one launch, 4 layers)
    {
        dim3 grid(1024, 1, 4);
        merge_lora2<<<grid, 256>>>(W[0], dW[0], dB[0], W[1], dW[1], dB[1],
                                   W[2], dW[2], dB[2], W[3], dW[3], dB[3]);
    }

    // 2) x -> fp16
    prep_h<<<4096, 256>>>(x);

    // 3) QKV projections
    cudaFuncSetAttribute(gemm_hmma, cudaFuncAttributeMaxDynamicSharedMemorySize, GSMEM);
    {
        dim3 grid(D_MODEL / 128, M_TOTAL / 128, 3);
        gemm_hmma<<<grid, 256, GSMEM>>>((const __half*)pxh, 0, 0,
                                        B[0], B[1], B[2], nullptr);
    }

    // 4) flash attention -> g_ao
    cudaFuncSetAttribute(flash_hmma, cudaFuncAttributeMaxDynamicSharedMemorySize, ATT_SMEM);
    {
        dim3 grid(SEQ / QROWS, BATCH * NHEAD);
        flash_hmma<<<grid, 256, ATT_SMEM>>>();
    }

    // 5) O projection -> d_out
    {
        dim3 grid(D_MODEL / 128, M_TOTAL / 128, 1);
        gemm_hmma<<<grid, 256, GSMEM>>>((const __half*)pao, 1, 3,
                                        B[3], B[3], B[3], out);
    }
}

// round 11
// speedup vs baseline: 9.3789x; 1.0059x over previous
#include <cuda_runtime.h>
#include <cuda_fp16.h>
#include <cstdint>

#define D_MODEL 1024
#define NHEAD   16
#define DHEAD   64
#define SEQ     2048
#define BATCH   2
#define M_TOTAL (BATCH * SEQ)   /* 4096 */
#define RANK    32

// ---------------- device scratch (all single fp16) ----------------
__device__ __half g_xh [(size_t)M_TOTAL * D_MODEL];         // x fp16
__device__ __half g_w2 [(size_t)4 * D_MODEL * D_MODEL];     // merged W fp16
__device__ __half g_ao [(size_t)M_TOTAL * D_MODEL];         // attn out fp16
__device__ __half g_qh [(size_t)BATCH * NHEAD * SEQ * 64];  // Q scaled by 0.125*log2e
__device__ __half g_kh [(size_t)BATCH * NHEAD * SEQ * 64];
__device__ __half g_vh [(size_t)BATCH * NHEAD * SEQ * 64];

// ---------------- PTX helpers (baseline PTX only) ----------------
__device__ __forceinline__ uint32_t smem_u32(const void* p) {
    uint32_t a;
    asm("{ .reg .u64 t; cvta.to.shared.u64 t, %1; cvt.u32.u64 %0, t; }" : "=r"(a) : "l"(p));
    return a;
}
__device__ __forceinline__ void cpa16(uint32_t dst, const void* src) {
    asm volatile("cp.async.cg.shared.global [%0], [%1], 16;" :: "r"(dst), "l"(src));
}
#define CP_COMMIT() asm volatile("cp.async.commit_group;" ::: "memory")
#define CP_WAIT(n)  asm volatile("cp.async.wait_group %0;" :: "n"(n) : "memory")

__device__ __forceinline__ void ldsm_x4(uint32_t (&r)[4], uint32_t addr) {
    asm volatile("ldmatrix.sync.aligned.m8n8.x4.shared.b16 {%0,%1,%2,%3}, [%4];"
                 : "=r"(r[0]), "=r"(r[1]), "=r"(r[2]), "=r"(r[3]) : "r"(addr));
}
__device__ __forceinline__ void ldsm_x4t(uint32_t (&r)[4], uint32_t addr) {
    asm volatile("ldmatrix.sync.aligned.m8n8.x4.trans.shared.b16 {%0,%1,%2,%3}, [%4];"
                 : "=r"(r[0]), "=r"(r[1]), "=r"(r[2]), "=r"(r[3]) : "r"(addr));
}
__device__ __forceinline__ void mma16816h(float (&d)[4], const uint32_t (&a)[4],
                                          uint32_t b0, uint32_t b1) {
    asm volatile("mma.sync.aligned.m16n8k16.row.col.f32.f16.f16.f32 "
                 "{%0,%1,%2,%3}, {%4,%5,%6,%7}, {%8,%9}, {%0,%1,%2,%3};"
                 : "+f"(d[0]), "+f"(d[1]), "+f"(d[2]), "+f"(d[3])
                 : "r"(a[0]), "r"(a[1]), "r"(a[2]), "r"(a[3]), "r"(b0), "r"(b1));
}
__device__ __forceinline__ uint32_t packh2(float v0, float v1) {
    __half2 t = __floats2half2_rn(v0, v1);
    return reinterpret_cast<uint32_t&>(t);
}
__device__ __forceinline__ float ex2(float x) {
    float y;
    asm("ex2.approx.ftz.f32 %0, %1;" : "=f"(y) : "f"(x));
    return y;
}

// ---------------- LoRA merge -> single fp16 (all 4 layers, one launch) -----
__global__ void merge_lora2(const float* __restrict__ W0, const float* __restrict__ dW0, const float* __restrict__ dB0,
                            const float* __restrict__ W1, const float* __restrict__ dW1, const float* __restrict__ dB1,
                            const float* __restrict__ W2, const float* __restrict__ dW2, const float* __restrict__ dB2,
                            const float* __restrict__ W3, const float* __restrict__ dW3, const float* __restrict__ dB3)
{
    const int layer = blockIdx.z;
    const float* W  = (layer == 0) ? W0  : (layer == 1) ? W1  : (layer == 2) ? W2  : W3;
    const float* dW = (layer == 0) ? dW0 : (layer == 1) ? dW1 : (layer == 2) ? dW2 : dW3;
    const float* dB = (layer == 0) ? dB0 : (layer == 1) ? dB1 : (layer == 2) ? dB2 : dB3;

    int e  = blockIdx.x * 256 + threadIdx.x;
    int n  = e >> 8;
    int kq = e & 255;
    float4 s = *(const float4*)(W + (size_t)n * D_MODEL + kq * 4);
    const float4* dW4 = (const float4*)dW;
#pragma unroll
    for (int r = 0; r < RANK; r++) {
        float b  = dB[n * RANK + r];
        float4 w = dW4[r * 256 + kq];
        s.x += b * w.x; s.y += b * w.y; s.z += b * w.z; s.w += b * w.w;
    }
    __half2* p = (__half2*)(g_w2 + (size_t)(layer * D_MODEL + n) * D_MODEL + kq * 4);
    p[0] = __floats2half2_rn(s.x, s.y);
    p[1] = __floats2half2_rn(s.z, s.w);
}

// ---------------- x -> single fp16 ----------------
__global__ void prep_h(const float* __restrict__ src)
{
    int e = blockIdx.x * 256 + threadIdx.x;
    float4 s = *(const float4*)(src + (size_t)e * 4);
    __half2* p = (__half2*)(g_xh + (size_t)e * 4);
    p[0] = __floats2half2_rn(s.x, s.y);
    p[1] = __floats2half2_rn(s.z, s.w);
}

// ---------------- HMMA GEMM: C[128,128] = A @ W^T (+bias), single fp16 -----
#define GKC   64
#define GNCH  16
#define GROWB 144
#define GT_BYTES (128 * GROWB)      /* 18432 */
#define GSTAGE   (2 * GT_BYTES)     /* 36864: A | W */
#define GSTAGES  3
#define GSMEM    (GSTAGES * GSTAGE) /* 110592, 2 CTAs/SM */

__global__ void __launch_bounds__(256, 2)
gemm_hmma(const __half* __restrict__ Abase,
          int mode, int layer_base,
          const float* __restrict__ b0, const float* __restrict__ b1,
          const float* __restrict__ b2, float* __restrict__ outO)
{
    extern __shared__ __align__(128) char smem[];
    const uint32_t sb = smem_u32(smem);
    const int tid = threadIdx.x, ln = tid & 31, w = tid >> 5;
    const int wm = w & 1, wn = w >> 1;
    const int bx = blockIdx.x, by = blockIdx.y, z = blockIdx.z;
    const int layer = layer_base + z;

    const __half* Arow = Abase + (size_t)(by * 128) * D_MODEL;
    const __half* Wrow = g_w2 + ((size_t)layer * D_MODEL + bx * 128) * D_MODEL;

    float acc[4][4][4] = {};

#define GLOAD(c) do {                                                          \
        int s_ = (c) % GSTAGES;                                                \
        int x_ = (c) * GKC;                                                    \
        uint32_t bA_ = sb + s_ * GSTAGE;                                       \
        uint32_t bW_ = bA_ + GT_BYTES;                                         \
        _Pragma("unroll")                                                      \
        for (int u_ = 0; u_ < 4; u_++) {                                       \
            int e_ = tid + u_ * 256;                                           \
            int row_ = e_ >> 3, seg_ = (e_ & 7) * 16;                          \
            cpa16(bA_ + row_ * GROWB + seg_,                                   \
                  (const char*)(Arow + (size_t)row_ * D_MODEL + x_) + seg_);   \
            cpa16(bW_ + row_ * GROWB + seg_,                                   \
                  (const char*)(Wrow + (size_t)row_ * D_MODEL + x_) + seg_);   \
        }                                                                      \
        CP_COMMIT();                                                           \
    } while (0)

    GLOAD(0);
    GLOAD(1);
    for (int c = 0; c < GNCH; c++) {
        if (c + 2 < GNCH) { CP_WAIT(1); } else { CP_WAIT(0); }
        __syncthreads();
        if (c + 2 < GNCH) GLOAD(c + 2);

        const uint32_t bA = sb + (c % GSTAGES) * GSTAGE;
        const uint32_t bW = bA + GT_BYTES;
#pragma unroll
        for (int ks = 0; ks < 4; ks++) {
            const int k0 = ks * 16;
            uint32_t afr[4][4];
#pragma unroll
            for (int i = 0; i < 4; i++) {
                int row = wm * 64 + i * 16 + (ln & 15);
                ldsm_x4(afr[i], bA + row * GROWB + (k0 + ((ln >> 4) << 3)) * 2);
            }
            uint32_t bfr[2][4];
#pragma unroll
            for (int j = 0; j < 2; j++) {
                int n = wn * 32 + j * 16 + (ln & 7) + ((ln & 16) ? 8 : 0);
                ldsm_x4(bfr[j], bW + n * GROWB + (k0 + ((ln & 8) ? 8 : 0)) * 2);
            }
#pragma unroll
            for (int i = 0; i < 4; i++)
#pragma unroll
                for (int jj = 0; jj < 4; jj++)
                    mma16816h(acc[i][jj], afr[i], bfr[jj >> 1][(jj & 1) * 2],
                              bfr[jj >> 1][(jj & 1) * 2 + 1]);
        }
    }

    const float* bias = (z == 0) ? b0 : (z == 1) ? b1 : b2;
    const float qscale = (mode == 0 && z == 0) ? 0.125f * 1.4426950408889634f : 1.0f;
#pragma unroll
    for (int i = 0; i < 4; i++) {
#pragma unroll
        for (int dl = 0; dl < 2; dl++) {
            const int m = by * 128 + wm * 64 + i * 16 + (ln >> 2) + dl * 8;
#pragma unroll
            for (int jj = 0; jj < 4; jj++) {
                const int cgl = bx * 128 + wn * 32 + jj * 8 + (ln & 3) * 2;
                float v0 = (acc[i][jj][dl * 2 + 0] + bias[cgl])     * qscale;
                float v1 = (acc[i][jj][dl * 2 + 1] + bias[cgl + 1]) * qscale;
                if (mode == 0) {
                    const int h = cgl >> 6, d = cgl & 63;
                    const int b = m >> 11, n = m & 2047;
                    const size_t rowb = (size_t)(b * NHEAD + h) * SEQ + n;
                    __half* base = ((z == 0) ? g_qh : (z == 1) ? g_kh : g_vh)
                                   + rowb * 64 + d;
                    *(__half2*)base = __floats2half2_rn(v0, v1);
                } else {
                    float2 o; o.x = v0; o.y = v1;
                    *(float2*)(outO + (size_t)m * D_MODEL + cgl) = o;
                }
            }
        }
    }
}

// ---------------- Flash attention: 4-deep 64-row ring, fused exp/PV --------
#define KROWB 144                         /* 64 fp16 + 8 pad */
#define KTILEB (64 * KROWB)               /* 9216 */
#define NBUF  4
#define QROWS 128
#define SM_Q   0
#define QBYTES (QROWS * KROWB)            /* 18432 */
#define SM_K0  QBYTES
#define SM_V0  (SM_K0 + NBUF * KTILEB)    /* +36864 */
#define ATT_SMEM (SM_V0 + NBUF * KTILEB)  /* 92160, 2 CTAs/SM */
#define NT (SEQ / 64)                     /* 32 tiles */

__global__ void __launch_bounds__(256, 2)
flash_hmma()
{
    extern __shared__ __align__(128) char smem[];
    const uint32_t sb = smem_u32(smem);
    const int tid = threadIdx.x, ln = tid & 31, w = tid >> 5;
    const int qt = blockIdx.x, bh = blockIdx.y;

    const __half* qg = g_qh + ((size_t)bh * SEQ + qt * QROWS) * 64;
    const __half* kg = g_kh + (size_t)bh * SEQ * 64;
    const __half* vg = g_vh + (size_t)bh * SEQ * 64;

    // Q tile (commit group 0)
#pragma unroll
    for (int u = 0; u < 4; u++) {
        int e = tid + u * 256;
        int row = e >> 3, seg = (e & 7) * 16;
        cpa16(sb + SM_Q + row * KROWB + seg, (const char*)(qg + (size_t)row * 64) + seg);
    }
    CP_COMMIT();

// load a 64-row K+V tile into ring slot t&3
#define ATT_LOAD(t) do {                                                       \
        int buf_ = (t) & 3;                                                    \
        const __half* kb_ = kg + (size_t)(t) * 64 * 64;                        \
        const __half* vb_ = vg + (size_t)(t) * 64 * 64;                        \
        uint32_t kd_ = sb + SM_K0 + buf_ * KTILEB;                             \
        uint32_t vd_ = sb + SM_V0 + buf_ * KTILEB;                             \
        _Pragma("unroll")                                                      \
        for (int u_ = 0; u_ < 2; u_++) {                                       \
            int e_ = tid + u_ * 256;                                           \
            int row_ = e_ >> 3, seg_ = (e_ & 7) * 16;                          \
            cpa16(kd_ + row_ * KROWB + seg_,                                   \
                  (const char*)(kb_ + (size_t)row_ * 64) + seg_);              \
            cpa16(vd_ + row_ * KROWB + seg_,                                   \
                  (const char*)(vb_ + (size_t)row_ * 64) + seg_);              \
        }                                                                      \
        CP_COMMIT();                                                           \
    } while (0)

    ATT_LOAD(0);
    ATT_LOAD(1);
    ATT_LOAD(2);

    const uint32_t qaddr = sb + SM_Q + (w * 16 + (ln & 15)) * KROWB + (((ln >> 4) << 3)) * 2;
    const int krow8  = (ln & 7) + ((ln & 16) ? 8 : 0);
    const int kcol8  = (ln & 8) ? 8 : 0;
    const int vrow16 = ln & 15;
    const int vcol8  = (ln & 16) ? 8 : 0;

    uint32_t qf[4][4];
    bool qloaded = false;

    float m0 = -1e30f, m1 = -1e30f, l0 = 0.f, l1 = 0.f;
    float acco[8][4] = {};

#pragma unroll 1
    for (int i = 0; i < NT; i++) {
        // tile i ready; ring slot (i+3)&3 reusable after this barrier
        if (i < NT - 2)      CP_WAIT(2);
        else                 CP_WAIT(0);
        __syncthreads();
        if (i + 3 < NT) ATT_LOAD(i + 3);

        if (!qloaded) {       // first iter: Q group completed as well
#pragma unroll
            for (int s = 0; s < 4; s++)
                ldsm_x4(qf[s], qaddr + (s * 16) * 2);
            qloaded = true;
        }

        const uint32_t bK = sb + SM_K0 + (i & 3) * KTILEB;
        const uint32_t bV = sb + SM_V0 + (i & 3) * KTILEB;

        // ---- S burst right after the barrier: fills the tensor pipe ----
        float accs[8][4] = {};
#pragma unroll
        for (int ks = 0; ks < 4; ks++) {
#pragma unroll
            for (int nbp = 0; nbp < 4; nbp++) {
                uint32_t kb[4];
                ldsm_x4(kb, bK + (nbp * 16 + krow8) * KROWB + (ks * 16 + kcol8) * 2);
                mma16816h(accs[2 * nbp],     qf[ks], kb[0], kb[1]);
                mma16816h(accs[2 * nbp + 1], qf[ks], kb[2], kb[3]);
            }
        }

        // ---- row max + rescale (short chain) ----
        float mx0 = -1e30f, mx1 = -1e30f;
#pragma unroll
        for (int jj = 0; jj < 8; jj++) {
            mx0 = fmaxf(mx0, fmaxf(accs[jj][0], accs[jj][1]));
            mx1 = fmaxf(mx1, fmaxf(accs[jj][2], accs[jj][3]));
        }
        mx0 = fmaxf(mx0, __shfl_xor_sync(0xffffffffu, mx0, 1));
        mx0 = fmaxf(mx0, __shfl_xor_sync(0xffffffffu, mx0, 2));
        mx1 = fmaxf(mx1, __shfl_xor_sync(0xffffffffu, mx1, 1));
        mx1 = fmaxf(mx1, __shfl_xor_sync(0xffffffffu, mx1, 2));
        const float mn0 = fmaxf(m0, mx0), mn1 = fmaxf(m1, mx1);
        const float a0 = ex2(m0 - mn0), a1 = ex2(m1 - mn1);
        m0 = mn0; m1 = mn1;
        l0 *= a0; l1 *= a1;
#pragma unroll
        for (int jj = 0; jj < 8; jj++) {
            acco[jj][0] *= a0; acco[jj][1] *= a0;
            acco[jj][2] *= a1; acco[jj][3] *= a1;
        }

        // ---- fused exp -> pack -> PV: MUFU chunks interleaved with mma ----
        float s0 = 0.f, s1 = 0.f;
#pragma unroll
        for (int ks = 0; ks < 4; ks++) {
            float e00 = ex2(accs[2 * ks][0] - m0);
            float e01 = ex2(accs[2 * ks][1] - m0);
            float e02 = ex2(accs[2 * ks][2] - m1);
            float e03 = ex2(accs[2 * ks][3] - m1);
            float e10 = ex2(accs[2 * ks + 1][0] - m0);
            float e11 = ex2(accs[2 * ks + 1][1] - m0);
            float e12 = ex2(accs[2 * ks + 1][2] - m1);
            float e13 = ex2(accs[2 * ks + 1][3] - m1);
            s0 += e00 + e01 + e10 + e11;
            s1 += e02 + e03 + e12 + e13;
            uint32_t phi[4];
            phi[0] = packh2(e00, e01);
            phi[1] = packh2(e02, e03);
            phi[2] = packh2(e10, e11);
            phi[3] = packh2(e12, e13);
#pragma unroll
            for (int nbp = 0; nbp < 4; nbp++) {
                uint32_t vb[4];
                ldsm_x4t(vb, bV + (ks * 16 + vrow16) * KROWB + (nbp * 16 + vcol8) * 2);
                mma16816h(acco[2 * nbp],     phi, vb[0], vb[1]);
                mma16816h(acco[2 * nbp + 1], phi, vb[2], vb[3]);
            }
        }
        s0 += __shfl_xor_sync(0xffffffffu, s0, 1);
        s0 += __shfl_xor_sync(0xffffffffu, s0, 2);
        s1 += __shfl_xor_sync(0xffffffffu, s1, 1);
        s1 += __shfl_xor_sync(0xffffffffu, s1, 2);
        l0 += s0;
        l1 += s1;
    }

    // ---- epilogue: normalize, write single fp16 to g_ao ----
    const int b = bh >> 4, h = bh & 15;
    const int q = ln >> 2, t4 = ln & 3;
    const float inv0 = 1.f / l0, inv1 = 1.f / l1;
    const size_t n0 = (size_t)qt * QROWS + w * 16 + q;
    const size_t mg0 = (size_t)b * SEQ + n0;
    const size_t mg1 = mg0 + 8;
#pragma unroll
    for (int jj = 0; jj < 8; jj++) {
        const int col = h * 64 + jj * 8 + t4 * 2;
        *(uint32_t*)(g_ao + mg0 * D_MODEL + col) =
            packh2(acco[jj][0] * inv0, acco[jj][1] * inv0);
        *(uint32_t*)(g_ao + mg1 * D_MODEL + col) =
            packh2(acco[jj][2] * inv1, acco[jj][3] * inv1);
    }
}

// ---------------- launch --------------------------------------------------
extern "C" void kernel_launch(void* const* d_in, const int* in_sizes, int n_in,
                              void* d_out, int out_size)
{
    const float* x = (const float*)d_in[0];
    const float* W [4] = {(const float*)d_in[1],  (const float*)d_in[5],
                          (const float*)d_in[9],  (const float*)d_in[13]};
    const float* B [4] = {(const float*)d_in[2],  (const float*)d_in[6],
                          (const float*)d_in[10], (const float*)d_in[14]};
    const float* dW[4] = {(const float*)d_in[3],  (const float*)d_in[7],
                          (const float*)d_in[11], (const float*)d_in[15]};
    const float* dB[4] = {(const float*)d_in[4],  (const float*)d_in[8],
                          (const float*)d_in[12], (const float*)d_in[16]};
    float* out = (float*)d_out;

    void *pxh, *pao;
    cudaGetSymbolAddress(&pxh, g_xh);
    cudaGetSymbolAddress(&pao, g_ao);

    // 1) LoRA merge -> single fp16
    {
        dim3 grid(1024, 1, 4);
        merge_lora2<<<grid, 256>>>(W[0], dW[0], dB[0], W[1], dW[1], dB[1],
                                   W[2], dW[2], dB[2], W[3], dW[3], dB[3]);
    }

    // 2) x -> fp16
    prep_h<<<4096, 256>>>(x);

    // 3) QKV projections
    cudaFuncSetAttribute(gemm_hmma, cudaFuncAttributeMaxDynamicSharedMemorySize, GSMEM);
    {
        dim3 grid(D_MODEL / 128, M_TOTAL / 128, 3);
        gemm_hmma<<<grid, 256, GSMEM>>>((const __half*)pxh, 0, 0,
                                        B[0], B[1], B[2], nullptr);
    }

    // 4) flash attention -> g_ao
    cudaFuncSetAttribute(flash_hmma, cudaFuncAttributeMaxDynamicSharedMemorySize, ATT_SMEM);
    {
        dim3 grid(SEQ / QROWS, BATCH * NHEAD);
        flash_hmma<<<grid, 256, ATT_SMEM>>>();
    }

    // 5) O projection -> d_out
    {
        dim3 grid(D_MODEL / 128, M_TOTAL / 128, 1);
        gemm_hmma<<<grid, 256, GSMEM>>>((const __half*)pao, 1, 3,
                                        B[3], B[3], B[3], out);
    }
}

// round 12
// speedup vs baseline: 9.3946x; 1.0017x over previous
#include <cuda_runtime.h>
#include <cuda_fp16.h>
#include <cstdint>

#define D_MODEL 1024
#define NHEAD   16
#define DHEAD   64
#define SEQ     2048
#define BATCH   2
#define M_TOTAL (BATCH * SEQ)   /* 4096 */
#define RANK    32

// ---------------- device scratch (all single fp16) ----------------
__device__ __half g_xh [(size_t)M_TOTAL * D_MODEL];         // x fp16
__device__ __half g_w2 [(size_t)4 * D_MODEL * D_MODEL];     // merged W fp16
__device__ __half g_ao [(size_t)M_TOTAL * D_MODEL];         // attn out fp16
__device__ __half g_qh [(size_t)BATCH * NHEAD * SEQ * 64];  // Q scaled by 0.125*log2e
__device__ __half g_kh [(size_t)BATCH * NHEAD * SEQ * 64];
__device__ __half g_vh [(size_t)BATCH * NHEAD * SEQ * 64];

// ---------------- PTX helpers (baseline PTX only) ----------------
__device__ __forceinline__ uint32_t smem_u32(const void* p) {
    uint32_t a;
    asm("{ .reg .u64 t; cvta.to.shared.u64 t, %1; cvt.u32.u64 %0, t; }" : "=r"(a) : "l"(p));
    return a;
}
__device__ __forceinline__ void cpa16(uint32_t dst, const void* src) {
    asm volatile("cp.async.cg.shared.global [%0], [%1], 16;" :: "r"(dst), "l"(src));
}
#define CP_COMMIT() asm volatile("cp.async.commit_group;" ::: "memory")
#define CP_WAIT(n)  asm volatile("cp.async.wait_group %0;" :: "n"(n) : "memory")

__device__ __forceinline__ void ldsm_x4(uint32_t (&r)[4], uint32_t addr) {
    asm volatile("ldmatrix.sync.aligned.m8n8.x4.shared.b16 {%0,%1,%2,%3}, [%4];"
                 : "=r"(r[0]), "=r"(r[1]), "=r"(r[2]), "=r"(r[3]) : "r"(addr));
}
__device__ __forceinline__ void ldsm_x4t(uint32_t (&r)[4], uint32_t addr) {
    asm volatile("ldmatrix.sync.aligned.m8n8.x4.trans.shared.b16 {%0,%1,%2,%3}, [%4];"
                 : "=r"(r[0]), "=r"(r[1]), "=r"(r[2]), "=r"(r[3]) : "r"(addr));
}
__device__ __forceinline__ void mma16816h(float (&d)[4], const uint32_t (&a)[4],
                                          uint32_t b0, uint32_t b1) {
    asm volatile("mma.sync.aligned.m16n8k16.row.col.f32.f16.f16.f32 "
                 "{%0,%1,%2,%3}, {%4,%5,%6,%7}, {%8,%9}, {%0,%1,%2,%3};"
                 : "+f"(d[0]), "+f"(d[1]), "+f"(d[2]), "+f"(d[3])
                 : "r"(a[0]), "r"(a[1]), "r"(a[2]), "r"(a[3]), "r"(b0), "r"(b1));
}
__device__ __forceinline__ uint32_t packh2(float v0, float v1) {
    __half2 t = __floats2half2_rn(v0, v1);
    return reinterpret_cast<uint32_t&>(t);
}
__device__ __forceinline__ float ex2(float x) {
    float y;
    asm("ex2.approx.ftz.f32 %0, %1;" : "=f"(y) : "f"(x));
    return y;
}
__device__ __forceinline__ uint32_t hmax2(uint32_t a, uint32_t b) {
    uint32_t d;
    asm("max.f16x2 %0, %1, %2;" : "=r"(d) : "r"(a), "r"(b));
    return d;
}

// ---------------- fused: LoRA merge (4 layers) + x->fp16, one launch -------
// blocks [0,4096): convert x; blocks [4096,8192): merge layer (b-4096)>>10
__global__ void merge_prep(const float* __restrict__ x,
                           const float* __restrict__ W0, const float* __restrict__ dW0, const float* __restrict__ dB0,
                           const float* __restrict__ W1, const float* __restrict__ dW1, const float* __restrict__ dB1,
                           const float* __restrict__ W2, const float* __restrict__ dW2, const float* __restrict__ dB2,
                           const float* __restrict__ W3, const float* __restrict__ dW3, const float* __restrict__ dB3)
{
    const int blk = blockIdx.x;
    if (blk < 4096) {
        int e = blk * 256 + threadIdx.x;
        float4 s = *(const float4*)(x + (size_t)e * 4);
        __half2* p = (__half2*)(g_xh + (size_t)e * 4);
        p[0] = __floats2half2_rn(s.x, s.y);
        p[1] = __floats2half2_rn(s.z, s.w);
        return;
    }
    const int bb = blk - 4096;
    const int layer = bb >> 10;
    const float* W  = (layer == 0) ? W0  : (layer == 1) ? W1  : (layer == 2) ? W2  : W3;
    const float* dW = (layer == 0) ? dW0 : (layer == 1) ? dW1 : (layer == 2) ? dW2 : dW3;
    const float* dB = (layer == 0) ? dB0 : (layer == 1) ? dB1 : (layer == 2) ? dB2 : dB3;

    int e  = (bb & 1023) * 256 + threadIdx.x;
    int n  = e >> 8;
    int kq = e & 255;
    float4 s = *(const float4*)(W + (size_t)n * D_MODEL + kq * 4);
    const float4* dW4 = (const float4*)dW;
#pragma unroll
    for (int r = 0; r < RANK; r++) {
        float b  = dB[n * RANK + r];
        float4 w = dW4[r * 256 + kq];
        s.x += b * w.x; s.y += b * w.y; s.z += b * w.z; s.w += b * w.w;
    }
    __half2* p = (__half2*)(g_w2 + (size_t)(layer * D_MODEL + n) * D_MODEL + kq * 4);
    p[0] = __floats2half2_rn(s.x, s.y);
    p[1] = __floats2half2_rn(s.z, s.w);
}

// ---------------- HMMA GEMM: C[128,128] = A @ W^T (+bias), single fp16 -----
#define GKC   64
#define GNCH  16
#define GROWB 144
#define GT_BYTES (128 * GROWB)      /* 18432 */
#define GSTAGE   (2 * GT_BYTES)     /* 36864: A | W */
#define GSTAGES  3
#define GSMEM    (GSTAGES * GSTAGE) /* 110592, 2 CTAs/SM */

__global__ void __launch_bounds__(256, 2)
gemm_hmma(const __half* __restrict__ Abase,
          int mode, int layer_base,
          const float* __restrict__ b0, const float* __restrict__ b1,
          const float* __restrict__ b2, float* __restrict__ outO)
{
    extern __shared__ __align__(128) char smem[];
    const uint32_t sb = smem_u32(smem);
    const int tid = threadIdx.x, ln = tid & 31, w = tid >> 5;
    const int wm = w & 1, wn = w >> 1;
    const int bx = blockIdx.x, by = blockIdx.y, z = blockIdx.z;
    const int layer = layer_base + z;

    const __half* Arow = Abase + (size_t)(by * 128) * D_MODEL;
    const __half* Wrow = g_w2 + ((size_t)layer * D_MODEL + bx * 128) * D_MODEL;

    float acc[4][4][4] = {};

#define GLOAD(c) do {                                                          \
        int s_ = (c) % GSTAGES;                                                \
        int x_ = (c) * GKC;                                                    \
        uint32_t bA_ = sb + s_ * GSTAGE;                                       \
        uint32_t bW_ = bA_ + GT_BYTES;                                         \
        _Pragma("unroll")                                                      \
        for (int u_ = 0; u_ < 4; u_++) {                                       \
            int e_ = tid + u_ * 256;                                           \
            int row_ = e_ >> 3, seg_ = (e_ & 7) * 16;                          \
            cpa16(bA_ + row_ * GROWB + seg_,                                   \
                  (const char*)(Arow + (size_t)row_ * D_MODEL + x_) + seg_);   \
            cpa16(bW_ + row_ * GROWB + seg_,                                   \
                  (const char*)(Wrow + (size_t)row_ * D_MODEL + x_) + seg_);   \
        }                                                                      \
        CP_COMMIT();                                                           \
    } while (0)

    GLOAD(0);
    GLOAD(1);
    for (int c = 0; c < GNCH; c++) {
        if (c + 2 < GNCH) { CP_WAIT(1); } else { CP_WAIT(0); }
        __syncthreads();
        if (c + 2 < GNCH) GLOAD(c + 2);

        const uint32_t bA = sb + (c % GSTAGES) * GSTAGE;
        const uint32_t bW = bA + GT_BYTES;
#pragma unroll
        for (int ks = 0; ks < 4; ks++) {
            const int k0 = ks * 16;
            uint32_t afr[4][4];
#pragma unroll
            for (int i = 0; i < 4; i++) {
                int row = wm * 64 + i * 16 + (ln & 15);
                ldsm_x4(afr[i], bA + row * GROWB + (k0 + ((ln >> 4) << 3)) * 2);
            }
            uint32_t bfr[2][4];
#pragma unroll
            for (int j = 0; j < 2; j++) {
                int n = wn * 32 + j * 16 + (ln & 7) + ((ln & 16) ? 8 : 0);
                ldsm_x4(bfr[j], bW + n * GROWB + (k0 + ((ln & 8) ? 8 : 0)) * 2);
            }
#pragma unroll
            for (int i = 0; i < 4; i++)
#pragma unroll
                for (int jj = 0; jj < 4; jj++)
                    mma16816h(acc[i][jj], afr[i], bfr[jj >> 1][(jj & 1) * 2],
                              bfr[jj >> 1][(jj & 1) * 2 + 1]);
        }
    }

    const float* bias = (z == 0) ? b0 : (z == 1) ? b1 : b2;
    const float qscale = (mode == 0 && z == 0) ? 0.125f * 1.4426950408889634f : 1.0f;
#pragma unroll
    for (int i = 0; i < 4; i++) {
#pragma unroll
        for (int dl = 0; dl < 2; dl++) {
            const int m = by * 128 + wm * 64 + i * 16 + (ln >> 2) + dl * 8;
#pragma unroll
            for (int jj = 0; jj < 4; jj++) {
                const int cgl = bx * 128 + wn * 32 + jj * 8 + (ln & 3) * 2;
                float v0 = (acc[i][jj][dl * 2 + 0] + bias[cgl])     * qscale;
                float v1 = (acc[i][jj][dl * 2 + 1] + bias[cgl + 1]) * qscale;
                if (mode == 0) {
                    const int h = cgl >> 6, d = cgl & 63;
                    const int b = m >> 11, n = m & 2047;
                    const size_t rowb = (size_t)(b * NHEAD + h) * SEQ + n;
                    __half* base = ((z == 0) ? g_qh : (z == 1) ? g_kh : g_vh)
                                   + rowb * 64 + d;
                    *(__half2*)base = __floats2half2_rn(v0, v1);
                } else {
                    float2 o; o.x = v0; o.y = v1;
                    *(float2*)(outO + (size_t)m * D_MODEL + cgl) = o;
                }
            }
        }
    }
}

// ---------------- Flash attention: 4-deep ring, lean softmax ---------------
#define KROWB 144                         /* 64 fp16 + 8 pad */
#define KTILEB (64 * KROWB)               /* 9216 */
#define NBUF  4
#define QROWS 128
#define SM_Q   0
#define QBYTES (QROWS * KROWB)            /* 18432 */
#define SM_K0  QBYTES
#define SM_V0  (SM_K0 + NBUF * KTILEB)
#define ATT_SMEM (SM_V0 + NBUF * KTILEB)  /* 92160, 2 CTAs/SM */
#define NT (SEQ / 64)                     /* 32 tiles */

__global__ void __launch_bounds__(256, 2)
flash_hmma()
{
    extern __shared__ __align__(128) char smem[];
    const uint32_t sb = smem_u32(smem);
    const int tid = threadIdx.x, ln = tid & 31, w = tid >> 5;
    const int qt = blockIdx.x, bh = blockIdx.y;

    const __half* qg = g_qh + ((size_t)bh * SEQ + qt * QROWS) * 64;
    const __half* kg = g_kh + (size_t)bh * SEQ * 64;
    const __half* vg = g_vh + (size_t)bh * SEQ * 64;

#pragma unroll
    for (int u = 0; u < 4; u++) {
        int e = tid + u * 256;
        int row = e >> 3, seg = (e & 7) * 16;
        cpa16(sb + SM_Q + row * KROWB + seg, (const char*)(qg + (size_t)row * 64) + seg);
    }
    CP_COMMIT();

#define ATT_LOAD(t) do {                                                       \
        int buf_ = (t) & 3;                                                    \
        const __half* kb_ = kg + (size_t)(t) * 64 * 64;                        \
        const __half* vb_ = vg + (size_t)(t) * 64 * 64;                        \
        uint32_t kd_ = sb + SM_K0 + buf_ * KTILEB;                             \
        uint32_t vd_ = sb + SM_V0 + buf_ * KTILEB;                             \
        _Pragma("unroll")                                                      \
        for (int u_ = 0; u_ < 2; u_++) {                                       \
            int e_ = tid + u_ * 256;                                           \
            int row_ = e_ >> 3, seg_ = (e_ & 7) * 16;                          \
            cpa16(kd_ + row_ * KROWB + seg_,                                   \
                  (const char*)(kb_ + (size_t)row_ * 64) + seg_);              \
            cpa16(vd_ + row_ * KROWB + seg_,                                   \
                  (const char*)(vb_ + (size_t)row_ * 64) + seg_);              \
        }                                                                      \
        CP_COMMIT();                                                           \
    } while (0)

    ATT_LOAD(0);
    ATT_LOAD(1);
    ATT_LOAD(2);

    const uint32_t qaddr = sb + SM_Q + (w * 16 + (ln & 15)) * KROWB + (((ln >> 4) << 3)) * 2;
    const int krow8  = (ln & 7) + ((ln & 16) ? 8 : 0);
    const int kcol8  = (ln & 8) ? 8 : 0;
    const int vrow16 = ln & 15;
    const int vcol8  = (ln & 16) ? 8 : 0;

    uint32_t qf[4][4];
    bool qloaded = false;

    float m0 = -1e30f, m1 = -1e30f;
    float lp0 = 0.f, lp1 = 0.f;       // per-thread partial row sums
    float acco[8][4] = {};

#pragma unroll 1
    for (int i = 0; i < NT; i++) {
        if (i < NT - 2)      CP_WAIT(2);
        else                 CP_WAIT(0);
        __syncthreads();
        if (i + 3 < NT) ATT_LOAD(i + 3);

        if (!qloaded) {
#pragma unroll
            for (int s = 0; s < 4; s++)
                ldsm_x4(qf[s], qaddr + (s * 16) * 2);
            qloaded = true;
        }

        const uint32_t bK = sb + SM_K0 + (i & 3) * KTILEB;
        const uint32_t bV = sb + SM_V0 + (i & 3) * KTILEB;

        // ---- S burst ----
        float accs[8][4] = {};
#pragma unroll
        for (int ks = 0; ks < 4; ks++) {
#pragma unroll
            for (int nbp = 0; nbp < 4; nbp++) {
                uint32_t kb[4];
                ldsm_x4(kb, bK + (nbp * 16 + krow8) * KROWB + (ks * 16 + kcol8) * 2);
                mma16816h(accs[2 * nbp],     qf[ks], kb[0], kb[1]);
                mma16816h(accs[2 * nbp + 1], qf[ks], kb[2], kb[3]);
            }
        }

        // ---- row max: packed fp16 quad-reduce (consistent across quad) ----
        float mx0 = -1e30f, mx1 = -1e30f;
#pragma unroll
        for (int jj = 0; jj < 8; jj++) {
            mx0 = fmaxf(mx0, fmaxf(accs[jj][0], accs[jj][1]));
            mx1 = fmaxf(mx1, fmaxf(accs[jj][2], accs[jj][3]));
        }
        uint32_t pku = packh2(mx0, mx1);
        pku = hmax2(pku, __shfl_xor_sync(0xffffffffu, pku, 1));
        pku = hmax2(pku, __shfl_xor_sync(0xffffffffu, pku, 2));
        {
            __half2 pk = reinterpret_cast<__half2&>(pku);
            mx0 = __low2float(pk);
            mx1 = __high2float(pk);
        }
        const float mn0 = fmaxf(m0, mx0), mn1 = fmaxf(m1, mx1);
        const float a0 = ex2(m0 - mn0), a1 = ex2(m1 - mn1);
        m0 = mn0; m1 = mn1;
        lp0 *= a0; lp1 *= a1;
#pragma unroll
        for (int jj = 0; jj < 8; jj++) {
            acco[jj][0] *= a0; acco[jj][1] *= a0;
            acco[jj][2] *= a1; acco[jj][3] *= a1;
        }

        // ---- fused exp -> pack -> PV; l kept as per-thread partials ----
#pragma unroll
        for (int ks = 0; ks < 4; ks++) {
            float e00 = ex2(accs[2 * ks][0] - m0);
            float e01 = ex2(accs[2 * ks][1] - m0);
            float e02 = ex2(accs[2 * ks][2] - m1);
            float e03 = ex2(accs[2 * ks][3] - m1);
            float e10 = ex2(accs[2 * ks + 1][0] - m0);
            float e11 = ex2(accs[2 * ks + 1][1] - m0);
            float e12 = ex2(accs[2 * ks + 1][2] - m1);
            float e13 = ex2(accs[2 * ks + 1][3] - m1);
            lp0 += e00 + e01 + e10 + e11;
            lp1 += e02 + e03 + e12 + e13;
            uint32_t phi[4];
            phi[0] = packh2(e00, e01);
            phi[1] = packh2(e02, e03);
            phi[2] = packh2(e10, e11);
            phi[3] = packh2(e12, e13);
#pragma unroll
            for (int nbp = 0; nbp < 4; nbp++) {
                uint32_t vb[4];
                ldsm_x4t(vb, bV + (ks * 16 + vrow16) * KROWB + (nbp * 16 + vcol8) * 2);
                mma16816h(acco[2 * nbp],     phi, vb[0], vb[1]);
                mma16816h(acco[2 * nbp + 1], phi, vb[2], vb[3]);
            }
        }
    }

    // ---- epilogue: quad-reduce l once, normalize, write fp16 ----
    float l0 = lp0, l1 = lp1;
    l0 += __shfl_xor_sync(0xffffffffu, l0, 1);
    l0 += __shfl_xor_sync(0xffffffffu, l0, 2);
    l1 += __shfl_xor_sync(0xffffffffu, l1, 1);
    l1 += __shfl_xor_sync(0xffffffffu, l1, 2);

    const int b = bh >> 4, h = bh & 15;
    const int q = ln >> 2, t4 = ln & 3;
    const float inv0 = 1.f / l0, inv1 = 1.f / l1;
    const size_t n0 = (size_t)qt * QROWS + w * 16 + q;
    const size_t mg0 = (size_t)b * SEQ + n0;
    const size_t mg1 = mg0 + 8;
#pragma unroll
    for (int jj = 0; jj < 8; jj++) {
        const int col = h * 64 + jj * 8 + t4 * 2;
        *(uint32_t*)(g_ao + mg0 * D_MODEL + col) =
            packh2(acco[jj][0] * inv0, acco[jj][1] * inv0);
        *(uint32_t*)(g_ao + mg1 * D_MODEL + col) =
            packh2(acco[jj][2] * inv1, acco[jj][3] * inv1);
    }
}

// ---------------- launch --------------------------------------------------
extern "C" void kernel_launch(void* const* d_in, const int* in_sizes, int n_in,
                              void* d_out, int out_size)
{
    const float* x = (const float*)d_in[0];
    const float* W [4] = {(const float*)d_in[1],  (const float*)d_in[5],
                          (const float*)d_in[9],  (const float*)d_in[13]};
    const float* B [4] = {(const float*)d_in[2],  (const float*)d_in[6],
                          (const float*)d_in[10], (const float*)d_in[14]};
    const float* dW[4] = {(const float*)d_in[3],  (const float*)d_in[7],
                          (const float*)d_in[11], (const float*)d_in[15]};
    const float* dB[4] = {(const float*)d_in[4],  (const float*)d_in[8],
                          (const float*)d_in[12], (const float*)d_in[16]};
    float* out = (float*)d_out;

    void *pxh, *pao;
    cudaGetSymbolAddress(&pxh, g_xh);
    cudaGetSymbolAddress(&pao, g_ao);

    // 1) fused LoRA merge + x->fp16 (single launch)
    merge_prep<<<8192, 256>>>(x,
                              W[0], dW[0], dB[0], W[1], dW[1], dB[1],
                              W[2], dW[2], dB[2], W[3], dW[3], dB[3]);

    // 2) QKV projections
    cudaFuncSetAttribute(gemm_hmma, cudaFuncAttributeMaxDynamicSharedMemorySize, GSMEM);
    {
        dim3 grid(D_MODEL / 128, M_TOTAL / 128, 3);
        gemm_hmma<<<grid, 256, GSMEM>>>((const __half*)pxh, 0, 0,
                                        B[0], B[1], B[2], nullptr);
    }

    // 3) flash attention -> g_ao
    cudaFuncSetAttribute(flash_hmma, cudaFuncAttributeMaxDynamicSharedMemorySize, ATT_SMEM);
    {
        dim3 grid(SEQ / QROWS, BATCH * NHEAD);
        flash_hmma<<<grid, 256, ATT_SMEM>>>();
    }

    // 4) O projection -> d_out
    {
        dim3 grid(D_MODEL / 128, M_TOTAL / 128, 1);
        gemm_hmma<<<grid, 256, GSMEM>>>((const __half*)pao, 1, 3,
                                        B[3], B[3], B[3], out);
    }
}

// round 13
// speedup vs baseline: 9.5479x; 1.0163x over previous
#include <cuda_runtime.h>
#include <cuda_fp16.h>
#include <cstdint>

#define D_MODEL 1024
#define NHEAD   16
#define DHEAD   64
#define SEQ     2048
#define BATCH   2
#define M_TOTAL (BATCH * SEQ)   /* 4096 */
#define RANK    32

// ---------------- device scratch (all single fp16) ----------------
__device__ __half g_xh [(size_t)M_TOTAL * D_MODEL];
__device__ __half g_w2 [(size_t)4 * D_MODEL * D_MODEL];
__device__ __half g_ao [(size_t)M_TOTAL * D_MODEL];
__device__ __half g_qh [(size_t)BATCH * NHEAD * SEQ * 64];  // Q * 0.125*log2e
__device__ __half g_kh [(size_t)BATCH * NHEAD * SEQ * 64];
__device__ __half g_vh [(size_t)BATCH * NHEAD * SEQ * 64];

// ---------------- PTX helpers (baseline PTX only) ----------------
__device__ __forceinline__ uint32_t smem_u32(const void* p) {
    uint32_t a;
    asm("{ .reg .u64 t; cvta.to.shared.u64 t, %1; cvt.u32.u64 %0, t; }" : "=r"(a) : "l"(p));
    return a;
}
__device__ __forceinline__ void cpa16(uint32_t dst, const void* src) {
    asm volatile("cp.async.cg.shared.global [%0], [%1], 16;" :: "r"(dst), "l"(src));
}
#define CP_COMMIT() asm volatile("cp.async.commit_group;" ::: "memory")
#define CP_WAIT(n)  asm volatile("cp.async.wait_group %0;" :: "n"(n) : "memory")

__device__ __forceinline__ void ldsm_x4(uint32_t (&r)[4], uint32_t addr) {
    asm volatile("ldmatrix.sync.aligned.m8n8.x4.shared.b16 {%0,%1,%2,%3}, [%4];"
                 : "=r"(r[0]), "=r"(r[1]), "=r"(r[2]), "=r"(r[3]) : "r"(addr));
}
__device__ __forceinline__ void ldsm_x4t(uint32_t (&r)[4], uint32_t addr) {
    asm volatile("ldmatrix.sync.aligned.m8n8.x4.trans.shared.b16 {%0,%1,%2,%3}, [%4];"
                 : "=r"(r[0]), "=r"(r[1]), "=r"(r[2]), "=r"(r[3]) : "r"(addr));
}
// fp32-accumulate mma (GEMMs, PV)
__device__ __forceinline__ void mma16816h(float (&d)[4], const uint32_t (&a)[4],
                                          uint32_t b0, uint32_t b1) {
    asm volatile("mma.sync.aligned.m16n8k16.row.col.f32.f16.f16.f32 "
                 "{%0,%1,%2,%3}, {%4,%5,%6,%7}, {%8,%9}, {%0,%1,%2,%3};"
                 : "+f"(d[0]), "+f"(d[1]), "+f"(d[2]), "+f"(d[3])
                 : "r"(a[0]), "r"(a[1]), "r"(a[2]), "r"(a[3]), "r"(b0), "r"(b1));
}
// fp16-accumulate mma (S = QK^T only; 2x rate on HMMA)
__device__ __forceinline__ void mma16816hh(uint32_t (&d)[2], const uint32_t (&a)[4],
                                           uint32_t b0, uint32_t b1) {
    asm volatile("mma.sync.aligned.m16n8k16.row.col.f16.f16.f16.f16 "
                 "{%0,%1}, {%2,%3,%4,%5}, {%6,%7}, {%0,%1};"
                 : "+r"(d[0]), "+r"(d[1])
                 : "r"(a[0]), "r"(a[1]), "r"(a[2]), "r"(a[3]), "r"(b0), "r"(b1));
}
__device__ __forceinline__ uint32_t packh2(float v0, float v1) {
    __half2 t = __floats2half2_rn(v0, v1);
    return reinterpret_cast<uint32_t&>(t);
}
__device__ __forceinline__ float ex2(float x) {
    float y;
    asm("ex2.approx.ftz.f32 %0, %1;" : "=f"(y) : "f"(x));
    return y;
}

// ---------------- fused: LoRA merge (4 layers) + x->fp16, one launch -------
__global__ void merge_prep(const float* __restrict__ x,
                           const float* __restrict__ W0, const float* __restrict__ dW0, const float* __restrict__ dB0,
                           const float* __restrict__ W1, const float* __restrict__ dW1, const float* __restrict__ dB1,
                           const float* __restrict__ W2, const float* __restrict__ dW2, const float* __restrict__ dB2,
                           const float* __restrict__ W3, const float* __restrict__ dW3, const float* __restrict__ dB3)
{
    const int blk = blockIdx.x;
    if (blk < 4096) {
        int e = blk * 256 + threadIdx.x;
        float4 s = *(const float4*)(x + (size_t)e * 4);
        __half2* p = (__half2*)(g_xh + (size_t)e * 4);
        p[0] = __floats2half2_rn(s.x, s.y);
        p[1] = __floats2half2_rn(s.z, s.w);
        return;
    }
    const int bb = blk - 4096;
    const int layer = bb >> 10;
    const float* W  = (layer == 0) ? W0  : (layer == 1) ? W1  : (layer == 2) ? W2  : W3;
    const float* dW = (layer == 0) ? dW0 : (layer == 1) ? dW1 : (layer == 2) ? dW2 : dW3;
    const float* dB = (layer == 0) ? dB0 : (layer == 1) ? dB1 : (layer == 2) ? dB2 : dB3;

    int e  = (bb & 1023) * 256 + threadIdx.x;
    int n  = e >> 8;
    int kq = e & 255;
    float4 s = *(const float4*)(W + (size_t)n * D_MODEL + kq * 4);
    const float4* dW4 = (const float4*)dW;
#pragma unroll
    for (int r = 0; r < RANK; r++) {
        float b  = dB[n * RANK + r];
        float4 w = dW4[r * 256 + kq];
        s.x += b * w.x; s.y += b * w.y; s.z += b * w.z; s.w += b * w.w;
    }
    __half2* p = (__half2*)(g_w2 + (size_t)(layer * D_MODEL + n) * D_MODEL + kq * 4);
    p[0] = __floats2half2_rn(s.x, s.y);
    p[1] = __floats2half2_rn(s.z, s.w);
}

// ---------------- HMMA GEMM (unchanged, known-good) -------------------------
#define GKC   64
#define GNCH  16
#define GROWB 144
#define GT_BYTES (128 * GROWB)
#define GSTAGE   (2 * GT_BYTES)
#define GSTAGES  3
#define GSMEM    (GSTAGES * GSTAGE)

__global__ void __launch_bounds__(256, 2)
gemm_hmma(const __half* __restrict__ Abase,
          int mode, int layer_base,
          const float* __restrict__ b0, const float* __restrict__ b1,
          const float* __restrict__ b2, float* __restrict__ outO)
{
    extern __shared__ __align__(128) char smem[];
    const uint32_t sb = smem_u32(smem);
    const int tid = threadIdx.x, ln = tid & 31, w = tid >> 5;
    const int wm = w & 1, wn = w >> 1;
    const int bx = blockIdx.x, by = blockIdx.y, z = blockIdx.z;
    const int layer = layer_base + z;

    const __half* Arow = Abase + (size_t)(by * 128) * D_MODEL;
    const __half* Wrow = g_w2 + ((size_t)layer * D_MODEL + bx * 128) * D_MODEL;

    float acc[4][4][4] = {};

#define GLOAD(c) do {                                                          \
        int s_ = (c) % GSTAGES;                                                \
        int x_ = (c) * GKC;                                                    \
        uint32_t bA_ = sb + s_ * GSTAGE;                                       \
        uint32_t bW_ = bA_ + GT_BYTES;                                         \
        _Pragma("unroll")                                                      \
        for (int u_ = 0; u_ < 4; u_++) {                                       \
            int e_ = tid + u_ * 256;                                           \
            int row_ = e_ >> 3, seg_ = (e_ & 7) * 16;                          \
            cpa16(bA_ + row_ * GROWB + seg_,                                   \
                  (const char*)(Arow + (size_t)row_ * D_MODEL + x_) + seg_);   \
            cpa16(bW_ + row_ * GROWB + seg_,                                   \
                  (const char*)(Wrow + (size_t)row_ * D_MODEL + x_) + seg_);   \
        }                                                                      \
        CP_COMMIT();                                                           \
    } while (0)

    GLOAD(0);
    GLOAD(1);
    for (int c = 0; c < GNCH; c++) {
        if (c + 2 < GNCH) { CP_WAIT(1); } else { CP_WAIT(0); }
        __syncthreads();
        if (c + 2 < GNCH) GLOAD(c + 2);

        const uint32_t bA = sb + (c % GSTAGES) * GSTAGE;
        const uint32_t bW = bA + GT_BYTES;
#pragma unroll
        for (int ks = 0; ks < 4; ks++) {
            const int k0 = ks * 16;
            uint32_t afr[4][4];
#pragma unroll
            for (int i = 0; i < 4; i++) {
                int row = wm * 64 + i * 16 + (ln & 15);
                ldsm_x4(afr[i], bA + row * GROWB + (k0 + ((ln >> 4) << 3)) * 2);
            }
            uint32_t bfr[2][4];
#pragma unroll
            for (int j = 0; j < 2; j++) {
                int n = wn * 32 + j * 16 + (ln & 7) + ((ln & 16) ? 8 : 0);
                ldsm_x4(bfr[j], bW + n * GROWB + (k0 + ((ln & 8) ? 8 : 0)) * 2);
            }
#pragma unroll
            for (int i = 0; i < 4; i++)
#pragma unroll
                for (int jj = 0; jj < 4; jj++)
                    mma16816h(acc[i][jj], afr[i], bfr[jj >> 1][(jj & 1) * 2],
                              bfr[jj >> 1][(jj & 1) * 2 + 1]);
        }
    }

    const float* bias = (z == 0) ? b0 : (z == 1) ? b1 : b2;
    const float qscale = (mode == 0 && z == 0) ? 0.125f * 1.4426950408889634f : 1.0f;
#pragma unroll
    for (int i = 0; i < 4; i++) {
#pragma unroll
        for (int dl = 0; dl < 2; dl++) {
            const int m = by * 128 + wm * 64 + i * 16 + (ln >> 2) + dl * 8;
#pragma unroll
            for (int jj = 0; jj < 4; jj++) {
                const int cgl = bx * 128 + wn * 32 + jj * 8 + (ln & 3) * 2;
                float v0 = (acc[i][jj][dl * 2 + 0] + bias[cgl])     * qscale;
                float v1 = (acc[i][jj][dl * 2 + 1] + bias[cgl + 1]) * qscale;
                if (mode == 0) {
                    const int h = cgl >> 6, d = cgl & 63;
                    const int b = m >> 11, n = m & 2047;
                    const size_t rowb = (size_t)(b * NHEAD + h) * SEQ + n;
                    __half* base = ((z == 0) ? g_qh : (z == 1) ? g_kh : g_vh)
                                   + rowb * 64 + d;
                    *(__half2*)base = __floats2half2_rn(v0, v1);
                } else {
                    float2 o; o.x = v0; o.y = v1;
                    *(float2*)(outO + (size_t)m * D_MODEL + cgl) = o;
                }
            }
        }
    }
}

// ---------------- Flash attention: reg-Q, 6-deep ring, fp16-acc S ----------
#define KROWB 144                         /* 64 fp16 + 8 pad */
#define KTILEB (64 * KROWB)               /* 9216 */
#define NBUF  6
#define QROWS 128
#define SM_K0  0
#define SM_V0  (NBUF * KTILEB)            /* 55296 */
#define ATT_SMEM (2 * NBUF * KTILEB)      /* 110592, 2 CTAs/SM */
#define NT (SEQ / 64)                     /* 32 tiles */

__global__ void __launch_bounds__(256, 2)
flash_hmma()
{
    extern __shared__ __align__(128) char smem[];
    const uint32_t sb = smem_u32(smem);
    const int tid = threadIdx.x, ln = tid & 31, w = tid >> 5;
    const int qt = blockIdx.x, bh = blockIdx.y;

    const __half* qg = g_qh + ((size_t)bh * SEQ + qt * QROWS) * 64;
    const __half* kg = g_kh + (size_t)bh * SEQ * 64;
    const __half* vg = g_vh + (size_t)bh * SEQ * 64;

#define ATT_LOAD(t) do {                                                       \
        int buf_ = (t) % NBUF;                                                 \
        const __half* kb_ = kg + (size_t)(t) * 64 * 64;                        \
        const __half* vb_ = vg + (size_t)(t) * 64 * 64;                        \
        uint32_t kd_ = sb + SM_K0 + buf_ * KTILEB;                             \
        uint32_t vd_ = sb + SM_V0 + buf_ * KTILEB;                             \
        _Pragma("unroll")                                                      \
        for (int u_ = 0; u_ < 2; u_++) {                                       \
            int e_ = tid + u_ * 256;                                           \
            int row_ = e_ >> 3, seg_ = (e_ & 7) * 16;                          \
            cpa16(kd_ + row_ * KROWB + seg_,                                   \
                  (const char*)(kb_ + (size_t)row_ * 64) + seg_);              \
            cpa16(vd_ + row_ * KROWB + seg_,                                   \
                  (const char*)(vb_ + (size_t)row_ * 64) + seg_);              \
        }                                                                      \
        CP_COMMIT();                                                           \
    } while (0)

    ATT_LOAD(0); ATT_LOAD(1); ATT_LOAD(2); ATT_LOAD(3); ATT_LOAD(4);

    // ---- Q fragments straight from gmem (A m16k16 fragment layout) ----
    // a0=(r, c..c+1)  a1=(r+8, c..)  a2=(r, c+8..)  a3=(r+8, c+8..)
    // r = ln>>2, c = (ln&3)*2, block s covers k = s*16..s*16+15
    uint32_t qf[4][4];
    {
        const __half* q0 = qg + (size_t)(w * 16 + (ln >> 2)) * 64 + (ln & 3) * 2;
        const __half* q8 = q0 + 8 * 64;
#pragma unroll
        for (int s = 0; s < 4; s++) {
            qf[s][0] = *(const uint32_t*)(q0 + s * 16);
            qf[s][1] = *(const uint32_t*)(q8 + s * 16);
            qf[s][2] = *(const uint32_t*)(q0 + s * 16 + 8);
            qf[s][3] = *(const uint32_t*)(q8 + s * 16 + 8);
        }
    }

    const int krow8  = (ln & 7) + ((ln & 16) ? 8 : 0);
    const int kcol8  = (ln & 8) ? 8 : 0;
    const int vrow16 = ln & 15;
    const int vcol8  = (ln & 16) ? 8 : 0;

    float m0 = -1e30f, m1 = -1e30f;
    float lp0 = 0.f, lp1 = 0.f;
    float acco[8][4] = {};

#pragma unroll 1
    for (int i = 0; i < NT; i++) {
        {
            const int rem = NT - 1 - i;   // tiles still outstanding after i
            if      (rem >= 4) CP_WAIT(4);
            else if (rem == 3) CP_WAIT(3);
            else if (rem == 2) CP_WAIT(2);
            else if (rem == 1) CP_WAIT(1);
            else               CP_WAIT(0);
        }
        __syncthreads();
        if (i + 5 < NT) ATT_LOAD(i + 5);

        const uint32_t bK = sb + SM_K0 + (i % NBUF) * KTILEB;
        const uint32_t bV = sb + SM_V0 + (i % NBUF) * KTILEB;

        // ---- S = Q K^T, fp16 accumulators (2x HMMA rate) ----
        uint32_t sh[8][2] = {};
#pragma unroll
        for (int ks = 0; ks < 4; ks++) {
#pragma unroll
            for (int nbp = 0; nbp < 4; nbp++) {
                uint32_t kb[4];
                ldsm_x4(kb, bK + (nbp * 16 + krow8) * KROWB + (ks * 16 + kcol8) * 2);
                mma16816hh(sh[2 * nbp],     qf[ks], kb[0], kb[1]);
                mma16816hh(sh[2 * nbp + 1], qf[ks], kb[2], kb[3]);
            }
        }
        // unpack to fp32: [0]=(r,c) [1]=(r,c+1) [2]=(r+8,c) [3]=(r+8,c+1)
        float accs[8][4];
#pragma unroll
        for (int jj = 0; jj < 8; jj++) {
            __half2 lo = reinterpret_cast<__half2&>(sh[jj][0]);
            __half2 hi = reinterpret_cast<__half2&>(sh[jj][1]);
            accs[jj][0] = __low2float(lo);  accs[jj][1] = __high2float(lo);
            accs[jj][2] = __low2float(hi);  accs[jj][3] = __high2float(hi);
        }

        // ---- warp-local online softmax (base-2) ----
        float mx0 = -1e30f, mx1 = -1e30f;
#pragma unroll
        for (int jj = 0; jj < 8; jj++) {
            mx0 = fmaxf(mx0, fmaxf(accs[jj][0], accs[jj][1]));
            mx1 = fmaxf(mx1, fmaxf(accs[jj][2], accs[jj][3]));
        }
        mx0 = fmaxf(mx0, __shfl_xor_sync(0xffffffffu, mx0, 1));
        mx0 = fmaxf(mx0, __shfl_xor_sync(0xffffffffu, mx0, 2));
        mx1 = fmaxf(mx1, __shfl_xor_sync(0xffffffffu, mx1, 1));
        mx1 = fmaxf(mx1, __shfl_xor_sync(0xffffffffu, mx1, 2));
        const float mn0 = fmaxf(m0, mx0), mn1 = fmaxf(m1, mx1);
        const float a0 = ex2(m0 - mn0), a1 = ex2(m1 - mn1);
        m0 = mn0; m1 = mn1;
        lp0 *= a0; lp1 *= a1;
#pragma unroll
        for (int jj = 0; jj < 8; jj++) {
            acco[jj][0] *= a0; acco[jj][1] *= a0;
            acco[jj][2] *= a1; acco[jj][3] *= a1;
        }

        // ---- fused exp -> pack -> PV (fp32 acc) ----
#pragma unroll
        for (int ks = 0; ks < 4; ks++) {
            float e00 = ex2(accs[2 * ks][0] - m0);
            float e01 = ex2(accs[2 * ks][1] - m0);
            float e02 = ex2(accs[2 * ks][2] - m1);
            float e03 = ex2(accs[2 * ks][3] - m1);
            float e10 = ex2(accs[2 * ks + 1][0] - m0);
            float e11 = ex2(accs[2 * ks + 1][1] - m0);
            float e12 = ex2(accs[2 * ks + 1][2] - m1);
            float e13 = ex2(accs[2 * ks + 1][3] - m1);
            lp0 += e00 + e01 + e10 + e11;
            lp1 += e02 + e03 + e12 + e13;
            uint32_t phi[4];
            phi[0] = packh2(e00, e01);
            phi[1] = packh2(e02, e03);
            phi[2] = packh2(e10, e11);
            phi[3] = packh2(e12, e13);
#pragma unroll
            for (int nbp = 0; nbp < 4; nbp++) {
                uint32_t vb[4];
                ldsm_x4t(vb, bV + (ks * 16 + vrow16) * KROWB + (nbp * 16 + vcol8) * 2);
                mma16816h(acco[2 * nbp],     phi, vb[0], vb[1]);
                mma16816h(acco[2 * nbp + 1], phi, vb[2], vb[3]);
            }
        }
    }

    // ---- epilogue: quad-reduce l once, normalize, write fp16 ----
    float l0 = lp0, l1 = lp1;
    l0 += __shfl_xor_sync(0xffffffffu, l0, 1);
    l0 += __shfl_xor_sync(0xffffffffu, l0, 2);
    l1 += __shfl_xor_sync(0xffffffffu, l1, 1);
    l1 += __shfl_xor_sync(0xffffffffu, l1, 2);

    const int b = bh >> 4, h = bh & 15;
    const int q = ln >> 2, t4 = ln & 3;
    const float inv0 = 1.f / l0, inv1 = 1.f / l1;
    const size_t n0 = (size_t)qt * QROWS + w * 16 + q;
    const size_t mg0 = (size_t)b * SEQ + n0;
    const size_t mg1 = mg0 + 8;
#pragma unroll
    for (int jj = 0; jj < 8; jj++) {
        const int col = h * 64 + jj * 8 + t4 * 2;
        *(uint32_t*)(g_ao + mg0 * D_MODEL + col) =
            packh2(acco[jj][0] * inv0, acco[jj][1] * inv0);
        *(uint32_t*)(g_ao + mg1 * D_MODEL + col) =
            packh2(acco[jj][2] * inv1, acco[jj][3] * inv1);
    }
}

// ---------------- launch --------------------------------------------------
extern "C" void kernel_launch(void* const* d_in, const int* in_sizes, int n_in,
                              void* d_out, int out_size)
{
    const float* x = (const float*)d_in[0];
    const float* W [4] = {(const float*)d_in[1],  (const float*)d_in[5],
                          (const float*)d_in[9],  (const float*)d_in[13]};
    const float* B [4] = {(const float*)d_in[2],  (const float*)d_in[6],
                          (const float*)d_in[10], (const float*)d_in[14]};
    const float* dW[4] = {(const float*)d_in[3],  (const float*)d_in[7],
                          (const float*)d_in[11], (const float*)d_in[15]};
    const float* dB[4] = {(const float*)d_in[4],  (const float*)d_in[8],
                          (const float*)d_in[12], (const float*)d_in[16]};
    float* out = (float*)d_out;

    void *pxh, *pao;
    cudaGetSymbolAddress(&pxh, g_xh);
    cudaGetSymbolAddress(&pao, g_ao);

    // 1) fused LoRA merge + x->fp16
    merge_prep<<<8192, 256>>>(x,
                              W[0], dW[0], dB[0], W[1], dW[1], dB[1],
                              W[2], dW[2], dB[2], W[3], dW[3], dB[3]);

    // 2) QKV projections
    cudaFuncSetAttribute(gemm_hmma, cudaFuncAttributeMaxDynamicSharedMemorySize, GSMEM);
    {
        dim3 grid(D_MODEL / 128, M_TOTAL / 128, 3);
        gemm_hmma<<<grid, 256, GSMEM>>>((const __half*)pxh, 0, 0,
                                        B[0], B[1], B[2], nullptr);
    }

    // 3) flash attention -> g_ao
    cudaFuncSetAttribute(flash_hmma, cudaFuncAttributeMaxDynamicSharedMemorySize, ATT_SMEM);
    {
        dim3 grid(SEQ / QROWS, BATCH * NHEAD);
        flash_hmma<<<grid, 256, ATT_SMEM>>>();
    }

    // 4) O projection -> d_out
    {
        dim3 grid(D_MODEL / 128, M_TOTAL / 128, 1);
        gemm_hmma<<<grid, 256, GSMEM>>>((const __half*)pao, 1, 3,
                                        B[3], B[3], B[3], out);
    }
}

// round 14
// speedup vs baseline: 9.7675x; 1.0230x over previous
#include <cuda_runtime.h>
#include <cuda_fp16.h>
#include <cstdint>

#define D_MODEL 1024
#define NHEAD   16
#define DHEAD   64
#define SEQ     2048
#define BATCH   2
#define M_TOTAL (BATCH * SEQ)   /* 4096 */
#define RANK    32

// ---------------- device scratch (all single fp16) ----------------
__device__ __half g_xh [(size_t)M_TOTAL * D_MODEL];
__device__ __half g_w2 [(size_t)4 * D_MODEL * D_MODEL];
__device__ __half g_ao [(size_t)M_TOTAL * D_MODEL];
__device__ __half g_qh [(size_t)BATCH * NHEAD * SEQ * 64];  // Q * 0.125*log2e
__device__ __half g_kh [(size_t)BATCH * NHEAD * SEQ * 64];
__device__ __half g_vh [(size_t)BATCH * NHEAD * SEQ * 64];

// ---------------- PTX helpers (baseline PTX only) ----------------
__device__ __forceinline__ uint32_t smem_u32(const void* p) {
    uint32_t a;
    asm("{ .reg .u64 t; cvta.to.shared.u64 t, %1; cvt.u32.u64 %0, t; }" : "=r"(a) : "l"(p));
    return a;
}
__device__ __forceinline__ void cpa16(uint32_t dst, const void* src) {
    asm volatile("cp.async.cg.shared.global [%0], [%1], 16;" :: "r"(dst), "l"(src));
}
#define CP_COMMIT() asm volatile("cp.async.commit_group;" ::: "memory")
#define CP_WAIT(n)  asm volatile("cp.async.wait_group %0;" :: "n"(n) : "memory")

__device__ __forceinline__ void ldsm_x4(uint32_t (&r)[4], uint32_t addr) {
    asm volatile("ldmatrix.sync.aligned.m8n8.x4.shared.b16 {%0,%1,%2,%3}, [%4];"
                 : "=r"(r[0]), "=r"(r[1]), "=r"(r[2]), "=r"(r[3]) : "r"(addr));
}
__device__ __forceinline__ void ldsm_x4t(uint32_t (&r)[4], uint32_t addr) {
    asm volatile("ldmatrix.sync.aligned.m8n8.x4.trans.shared.b16 {%0,%1,%2,%3}, [%4];"
                 : "=r"(r[0]), "=r"(r[1]), "=r"(r[2]), "=r"(r[3]) : "r"(addr));
}
__device__ __forceinline__ void mma16816h(float (&d)[4], const uint32_t (&a)[4],
                                          uint32_t b0, uint32_t b1) {
    asm volatile("mma.sync.aligned.m16n8k16.row.col.f32.f16.f16.f32 "
                 "{%0,%1,%2,%3}, {%4,%5,%6,%7}, {%8,%9}, {%0,%1,%2,%3};"
                 : "+f"(d[0]), "+f"(d[1]), "+f"(d[2]), "+f"(d[3])
                 : "r"(a[0]), "r"(a[1]), "r"(a[2]), "r"(a[3]), "r"(b0), "r"(b1));
}
__device__ __forceinline__ void mma16816hh(uint32_t (&d)[2], const uint32_t (&a)[4],
                                           uint32_t b0, uint32_t b1) {
    asm volatile("mma.sync.aligned.m16n8k16.row.col.f16.f16.f16.f16 "
                 "{%0,%1}, {%2,%3,%4,%5}, {%6,%7}, {%0,%1};"
                 : "+r"(d[0]), "+r"(d[1])
                 : "r"(a[0]), "r"(a[1]), "r"(a[2]), "r"(a[3]), "r"(b0), "r"(b1));
}
__device__ __forceinline__ uint32_t packh2(float v0, float v1) {
    __half2 t = __floats2half2_rn(v0, v1);
    return reinterpret_cast<uint32_t&>(t);
}
__device__ __forceinline__ float ex2(float x) {
    float y;
    asm("ex2.approx.ftz.f32 %0, %1;" : "=f"(y) : "f"(x));
    return y;
}

// ---------------- smem-tiled LoRA merge: Wm = W + dB @ dW -> fp16 ----------
// grid (4 kgroups, 32 ngroups, 4 layers), 256 threads.
// dW tile [32r x 64 quads] (32KB) + dB tile [32n x 32r] staged in smem;
// L2 traffic per block: 32KB dW + 32KB W (vs 131KB dW/block before).
__global__ void __launch_bounds__(256)
merge_lora_t(const float* __restrict__ W0, const float* __restrict__ dW0, const float* __restrict__ dB0,
             const float* __restrict__ W1, const float* __restrict__ dW1, const float* __restrict__ dB1,
             const float* __restrict__ W2, const float* __restrict__ dW2, const float* __restrict__ dB2,
             const float* __restrict__ W3, const float* __restrict__ dW3, const float* __restrict__ dB3)
{
    const int kx = blockIdx.x;        // 0..3   (64 float4-quads each)
    const int ny = blockIdx.y;        // 0..31  (32 n-rows each)
    const int layer = blockIdx.z;
    const float* W  = (layer == 0) ? W0  : (layer == 1) ? W1  : (layer == 2) ? W2  : W3;
    const float* dW = (layer == 0) ? dW0 : (layer == 1) ? dW1 : (layer == 2) ? dW2 : dW3;
    const float* dB = (layer == 0) ? dB0 : (layer == 1) ? dB1 : (layer == 2) ? dB2 : dB3;

    __shared__ float4 dws[RANK][64];
    __shared__ float  dbs[32][RANK];

    const int tid = threadIdx.x;
    const float4* dW4 = (const float4*)dW;
    const int n0 = ny * 32;

#pragma unroll
    for (int i = 0; i < 8; i++) {       // dW tile: 32x64 quads
        int e = tid + i * 256;
        int r = e >> 6, q = e & 63;
        dws[r][q] = dW4[r * 256 + kx * 64 + q];
    }
#pragma unroll
    for (int i = 0; i < 4; i++) {       // dB tile: 32x32
        int e = tid + i * 256;
        int row = e >> 5, r = e & 31;
        dbs[row][r] = dB[(n0 + row) * RANK + r];
    }
    __syncthreads();

    const int q    = tid & 63;
    const int rowg = tid >> 6;          // 0..3, 8 rows each
    const float4* W4 = (const float4*)W;
    float4 s[8];
#pragma unroll
    for (int j = 0; j < 8; j++)
        s[j] = W4[(size_t)(n0 + rowg * 8 + j) * 256 + kx * 64 + q];
#pragma unroll
    for (int r = 0; r < RANK; r++) {
        float4 w = dws[r][q];
#pragma unroll
        for (int j = 0; j < 8; j++) {
            float b = dbs[rowg * 8 + j][r];
            s[j].x += b * w.x; s[j].y += b * w.y;
            s[j].z += b * w.z; s[j].w += b * w.w;
        }
    }
#pragma unroll
    for (int j = 0; j < 8; j++) {
        int n = n0 + rowg * 8 + j;
        __half2* p = (__half2*)(g_w2 + (size_t)(layer * D_MODEL + n) * D_MODEL
                                + (kx * 64 + q) * 4);
        p[0] = __floats2half2_rn(s[j].x, s[j].y);
        p[1] = __floats2half2_rn(s[j].z, s[j].w);
    }
}

// ---------------- x -> single fp16 ----------------
__global__ void prep_h(const float* __restrict__ src)
{
    int e = blockIdx.x * 256 + threadIdx.x;
    float4 s = *(const float4*)(src + (size_t)e * 4);
    __half2* p = (__half2*)(g_xh + (size_t)e * 4);
    p[0] = __floats2half2_rn(s.x, s.y);
    p[1] = __floats2half2_rn(s.z, s.w);
}

// ---------------- HMMA GEMM (unchanged, known-good) -------------------------
#define GKC   64
#define GNCH  16
#define GROWB 144
#define GT_BYTES (128 * GROWB)
#define GSTAGE   (2 * GT_BYTES)
#define GSTAGES  3
#define GSMEM    (GSTAGES * GSTAGE)

__global__ void __launch_bounds__(256, 2)
gemm_hmma(const __half* __restrict__ Abase,
          int mode, int layer_base,
          const float* __restrict__ b0, const float* __restrict__ b1,
          const float* __restrict__ b2, float* __restrict__ outO)
{
    extern __shared__ __align__(128) char smem[];
    const uint32_t sb = smem_u32(smem);
    const int tid = threadIdx.x, ln = tid & 31, w = tid >> 5;
    const int wm = w & 1, wn = w >> 1;
    const int bx = blockIdx.x, by = blockIdx.y, z = blockIdx.z;
    const int layer = layer_base + z;

    const __half* Arow = Abase + (size_t)(by * 128) * D_MODEL;
    const __half* Wrow = g_w2 + ((size_t)layer * D_MODEL + bx * 128) * D_MODEL;

    float acc[4][4][4] = {};

#define GLOAD(c) do {                                                          \
        int s_ = (c) % GSTAGES;                                                \
        int x_ = (c) * GKC;                                                    \
        uint32_t bA_ = sb + s_ * GSTAGE;                                       \
        uint32_t bW_ = bA_ + GT_BYTES;                                         \
        _Pragma("unroll")                                                      \
        for (int u_ = 0; u_ < 4; u_++) {                                       \
            int e_ = tid + u_ * 256;                                           \
            int row_ = e_ >> 3, seg_ = (e_ & 7) * 16;                          \
            cpa16(bA_ + row_ * GROWB + seg_,                                   \
                  (const char*)(Arow + (size_t)row_ * D_MODEL + x_) + seg_);   \
            cpa16(bW_ + row_ * GROWB + seg_,                                   \
                  (const char*)(Wrow + (size_t)row_ * D_MODEL + x_) + seg_);   \
        }                                                                      \
        CP_COMMIT();                                                           \
    } while (0)

    GLOAD(0);
    GLOAD(1);
    for (int c = 0; c < GNCH; c++) {
        if (c + 2 < GNCH) { CP_WAIT(1); } else { CP_WAIT(0); }
        __syncthreads();
        if (c + 2 < GNCH) GLOAD(c + 2);

        const uint32_t bA = sb + (c % GSTAGES) * GSTAGE;
        const uint32_t bW = bA + GT_BYTES;
#pragma unroll
        for (int ks = 0; ks < 4; ks++) {
            const int k0 = ks * 16;
            uint32_t afr[4][4];
#pragma unroll
            for (int i = 0; i < 4; i++) {
                int row = wm * 64 + i * 16 + (ln & 15);
                ldsm_x4(afr[i], bA + row * GROWB + (k0 + ((ln >> 4) << 3)) * 2);
            }
            uint32_t bfr[2][4];
#pragma unroll
            for (int j = 0; j < 2; j++) {
                int n = wn * 32 + j * 16 + (ln & 7) + ((ln & 16) ? 8 : 0);
                ldsm_x4(bfr[j], bW + n * GROWB + (k0 + ((ln & 8) ? 8 : 0)) * 2);
            }
#pragma unroll
            for (int i = 0; i < 4; i++)
#pragma unroll
                for (int jj = 0; jj < 4; jj++)
                    mma16816h(acc[i][jj], afr[i], bfr[jj >> 1][(jj & 1) * 2],
                              bfr[jj >> 1][(jj & 1) * 2 + 1]);
        }
    }

    const float* bias = (z == 0) ? b0 : (z == 1) ? b1 : b2;
    const float qscale = (mode == 0 && z == 0) ? 0.125f * 1.4426950408889634f : 1.0f;
#pragma unroll
    for (int i = 0; i < 4; i++) {
#pragma unroll
        for (int dl = 0; dl < 2; dl++) {
            const int m = by * 128 + wm * 64 + i * 16 + (ln >> 2) + dl * 8;
#pragma unroll
            for (int jj = 0; jj < 4; jj++) {
                const int cgl = bx * 128 + wn * 32 + jj * 8 + (ln & 3) * 2;
                float v0 = (acc[i][jj][dl * 2 + 0] + bias[cgl])     * qscale;
                float v1 = (acc[i][jj][dl * 2 + 1] + bias[cgl + 1]) * qscale;
                if (mode == 0) {
                    const int h = cgl >> 6, d = cgl & 63;
                    const int b = m >> 11, n = m & 2047;
                    const size_t rowb = (size_t)(b * NHEAD + h) * SEQ + n;
                    __half* base = ((z == 0) ? g_qh : (z == 1) ? g_kh : g_vh)
                                   + rowb * 64 + d;
                    *(__half2*)base = __floats2half2_rn(v0, v1);
                } else {
                    float2 o; o.x = v0; o.y = v1;
                    *(float2*)(outO + (size_t)m * D_MODEL + cgl) = o;
                }
            }
        }
    }
}

// ---------------- Flash attention (unchanged from round 13) ----------------
#define KROWB 144
#define KTILEB (64 * KROWB)
#define NBUF  6
#define QROWS 128
#define SM_K0  0
#define SM_V0  (NBUF * KTILEB)
#define ATT_SMEM (2 * NBUF * KTILEB)      /* 110592, 2 CTAs/SM */
#define NT (SEQ / 64)

__global__ void __launch_bounds__(256, 2)
flash_hmma()
{
    extern __shared__ __align__(128) char smem[];
    const uint32_t sb = smem_u32(smem);
    const int tid = threadIdx.x, ln = tid & 31, w = tid >> 5;
    const int qt = blockIdx.x, bh = blockIdx.y;

    const __half* qg = g_qh + ((size_t)bh * SEQ + qt * QROWS) * 64;
    const __half* kg = g_kh + (size_t)bh * SEQ * 64;
    const __half* vg = g_vh + (size_t)bh * SEQ * 64;

#define ATT_LOAD(t) do {                                                       \
        int buf_ = (t) % NBUF;                                                 \
        const __half* kb_ = kg + (size_t)(t) * 64 * 64;                        \
        const __half* vb_ = vg + (size_t)(t) * 64 * 64;                        \
        uint32_t kd_ = sb + SM_K0 + buf_ * KTILEB;                             \
        uint32_t vd_ = sb + SM_V0 + buf_ * KTILEB;                             \
        _Pragma("unroll")                                                      \
        for (int u_ = 0; u_ < 2; u_++) {                                       \
            int e_ = tid + u_ * 256;                                           \
            int row_ = e_ >> 3, seg_ = (e_ & 7) * 16;                          \
            cpa16(kd_ + row_ * KROWB + seg_,                                   \
                  (const char*)(kb_ + (size_t)row_ * 64) + seg_);              \
            cpa16(vd_ + row_ * KROWB + seg_,                                   \
                  (const char*)(vb_ + (size_t)row_ * 64) + seg_);              \
        }                                                                      \
        CP_COMMIT();                                                           \
    } while (0)

    ATT_LOAD(0); ATT_LOAD(1); ATT_LOAD(2); ATT_LOAD(3); ATT_LOAD(4);

    uint32_t qf[4][4];
    {
        const __half* q0 = qg + (size_t)(w * 16 + (ln >> 2)) * 64 + (ln & 3) * 2;
        const __half* q8 = q0 + 8 * 64;
#pragma unroll
        for (int s = 0; s < 4; s++) {
            qf[s][0] = *(const uint32_t*)(q0 + s * 16);
            qf[s][1] = *(const uint32_t*)(q8 + s * 16);
            qf[s][2] = *(const uint32_t*)(q0 + s * 16 + 8);
            qf[s][3] = *(const uint32_t*)(q8 + s * 16 + 8);
        }
    }

    const int krow8  = (ln & 7) + ((ln & 16) ? 8 : 0);
    const int kcol8  = (ln & 8) ? 8 : 0;
    const int vrow16 = ln & 15;
    const int vcol8  = (ln & 16) ? 8 : 0;

    float m0 = -1e30f, m1 = -1e30f;
    float lp0 = 0.f, lp1 = 0.f;
    float acco[8][4] = {};

#pragma unroll 1
    for (int i = 0; i < NT; i++) {
        {
            const int rem = NT - 1 - i;
            if      (rem >= 4) CP_WAIT(4);
            else if (rem == 3) CP_WAIT(3);
            else if (rem == 2) CP_WAIT(2);
            else if (rem == 1) CP_WAIT(1);
            else               CP_WAIT(0);
        }
        __syncthreads();
        if (i + 5 < NT) ATT_LOAD(i + 5);

        const uint32_t bK = sb + SM_K0 + (i % NBUF) * KTILEB;
        const uint32_t bV = sb + SM_V0 + (i % NBUF) * KTILEB;

        uint32_t sh[8][2] = {};
#pragma unroll
        for (int ks = 0; ks < 4; ks++) {
#pragma unroll
            for (int nbp = 0; nbp < 4; nbp++) {
                uint32_t kb[4];
                ldsm_x4(kb, bK + (nbp * 16 + krow8) * KROWB + (ks * 16 + kcol8) * 2);
                mma16816hh(sh[2 * nbp],     qf[ks], kb[0], kb[1]);
                mma16816hh(sh[2 * nbp + 1], qf[ks], kb[2], kb[3]);
            }
        }
        float accs[8][4];
#pragma unroll
        for (int jj = 0; jj < 8; jj++) {
            __half2 lo = reinterpret_cast<__half2&>(sh[jj][0]);
            __half2 hi = reinterpret_cast<__half2&>(sh[jj][1]);
            accs[jj][0] = __low2float(lo);  accs[jj][1] = __high2float(lo);
            accs[jj][2] = __low2float(hi);  accs[jj][3] = __high2float(hi);
        }

        float mx0 = -1e30f, mx1 = -1e30f;
#pragma unroll
        for (int jj = 0; jj < 8; jj++) {
            mx0 = fmaxf(mx0, fmaxf(accs[jj][0], accs[jj][1]));
            mx1 = fmaxf(mx1, fmaxf(accs[jj][2], accs[jj][3]));
        }
        mx0 = fmaxf(mx0, __shfl_xor_sync(0xffffffffu, mx0, 1));
        mx0 = fmaxf(mx0, __shfl_xor_sync(0xffffffffu, mx0, 2));
        mx1 = fmaxf(mx1, __shfl_xor_sync(0xffffffffu, mx1, 1));
        mx1 = fmaxf(mx1, __shfl_xor_sync(0xffffffffu, mx1, 2));
        const float mn0 = fmaxf(m0, mx0), mn1 = fmaxf(m1, mx1);
        const float a0 = ex2(m0 - mn0), a1 = ex2(m1 - mn1);
        m0 = mn0; m1 = mn1;
        lp0 *= a0; lp1 *= a1;
#pragma unroll
        for (int jj = 0; jj < 8; jj++) {
            acco[jj][0] *= a0; acco[jj][1] *= a0;
            acco[jj][2] *= a1; acco[jj][3] *= a1;
        }

#pragma unroll
        for (int ks = 0; ks < 4; ks++) {
            float e00 = ex2(accs[2 * ks][0] - m0);
            float e01 = ex2(accs[2 * ks][1] - m0);
            float e02 = ex2(accs[2 * ks][2] - m1);
            float e03 = ex2(accs[2 * ks][3] - m1);
            float e10 = ex2(accs[2 * ks + 1][0] - m0);
            float e11 = ex2(accs[2 * ks + 1][1] - m0);
            float e12 = ex2(accs[2 * ks + 1][2] - m1);
            float e13 = ex2(accs[2 * ks + 1][3] - m1);
            lp0 += e00 + e01 + e10 + e11;
            lp1 += e02 + e03 + e12 + e13;
            uint32_t phi[4];
            phi[0] = packh2(e00, e01);
            phi[1] = packh2(e02, e03);
            phi[2] = packh2(e10, e11);
            phi[3] = packh2(e12, e13);
#pragma unroll
            for (int nbp = 0; nbp < 4; nbp++) {
                uint32_t vb[4];
                ldsm_x4t(vb, bV + (ks * 16 + vrow16) * KROWB + (nbp * 16 + vcol8) * 2);
                mma16816h(acco[2 * nbp],     phi, vb[0], vb[1]);
                mma16816h(acco[2 * nbp + 1], phi, vb[2], vb[3]);
            }
        }
    }

    float l0 = lp0, l1 = lp1;
    l0 += __shfl_xor_sync(0xffffffffu, l0, 1);
    l0 += __shfl_xor_sync(0xffffffffu, l0, 2);
    l1 += __shfl_xor_sync(0xffffffffu, l1, 1);
    l1 += __shfl_xor_sync(0xffffffffu, l1, 2);

    const int b = bh >> 4, h = bh & 15;
    const int q = ln >> 2, t4 = ln & 3;
    const float inv0 = 1.f / l0, inv1 = 1.f / l1;
    const size_t n0 = (size_t)qt * QROWS + w * 16 + q;
    const size_t mg0 = (size_t)b * SEQ + n0;
    const size_t mg1 = mg0 + 8;
#pragma unroll
    for (int jj = 0; jj < 8; jj++) {
        const int col = h * 64 + jj * 8 + t4 * 2;
        *(uint32_t*)(g_ao + mg0 * D_MODEL + col) =
            packh2(acco[jj][0] * inv0, acco[jj][1] * inv0);
        *(uint32_t*)(g_ao + mg1 * D_MODEL + col) =
            packh2(acco[jj][2] * inv1, acco[jj][3] * inv1);
    }
}

// ---------------- launch --------------------------------------------------
extern "C" void kernel_launch(void* const* d_in, const int* in_sizes, int n_in,
                              void* d_out, int out_size)
{
    const float* x = (const float*)d_in[0];
    const float* W [4] = {(const float*)d_in[1],  (const float*)d_in[5],
                          (const float*)d_in[9],  (const float*)d_in[13]};
    const float* B [4] = {(const float*)d_in[2],  (const float*)d_in[6],
                          (const float*)d_in[10], (const float*)d_in[14]};
    const float* dW[4] = {(const float*)d_in[3],  (const float*)d_in[7],
                          (const float*)d_in[11], (const float*)d_in[15]};
    const float* dB[4] = {(const float*)d_in[4],  (const float*)d_in[8],
                          (const float*)d_in[12], (const float*)d_in[16]};
    float* out = (float*)d_out;

    void *pxh, *pao;
    cudaGetSymbolAddress(&pxh, g_xh);
    cudaGetSymbolAddress(&pao, g_ao);

    // 1) tiled LoRA merge + x->fp16 (independent, back-to-back)
    {
        dim3 grid(4, 32, 4);
        merge_lora_t<<<grid, 256>>>(W[0], dW[0], dB[0], W[1], dW[1], dB[1],
                                    W[2], dW[2], dB[2], W[3], dW[3], dB[3]);
    }
    prep_h<<<4096, 256>>>(x);

    // 2) QKV projections
    cudaFuncSetAttribute(gemm_hmma, cudaFuncAttributeMaxDynamicSharedMemorySize, GSMEM);
    {
        dim3 grid(D_MODEL / 128, M_TOTAL / 128, 3);
        gemm_hmma<<<grid, 256, GSMEM>>>((const __half*)pxh, 0, 0,
                                        B[0], B[1], B[2], nullptr);
    }

    // 3) flash attention -> g_ao
    cudaFuncSetAttribute(flash_hmma, cudaFuncAttributeMaxDynamicSharedMemorySize, ATT_SMEM);
    {
        dim3 grid(SEQ / QROWS, BATCH * NHEAD);
        flash_hmma<<<grid, 256, ATT_SMEM>>>();
    }

    // 4) O projection -> d_out
    {
        dim3 grid(D_MODEL / 128, M_TOTAL / 128, 1);
        gemm_hmma<<<grid, 256, GSMEM>>>((const __half*)pao, 1, 3,
                                        B[3], B[3], B[3], out);
    }
}

// round 15
// speedup vs baseline: 9.7772x; 1.0010x over previous
#include <cuda_runtime.h>
#include <cuda_fp16.h>
#include <cstdint>

#define D_MODEL 1024
#define NHEAD   16
#define DHEAD   64
#define SEQ     2048
#define BATCH   2
#define M_TOTAL (BATCH * SEQ)   /* 4096 */
#define RANK    32

// ---------------- device scratch (all single fp16) ----------------
__device__ __half g_xh [(size_t)M_TOTAL * D_MODEL];
__device__ __half g_w2 [(size_t)4 * D_MODEL * D_MODEL];
__device__ __half g_ao [(size_t)M_TOTAL * D_MODEL];
__device__ __half g_qh [(size_t)BATCH * NHEAD * SEQ * 64];  // Q * 0.125*log2e
__device__ __half g_kh [(size_t)BATCH * NHEAD * SEQ * 64];
__device__ __half g_vh [(size_t)BATCH * NHEAD * SEQ * 64];

// ---------------- PTX helpers (baseline PTX only) ----------------
__device__ __forceinline__ uint32_t smem_u32(const void* p) {
    uint32_t a;
    asm("{ .reg .u64 t; cvta.to.shared.u64 t, %1; cvt.u32.u64 %0, t; }" : "=r"(a) : "l"(p));
    return a;
}
__device__ __forceinline__ void cpa16(uint32_t dst, const void* src) {
    asm volatile("cp.async.cg.shared.global [%0], [%1], 16;" :: "r"(dst), "l"(src));
}
#define CP_COMMIT() asm volatile("cp.async.commit_group;" ::: "memory")
#define CP_WAIT(n)  asm volatile("cp.async.wait_group %0;" :: "n"(n) : "memory")

__device__ __forceinline__ void ldsm_x4(uint32_t (&r)[4], uint32_t addr) {
    asm volatile("ldmatrix.sync.aligned.m8n8.x4.shared.b16 {%0,%1,%2,%3}, [%4];"
                 : "=r"(r[0]), "=r"(r[1]), "=r"(r[2]), "=r"(r[3]) : "r"(addr));
}
__device__ __forceinline__ void ldsm_x4t(uint32_t (&r)[4], uint32_t addr) {
    asm volatile("ldmatrix.sync.aligned.m8n8.x4.trans.shared.b16 {%0,%1,%2,%3}, [%4];"
                 : "=r"(r[0]), "=r"(r[1]), "=r"(r[2]), "=r"(r[3]) : "r"(addr));
}
__device__ __forceinline__ void mma16816h(float (&d)[4], const uint32_t (&a)[4],
                                          uint32_t b0, uint32_t b1) {
    asm volatile("mma.sync.aligned.m16n8k16.row.col.f32.f16.f16.f32 "
                 "{%0,%1,%2,%3}, {%4,%5,%6,%7}, {%8,%9}, {%0,%1,%2,%3};"
                 : "+f"(d[0]), "+f"(d[1]), "+f"(d[2]), "+f"(d[3])
                 : "r"(a[0]), "r"(a[1]), "r"(a[2]), "r"(a[3]), "r"(b0), "r"(b1));
}
__device__ __forceinline__ void mma16816hh(uint32_t (&d)[2], const uint32_t (&a)[4],
                                           uint32_t b0, uint32_t b1) {
    asm volatile("mma.sync.aligned.m16n8k16.row.col.f16.f16.f16.f16 "
                 "{%0,%1}, {%2,%3,%4,%5}, {%6,%7}, {%0,%1};"
                 : "+r"(d[0]), "+r"(d[1])
                 : "r"(a[0]), "r"(a[1]), "r"(a[2]), "r"(a[3]), "r"(b0), "r"(b1));
}
__device__ __forceinline__ uint32_t packh2(float v0, float v1) {
    __half2 t = __floats2half2_rn(v0, v1);
    return reinterpret_cast<uint32_t&>(t);
}
__device__ __forceinline__ float ex2(float x) {
    float y;
    asm("ex2.approx.ftz.f32 %0, %1;" : "=f"(y) : "f"(x));
    return y;
}

// ---------------- smem-tiled LoRA merge (unchanged, known-good) ------------
__global__ void __launch_bounds__(256)
merge_lora_t(const float* __restrict__ W0, const float* __restrict__ dW0, const float* __restrict__ dB0,
             const float* __restrict__ W1, const float* __restrict__ dW1, const float* __restrict__ dB1,
             const float* __restrict__ W2, const float* __restrict__ dW2, const float* __restrict__ dB2,
             const float* __restrict__ W3, const float* __restrict__ dW3, const float* __restrict__ dB3)
{
    const int kx = blockIdx.x;
    const int ny = blockIdx.y;
    const int layer = blockIdx.z;
    const float* W  = (layer == 0) ? W0  : (layer == 1) ? W1  : (layer == 2) ? W2  : W3;
    const float* dW = (layer == 0) ? dW0 : (layer == 1) ? dW1 : (layer == 2) ? dW2 : dW3;
    const float* dB = (layer == 0) ? dB0 : (layer == 1) ? dB1 : (layer == 2) ? dB2 : dB3;

    __shared__ float4 dws[RANK][64];
    __shared__ float  dbs[32][RANK];

    const int tid = threadIdx.x;
    const float4* dW4 = (const float4*)dW;
    const int n0 = ny * 32;

#pragma unroll
    for (int i = 0; i < 8; i++) {
        int e = tid + i * 256;
        int r = e >> 6, q = e & 63;
        dws[r][q] = dW4[r * 256 + kx * 64 + q];
    }
#pragma unroll
    for (int i = 0; i < 4; i++) {
        int e = tid + i * 256;
        int row = e >> 5, r = e & 31;
        dbs[row][r] = dB[(n0 + row) * RANK + r];
    }
    __syncthreads();

    const int q    = tid & 63;
    const int rowg = tid >> 6;
    const float4* W4 = (const float4*)W;
    float4 s[8];
#pragma unroll
    for (int j = 0; j < 8; j++)
        s[j] = W4[(size_t)(n0 + rowg * 8 + j) * 256 + kx * 64 + q];
#pragma unroll
    for (int r = 0; r < RANK; r++) {
        float4 w = dws[r][q];
#pragma unroll
        for (int j = 0; j < 8; j++) {
            float b = dbs[rowg * 8 + j][r];
            s[j].x += b * w.x; s[j].y += b * w.y;
            s[j].z += b * w.z; s[j].w += b * w.w;
        }
    }
#pragma unroll
    for (int j = 0; j < 8; j++) {
        int n = n0 + rowg * 8 + j;
        __half2* p = (__half2*)(g_w2 + (size_t)(layer * D_MODEL + n) * D_MODEL
                                + (kx * 64 + q) * 4);
        p[0] = __floats2half2_rn(s[j].x, s[j].y);
        p[1] = __floats2half2_rn(s[j].z, s[j].w);
    }
}

// ---------------- x -> single fp16 ----------------
__global__ void prep_h(const float* __restrict__ src)
{
    int e = blockIdx.x * 256 + threadIdx.x;
    float4 s = *(const float4*)(src + (size_t)e * 4);
    __half2* p = (__half2*)(g_xh + (size_t)e * 4);
    p[0] = __floats2half2_rn(s.x, s.y);
    p[1] = __floats2half2_rn(s.z, s.w);
}

// ---------------- HMMA GEMM v2: C[128,64] tiles, 3 CTAs/SM -----------------
// 8 warps in 4(m) x 2(n); warp tile 32x32; acc = 32 floats/thread.
#define GKC   64
#define GNCH  16
#define GROWB 144
#define GA_BYTES (128 * GROWB)      /* 18432 */
#define GW_BYTES (64 * GROWB)       /*  9216 */
#define GSTAGE   (GA_BYTES + GW_BYTES)  /* 27648 */
#define GSMEM    (2 * GSTAGE)           /* 55296: 3 CTAs/SM */

__global__ void __launch_bounds__(256, 3)
gemm_hmma(const __half* __restrict__ Abase,
          int mode, int layer_base,
          const float* __restrict__ b0, const float* __restrict__ b1,
          const float* __restrict__ b2, float* __restrict__ outO)
{
    extern __shared__ __align__(128) char smem[];
    const uint32_t sb = smem_u32(smem);
    const int tid = threadIdx.x, ln = tid & 31, w = tid >> 5;
    const int wm = w & 3, wn = w >> 2;     // 4(m) x 2(n)
    const int bx = blockIdx.x, by = blockIdx.y, z = blockIdx.z;
    const int layer = layer_base + z;

    const __half* Arow = Abase + (size_t)(by * 128) * D_MODEL;
    const __half* Wrow = g_w2 + ((size_t)layer * D_MODEL + bx * 64) * D_MODEL;

    float acc[2][4][4] = {};

#define GLOAD(c) do {                                                          \
        int s_ = (c) & 1;                                                      \
        int x_ = (c) * GKC;                                                    \
        uint32_t bA_ = sb + s_ * GSTAGE;                                       \
        uint32_t bW_ = bA_ + GA_BYTES;                                         \
        _Pragma("unroll")                                                      \
        for (int u_ = 0; u_ < 4; u_++) {                                       \
            int e_ = tid + u_ * 256;                                           \
            int row_ = e_ >> 3, seg_ = (e_ & 7) * 16;                          \
            cpa16(bA_ + row_ * GROWB + seg_,                                   \
                  (const char*)(Arow + (size_t)row_ * D_MODEL + x_) + seg_);   \
        }                                                                      \
        _Pragma("unroll")                                                      \
        for (int u_ = 0; u_ < 2; u_++) {                                       \
            int e_ = tid + u_ * 256;                                           \
            int row_ = e_ >> 3, seg_ = (e_ & 7) * 16;                          \
            cpa16(bW_ + row_ * GROWB + seg_,                                   \
                  (const char*)(Wrow + (size_t)row_ * D_MODEL + x_) + seg_);   \
        }                                                                      \
        CP_COMMIT();                                                           \
    } while (0)

    GLOAD(0);
    for (int c = 0; c < GNCH; c++) {
        CP_WAIT(0);
        __syncthreads();
        if (c + 1 < GNCH) GLOAD(c + 1);   // loads overlap compute below

        const uint32_t bA = sb + (c & 1) * GSTAGE;
        const uint32_t bW = bA + GA_BYTES;
#pragma unroll
        for (int ks = 0; ks < 4; ks++) {
            const int k0 = ks * 16;
            uint32_t afr[2][4];
#pragma unroll
            for (int i = 0; i < 2; i++) {
                int row = wm * 32 + i * 16 + (ln & 15);
                ldsm_x4(afr[i], bA + row * GROWB + (k0 + ((ln >> 4) << 3)) * 2);
            }
            uint32_t bfr[2][4];
#pragma unroll
            for (int j = 0; j < 2; j++) {
                int n = wn * 32 + j * 16 + (ln & 7) + ((ln & 16) ? 8 : 0);
                ldsm_x4(bfr[j], bW + n * GROWB + (k0 + ((ln & 8) ? 8 : 0)) * 2);
            }
#pragma unroll
            for (int i = 0; i < 2; i++)
#pragma unroll
                for (int jj = 0; jj < 4; jj++)
                    mma16816h(acc[i][jj], afr[i], bfr[jj >> 1][(jj & 1) * 2],
                              bfr[jj >> 1][(jj & 1) * 2 + 1]);
        }
    }

    const float* bias = (z == 0) ? b0 : (z == 1) ? b1 : b2;
    const float qscale = (mode == 0 && z == 0) ? 0.125f * 1.4426950408889634f : 1.0f;
#pragma unroll
    for (int i = 0; i < 2; i++) {
#pragma unroll
        for (int dl = 0; dl < 2; dl++) {
            const int m = by * 128 + wm * 32 + i * 16 + (ln >> 2) + dl * 8;
#pragma unroll
            for (int jj = 0; jj < 4; jj++) {
                const int cgl = bx * 64 + wn * 32 + jj * 8 + (ln & 3) * 2;
                float v0 = (acc[i][jj][dl * 2 + 0] + bias[cgl])     * qscale;
                float v1 = (acc[i][jj][dl * 2 + 1] + bias[cgl + 1]) * qscale;
                if (mode == 0) {
                    const int h = cgl >> 6, d = cgl & 63;
                    const int b = m >> 11, n = m & 2047;
                    const size_t rowb = (size_t)(b * NHEAD + h) * SEQ + n;
                    __half* base = ((z == 0) ? g_qh : (z == 1) ? g_kh : g_vh)
                                   + rowb * 64 + d;
                    *(__half2*)base = __floats2half2_rn(v0, v1);
                } else {
                    float2 o; o.x = v0; o.y = v1;
                    *(float2*)(outO + (size_t)m * D_MODEL + cgl) = o;
                }
            }
        }
    }
}

// ---------------- Flash attention (unchanged, known-good) ------------------
#define KROWB 144
#define KTILEB (64 * KROWB)
#define NBUF  6
#define QROWS 128
#define SM_K0  0
#define SM_V0  (NBUF * KTILEB)
#define ATT_SMEM (2 * NBUF * KTILEB)      /* 110592, 2 CTAs/SM */
#define NT (SEQ / 64)

__global__ void __launch_bounds__(256, 2)
flash_hmma()
{
    extern __shared__ __align__(128) char smem[];
    const uint32_t sb = smem_u32(smem);
    const int tid = threadIdx.x, ln = tid & 31, w = tid >> 5;
    const int qt = blockIdx.x, bh = blockIdx.y;

    const __half* qg = g_qh + ((size_t)bh * SEQ + qt * QROWS) * 64;
    const __half* kg = g_kh + (size_t)bh * SEQ * 64;
    const __half* vg = g_vh + (size_t)bh * SEQ * 64;

#define ATT_LOAD(t) do {                                                       \
        int buf_ = (t) % NBUF;                                                 \
        const __half* kb_ = kg + (size_t)(t) * 64 * 64;                        \
        const __half* vb_ = vg + (size_t)(t) * 64 * 64;                        \
        uint32_t kd_ = sb + SM_K0 + buf_ * KTILEB;                             \
        uint32_t vd_ = sb + SM_V0 + buf_ * KTILEB;                             \
        _Pragma("unroll")                                                      \
        for (int u_ = 0; u_ < 2; u_++) {                                       \
            int e_ = tid + u_ * 256;                                           \
            int row_ = e_ >> 3, seg_ = (e_ & 7) * 16;                          \
            cpa16(kd_ + row_ * KROWB + seg_,                                   \
                  (const char*)(kb_ + (size_t)row_ * 64) + seg_);              \
            cpa16(vd_ + row_ * KROWB + seg_,                                   \
                  (const char*)(vb_ + (size_t)row_ * 64) + seg_);              \
        }                                                                      \
        CP_COMMIT();                                                           \
    } while (0)

    ATT_LOAD(0); ATT_LOAD(1); ATT_LOAD(2); ATT_LOAD(3); ATT_LOAD(4);

    uint32_t qf[4][4];
    {
        const __half* q0 = qg + (size_t)(w * 16 + (ln >> 2)) * 64 + (ln & 3) * 2;
        const __half* q8 = q0 + 8 * 64;
#pragma unroll
        for (int s = 0; s < 4; s++) {
            qf[s][0] = *(const uint32_t*)(q0 + s * 16);
            qf[s][1] = *(const uint32_t*)(q8 + s * 16);
            qf[s][2] = *(const uint32_t*)(q0 + s * 16 + 8);
            qf[s][3] = *(const uint32_t*)(q8 + s * 16 + 8);
        }
    }

    const int krow8  = (ln & 7) + ((ln & 16) ? 8 : 0);
    const int kcol8  = (ln & 8) ? 8 : 0;
    const int vrow16 = ln & 15;
    const int vcol8  = (ln & 16) ? 8 : 0;

    float m0 = -1e30f, m1 = -1e30f;
    float lp0 = 0.f, lp1 = 0.f;
    float acco[8][4] = {};

#pragma unroll 1
    for (int i = 0; i < NT; i++) {
        {
            const int rem = NT - 1 - i;
            if      (rem >= 4) CP_WAIT(4);
            else if (rem == 3) CP_WAIT(3);
            else if (rem == 2) CP_WAIT(2);
            else if (rem == 1) CP_WAIT(1);
            else               CP_WAIT(0);
        }
        __syncthreads();
        if (i + 5 < NT) ATT_LOAD(i + 5);

        const uint32_t bK = sb + SM_K0 + (i % NBUF) * KTILEB;
        const uint32_t bV = sb + SM_V0 + (i % NBUF) * KTILEB;

        uint32_t sh[8][2] = {};
#pragma unroll
        for (int ks = 0; ks < 4; ks++) {
#pragma unroll
            for (int nbp = 0; nbp < 4; nbp++) {
                uint32_t kb[4];
                ldsm_x4(kb, bK + (nbp * 16 + krow8) * KROWB + (ks * 16 + kcol8) * 2);
                mma16816hh(sh[2 * nbp],     qf[ks], kb[0], kb[1]);
                mma16816hh(sh[2 * nbp + 1], qf[ks], kb[2], kb[3]);
            }
        }
        float accs[8][4];
#pragma unroll
        for (int jj = 0; jj < 8; jj++) {
            __half2 lo = reinterpret_cast<__half2&>(sh[jj][0]);
            __half2 hi = reinterpret_cast<__half2&>(sh[jj][1]);
            accs[jj][0] = __low2float(lo);  accs[jj][1] = __high2float(lo);
            accs[jj][2] = __low2float(hi);  accs[jj][3] = __high2float(hi);
        }

        float mx0 = -1e30f, mx1 = -1e30f;
#pragma unroll
        for (int jj = 0; jj < 8; jj++) {
            mx0 = fmaxf(mx0, fmaxf(accs[jj][0], accs[jj][1]));
            mx1 = fmaxf(mx1, fmaxf(accs[jj][2], accs[jj][3]));
        }
        mx0 = fmaxf(mx0, __shfl_xor_sync(0xffffffffu, mx0, 1));
        mx0 = fmaxf(mx0, __shfl_xor_sync(0xffffffffu, mx0, 2));
        mx1 = fmaxf(mx1, __shfl_xor_sync(0xffffffffu, mx1, 1));
        mx1 = fmaxf(mx1, __shfl_xor_sync(0xffffffffu, mx1, 2));
        const float mn0 = fmaxf(m0, mx0), mn1 = fmaxf(m1, mx1);
        const float a0 = ex2(m0 - mn0), a1 = ex2(m1 - mn1);
        m0 = mn0; m1 = mn1;
        lp0 *= a0; lp1 *= a1;
#pragma unroll
        for (int jj = 0; jj < 8; jj++) {
            acco[jj][0] *= a0; acco[jj][1] *= a0;
            acco[jj][2] *= a1; acco[jj][3] *= a1;
        }

#pragma unroll
        for (int ks = 0; ks < 4; ks++) {
            float e00 = ex2(accs[2 * ks][0] - m0);
            float e01 = ex2(accs[2 * ks][1] - m0);
            float e02 = ex2(accs[2 * ks][2] - m1);
            float e03 = ex2(accs[2 * ks][3] - m1);
            float e10 = ex2(accs[2 * ks + 1][0] - m0);
            float e11 = ex2(accs[2 * ks + 1][1] - m0);
            float e12 = ex2(accs[2 * ks + 1][2] - m1);
            float e13 = ex2(accs[2 * ks + 1][3] - m1);
            lp0 += e00 + e01 + e10 + e11;
            lp1 += e02 + e03 + e12 + e13;
            uint32_t phi[4];
            phi[0] = packh2(e00, e01);
            phi[1] = packh2(e02, e03);
            phi[2] = packh2(e10, e11);
            phi[3] = packh2(e12, e13);
#pragma unroll
            for (int nbp = 0; nbp < 4; nbp++) {
                uint32_t vb[4];
                ldsm_x4t(vb, bV + (ks * 16 + vrow16) * KROWB + (nbp * 16 + vcol8) * 2);
                mma16816h(acco[2 * nbp],     phi, vb[0], vb[1]);
                mma16816h(acco[2 * nbp + 1], phi, vb[2], vb[3]);
            }
        }
    }

    float l0 = lp0, l1 = lp1;
    l0 += __shfl_xor_sync(0xffffffffu, l0, 1);
    l0 += __shfl_xor_sync(0xffffffffu, l0, 2);
    l1 += __shfl_xor_sync(0xffffffffu, l1, 1);
    l1 += __shfl_xor_sync(0xffffffffu, l1, 2);

    const int b = bh >> 4, h = bh & 15;
    const int q = ln >> 2, t4 = ln & 3;
    const float inv0 = 1.f / l0, inv1 = 1.f / l1;
    const size_t n0 = (size_t)qt * QROWS + w * 16 + q;
    const size_t mg0 = (size_t)b * SEQ + n0;
    const size_t mg1 = mg0 + 8;
#pragma unroll
    for (int jj = 0; jj < 8; jj++) {
        const int col = h * 64 + jj * 8 + t4 * 2;
        *(uint32_t*)(g_ao + mg0 * D_MODEL + col) =
            packh2(acco[jj][0] * inv0, acco[jj][1] * inv0);
        *(uint32_t*)(g_ao + mg1 * D_MODEL + col) =
            packh2(acco[jj][2] * inv1, acco[jj][3] * inv1);
    }
}

// ---------------- launch --------------------------------------------------
extern "C" void kernel_launch(void* const* d_in, const int* in_sizes, int n_in,
                              void* d_out, int out_size)
{
    const float* x = (const float*)d_in[0];
    const float* W [4] = {(const float*)d_in[1],  (const float*)d_in[5],
                          (const float*)d_in[9],  (const float*)d_in[13]};
    const float* B [4] = {(const float*)d_in[2],  (const float*)d_in[6],
                          (const float*)d_in[10], (const float*)d_in[14]};
    const float* dW[4] = {(const float*)d_in[3],  (const float*)d_in[7],
                          (const float*)d_in[11], (const float*)d_in[15]};
    const float* dB[4] = {(const float*)d_in[4],  (const float*)d_in[8],
                          (const float*)d_in[12], (const float*)d_in[16]};
    float* out = (float*)d_out;

    void *pxh, *pao;
    cudaGetSymbolAddress(&pxh, g_xh);
    cudaGetSymbolAddress(&pao, g_ao);

    // 1) tiled LoRA merge + x->fp16
    {
        dim3 grid(4, 32, 4);
        merge_lora_t<<<grid, 256>>>(W[0], dW[0], dB[0], W[1], dW[1], dB[1],
                                    W[2], dW[2], dB[2], W[3], dW[3], dB[3]);
    }
    prep_h<<<4096, 256>>>(x);

    // 2) QKV projections (128x64 tiles, 3 CTAs/SM)
    cudaFuncSetAttribute(gemm_hmma, cudaFuncAttributeMaxDynamicSharedMemorySize, GSMEM);
    {
        dim3 grid(D_MODEL / 64, M_TOTAL / 128, 3);
        gemm_hmma<<<grid, 256, GSMEM>>>((const __half*)pxh, 0, 0,
                                        B[0], B[1], B[2], nullptr);
    }

    // 3) flash attention -> g_ao
    cudaFuncSetAttribute(flash_hmma, cudaFuncAttributeMaxDynamicSharedMemorySize, ATT_SMEM);
    {
        dim3 grid(SEQ / QROWS, BATCH * NHEAD);
        flash_hmma<<<grid, 256, ATT_SMEM>>>();
    }

    // 4) O projection -> d_out
    {
        dim3 grid(D_MODEL / 64, M_TOTAL / 128, 1);
        gemm_hmma<<<grid, 256, GSMEM>>>((const __half*)pao, 1, 3,
                                        B[3], B[3], B[3], out);
    }
}